// round 4
// baseline (speedup 1.0000x reference)
#include <cuda_runtime.h>
#include <math.h>

#define S_LEN   2048
#define D_MODEL 2048
#define NH      16
#define NG      4
#define DHEAD   128
#define NB      2
#define MROWS   (NB*S_LEN)

__device__ float g_q  [(size_t)MROWS * (NH*DHEAD)];
__device__ float g_k  [(size_t)MROWS * (NG*DHEAD)];
__device__ float g_v  [(size_t)MROWS * (NG*DHEAD)];
__device__ float g_ctx[(size_t)MROWS * (NH*DHEAD)];
__device__ float g_rope[S_LEN * DHEAD];
__device__ const float* g_wq_slot;
__device__ const float* g_wo_slot;

/* ---- pick Wq/Wo among the three 4.2M-element candidates (mask is bool) -- */
__global__ void probe_kernel(const unsigned char* c0, const unsigned char* c1,
                             const unsigned char* c2) {
    if (threadIdx.x != 0 || blockIdx.x != 0) return;
    const unsigned char* cs[3] = {c0, c1, c2};
    int nb[3];
    for (int i = 0; i < 3; ++i) {
        int boolish = 1;
        for (int k = 0; k < 64; ++k)
            if (cs[i][k * 97] > 1) { boolish = 0; break; }
        nb[i] = boolish;
    }
    int a = -1, b = -1;
    for (int i = 0; i < 3; ++i)
        if (!nb[i]) { if (a < 0) a = i; else if (b < 0) b = i; }
    if (a < 0 || b < 0) { a = 0; b = 1; }      /* fallback: dict order */
    g_wq_slot = (const float*)cs[a];
    g_wo_slot = (const float*)cs[b];
}

/* ---- RoPE table: fp32 inv_freq/angle to match JAX, accurate trig -------- */
__global__ void build_rope_kernel() {
    int s = blockIdx.x, d = threadIdx.x;                 /* d: 0..63 */
    float e    = (float)d / 64.0f;
    float invf = 1.0f / powf(10000.0f, e);
    float ang  = (float)s * invf;
    g_rope[s*DHEAD + d]      = (float)cos((double)ang);
    g_rope[s*DHEAD + 64 + d] = (float)sin((double)ang);
}

/* ---- fp32 SIMT GEMM: C[M,N]=A[M,K]@B[K,N]; Bind overrides Bm if set ----- */
__global__ void __launch_bounds__(256) gemm_kernel(const float* __restrict__ A,
                                                   const float* Bm,
                                                   const float* const* Bind,
                                                   float* __restrict__ C,
                                                   int M, int N, int K) {
    if (Bind) Bm = *Bind;
    __shared__ float As[16][128];
    __shared__ float Bs[16][128];
    int bm = blockIdx.y * 128, bn = blockIdx.x * 128;
    int tid = threadIdx.x, ty = tid >> 4, tx = tid & 15;
    float acc[8][8];
    #pragma unroll
    for (int i = 0; i < 8; ++i)
        #pragma unroll
        for (int j = 0; j < 8; ++j) acc[i][j] = 0.f;

    for (int k0 = 0; k0 < K; k0 += 16) {
        #pragma unroll
        for (int p = 0; p < 2; ++p) {
            int r = (tid >> 2) + p*64, c = (tid & 3) * 4;
            float4 a4 = *(const float4*)(A + (size_t)(bm + r)*K + k0 + c);
            As[c+0][r] = a4.x; As[c+1][r] = a4.y;
            As[c+2][r] = a4.z; As[c+3][r] = a4.w;
        }
        #pragma unroll
        for (int p = 0; p < 2; ++p) {
            int r = (tid >> 5) + p*8, c = (tid & 31) * 4;
            *(float4*)(&Bs[r][c]) = *(const float4*)(Bm + (size_t)(k0 + r)*N + bn + c);
        }
        __syncthreads();
        #pragma unroll
        for (int kk = 0; kk < 16; ++kk) {
            float a[8], b[8];
            *(float4*)(a)   = *(float4*)(&As[kk][ty*8]);
            *(float4*)(a+4) = *(float4*)(&As[kk][ty*8+4]);
            *(float4*)(b)   = *(float4*)(&Bs[kk][tx*8]);
            *(float4*)(b+4) = *(float4*)(&Bs[kk][tx*8+4]);
            #pragma unroll
            for (int i = 0; i < 8; ++i)
                #pragma unroll
                for (int j = 0; j < 8; ++j)
                    acc[i][j] = fmaf(a[i], b[j], acc[i][j]);
        }
        __syncthreads();
    }
    #pragma unroll
    for (int i = 0; i < 8; ++i) {
        size_t off = (size_t)(bm + ty*8 + i)*N + bn + tx*8;
        *(float4*)(C + off)     = make_float4(acc[i][0],acc[i][1],acc[i][2],acc[i][3]);
        *(float4*)(C + off + 4) = make_float4(acc[i][4],acc[i][5],acc[i][6],acc[i][7]);
    }
}

__global__ void rope_kernel(float* __restrict__ buf, int heads) {
    int bs = blockIdx.x, h = blockIdx.y, d = threadIdx.x;
    int s = bs & (S_LEN - 1);
    size_t base = (size_t)bs * heads * DHEAD + (size_t)h * DHEAD;
    float c  = g_rope[s*DHEAD + d];
    float sn = g_rope[s*DHEAD + 64 + d];
    float x1 = buf[base + d], x2 = buf[base + 64 + d];
    buf[base + d]      = x1*c - x2*sn;
    buf[base + 64 + d] = x2*c + x1*sn;
}

__global__ void cache_kernel(float* __restrict__ outc) {
    const size_t CACHE = (size_t)NB*NG*S_LEN*DHEAD;
    size_t idx = (size_t)blockIdx.x * blockDim.x + threadIdx.x;
    if (idx >= CACHE) return;
    int d = (int)(idx & 127);
    int s = (int)((idx >> 7) & (S_LEN-1));
    int g = (int)((idx >> 18) & (NG-1));
    int b = (int)(idx >> 20);
    size_t src = ((size_t)(b*S_LEN + s))*(NG*DHEAD) + (size_t)g*DHEAD + d;
    outc[idx]         = g_k[src];
    outc[CACHE + idx] = g_v[src];
}

/* ---- attention: warp-per-query-row, causal GQA, fp32 -------------------- */
__global__ void __launch_bounds__(512) attn_kernel() {
    __shared__ float sK[32*128];
    __shared__ float sV[32*128];

    int h = blockIdx.y, b = blockIdx.z;
    int g = h >> 2;
    int q0 = blockIdx.x * 16;
    int tid = threadIdx.x, w = tid >> 5, lane = tid & 31;
    int q_abs = q0 + w;

    const float* qp = g_q + ((size_t)(b*S_LEN + q_abs))*(NH*DHEAD)
                          + (size_t)h*DHEAD + lane*4;
    float4 qv = *(const float4*)qp;

    const float scale = 0.08838834764831845f;
    float m = -1e30f, l = 0.f;
    float4 acc = make_float4(0.f, 0.f, 0.f, 0.f);

    const float* kbase = g_k + (size_t)(b*S_LEN)*(NG*DHEAD) + (size_t)g*DHEAD;
    const float* vbase = g_v + (size_t)(b*S_LEN)*(NG*DHEAD) + (size_t)g*DHEAD;

    int nt = (q0 + 47) >> 5;
    for (int kt = 0; kt < nt; ++kt) {
        int k0 = kt * 32;
        __syncthreads();
        for (int t = tid; t < 1024; t += 512) {
            int r = t >> 5, c4 = (t & 31) << 2;
            *(float4*)(sK + r*128 + c4) =
                *(const float4*)(kbase + (size_t)(k0 + r)*(NG*DHEAD) + c4);
            *(float4*)(sV + r*128 + c4) =
                *(const float4*)(vbase + (size_t)(k0 + r)*(NG*DHEAD) + c4);
        }
        __syncthreads();

        int hi = q_abs + 1 - k0;
        if (hi > 32) hi = 32;
        for (int kk = 0; kk < hi; ++kk) {
            float4 kv = *(float4*)(sK + kk*128 + lane*4);
            float sc = qv.x*kv.x + qv.y*kv.y + qv.z*kv.z + qv.w*kv.w;
            sc += __shfl_xor_sync(0xffffffffu, sc, 16);
            sc += __shfl_xor_sync(0xffffffffu, sc, 8);
            sc += __shfl_xor_sync(0xffffffffu, sc, 4);
            sc += __shfl_xor_sync(0xffffffffu, sc, 2);
            sc += __shfl_xor_sync(0xffffffffu, sc, 1);
            sc *= scale;
            float m_new = fmaxf(m, sc);
            float corr  = __expf(m - m_new);
            float p     = __expf(sc - m_new);
            l = l*corr + p;
            m = m_new;
            float4 vv = *(float4*)(sV + kk*128 + lane*4);
            acc.x = acc.x*corr + p*vv.x;
            acc.y = acc.y*corr + p*vv.y;
            acc.z = acc.z*corr + p*vv.z;
            acc.w = acc.w*corr + p*vv.w;
        }
    }

    float inv_l = 1.0f / l;
    float* op = g_ctx + ((size_t)(b*S_LEN + q_abs))*(NH*DHEAD)
                      + (size_t)h*DHEAD + lane*4;
    *(float4*)op = make_float4(acc.x*inv_l, acc.y*inv_l, acc.z*inv_l, acc.w*inv_l);
}

extern "C" void kernel_launch(void* const* d_in, const int* in_sizes, int n_in,
                              void* d_out, int out_size) {
    /* identify inputs by size signature: x=8388608, {Wk,Wv}=1048576 (in
       order), {Wq,Wo,mask}=4194304 (mask found by content on device) */
    int idx_x = -1, sm[2], nsm = 0, bg[3], nbg = 0;
    for (int i = 0; i < n_in; ++i) {
        if (in_sizes[i] == 8388608 && idx_x < 0) idx_x = i;
        else if (in_sizes[i] == 1048576 && nsm < 2) sm[nsm++] = i;
        else if (in_sizes[i] == 4194304 && nbg < 3) bg[nbg++] = i;
    }
    const float *x, *Wk, *Wv;
    const unsigned char *c0, *c1, *c2;
    if (idx_x >= 0 && nsm == 2 && nbg == 3) {
        x  = (const float*)d_in[idx_x];
        Wk = (const float*)d_in[sm[0]];
        Wv = (const float*)d_in[sm[1]];
        c0 = (const unsigned char*)d_in[bg[0]];
        c1 = (const unsigned char*)d_in[bg[1]];
        c2 = (const unsigned char*)d_in[bg[2]];
    } else {                                   /* positional fallback */
        x  = (const float*)d_in[0];
        Wk = (const float*)d_in[2];
        Wv = (const float*)d_in[3];
        c0 = (const unsigned char*)d_in[1];
        c1 = (const unsigned char*)d_in[4];
        c2 = (const unsigned char*)d_in[5];
    }
    float* out = (float*)d_out;

    float *qp, *kp, *vp, *cp;
    const float **wq_slot, **wo_slot;
    cudaGetSymbolAddress((void**)&qp, g_q);
    cudaGetSymbolAddress((void**)&kp, g_k);
    cudaGetSymbolAddress((void**)&vp, g_v);
    cudaGetSymbolAddress((void**)&cp, g_ctx);
    cudaGetSymbolAddress((void**)&wq_slot, g_wq_slot);
    cudaGetSymbolAddress((void**)&wo_slot, g_wo_slot);

    probe_kernel<<<1, 32>>>(c0, c1, c2);
    build_rope_kernel<<<S_LEN, 64>>>();

    gemm_kernel<<<dim3((NH*DHEAD)/128, MROWS/128), 256>>>(x, 0, wq_slot, qp, MROWS, NH*DHEAD, D_MODEL);
    gemm_kernel<<<dim3((NG*DHEAD)/128, MROWS/128), 256>>>(x, Wk, 0, kp, MROWS, NG*DHEAD, D_MODEL);
    gemm_kernel<<<dim3((NG*DHEAD)/128, MROWS/128), 256>>>(x, Wv, 0, vp, MROWS, NG*DHEAD, D_MODEL);

    rope_kernel<<<dim3(MROWS, NH), 64>>>(qp, NH);
    rope_kernel<<<dim3(MROWS, NG), 64>>>(kp, NG);

    const size_t OUT_MAIN = (size_t)NB * S_LEN * D_MODEL;
    const size_t CACHE    = (size_t)NB * NG * S_LEN * DHEAD;
    if ((size_t)out_size >= OUT_MAIN + 2*CACHE) {
        cache_kernel<<<(int)((CACHE + 255)/256), 256>>>(out + OUT_MAIN);
    }

    attn_kernel<<<dim3(S_LEN/16, NH, NB), 512>>>();

    gemm_kernel<<<dim3(D_MODEL/128, MROWS/128), 256>>>(cp, 0, wo_slot, out, MROWS, D_MODEL, D_MODEL);
}

// round 5
// speedup vs baseline: 1.6019x; 1.6019x over previous
#include <cuda_runtime.h>
#include <math.h>

#define S_LEN   2048
#define D_MODEL 2048
#define NH      16
#define NG      4
#define DHEAD   128
#define NB      2
#define MROWS   (NB*S_LEN)

__device__ float g_q  [(size_t)MROWS * (NH*DHEAD)];
__device__ float g_k  [(size_t)MROWS * (NG*DHEAD)];
__device__ float g_v  [(size_t)MROWS * (NG*DHEAD)];
__device__ float g_ctx[(size_t)MROWS * (NH*DHEAD)];
__device__ float g_rope[S_LEN * DHEAD];
__device__ const float* g_wq_slot;
__device__ const float* g_wo_slot;

/* ---- pick Wq/Wo among the three 4.2M-element candidates (mask is bool) -- */
__global__ void probe_kernel(const unsigned char* c0, const unsigned char* c1,
                             const unsigned char* c2) {
    if (threadIdx.x != 0 || blockIdx.x != 0) return;
    const unsigned char* cs[3] = {c0, c1, c2};
    int nb[3];
    for (int i = 0; i < 3; ++i) {
        int boolish = 1;
        for (int k = 0; k < 64; ++k)
            if (cs[i][k * 97] > 1) { boolish = 0; break; }
        nb[i] = boolish;
    }
    int a = -1, b = -1;
    for (int i = 0; i < 3; ++i)
        if (!nb[i]) { if (a < 0) a = i; else if (b < 0) b = i; }
    if (a < 0 || b < 0) { a = 0; b = 1; }
    g_wq_slot = (const float*)cs[a];
    g_wo_slot = (const float*)cs[b];
}

__global__ void build_rope_kernel() {
    int s = blockIdx.x, d = threadIdx.x;                 /* d: 0..63 */
    float e    = (float)d / 64.0f;
    float invf = 1.0f / powf(10000.0f, e);
    float ang  = (float)s * invf;
    g_rope[s*DHEAD + d]      = (float)cos((double)ang);
    g_rope[s*DHEAD + 64 + d] = (float)sin((double)ang);
}

/* ---- fused QKV GEMM: A=x [4096,2048]; block-routed to Wq/Wk/Wv ---------- */
__global__ void __launch_bounds__(256) qkv_gemm_kernel(const float* __restrict__ A,
                                                       const float* Wk,
                                                       const float* Wv) {
    __shared__ float As[16][128];
    __shared__ float Bs[16][128];
    int bx = blockIdx.x;
    const float* Bm; float* C; int N; int bn;
    if (bx < 16)      { Bm = g_wq_slot; C = g_q; N = NH*DHEAD; bn = bx*128; }
    else if (bx < 20) { Bm = Wk;        C = g_k; N = NG*DHEAD; bn = (bx-16)*128; }
    else              { Bm = Wv;        C = g_v; N = NG*DHEAD; bn = (bx-20)*128; }
    int bm = blockIdx.y * 128;
    int tid = threadIdx.x, ty = tid >> 4, tx = tid & 15;
    float acc[8][8];
    #pragma unroll
    for (int i = 0; i < 8; ++i)
        #pragma unroll
        for (int j = 0; j < 8; ++j) acc[i][j] = 0.f;

    for (int k0 = 0; k0 < D_MODEL; k0 += 16) {
        #pragma unroll
        for (int p = 0; p < 2; ++p) {
            int r = (tid >> 2) + p*64, c = (tid & 3) * 4;
            float4 a4 = *(const float4*)(A + (size_t)(bm + r)*D_MODEL + k0 + c);
            As[c+0][r] = a4.x; As[c+1][r] = a4.y;
            As[c+2][r] = a4.z; As[c+3][r] = a4.w;
        }
        #pragma unroll
        for (int p = 0; p < 2; ++p) {
            int r = (tid >> 5) + p*8, c = (tid & 31) * 4;
            *(float4*)(&Bs[r][c]) = *(const float4*)(Bm + (size_t)(k0 + r)*N + bn + c);
        }
        __syncthreads();
        #pragma unroll
        for (int kk = 0; kk < 16; ++kk) {
            float a[8], b[8];
            *(float4*)(a)   = *(float4*)(&As[kk][ty*8]);
            *(float4*)(a+4) = *(float4*)(&As[kk][ty*8+4]);
            *(float4*)(b)   = *(float4*)(&Bs[kk][tx*8]);
            *(float4*)(b+4) = *(float4*)(&Bs[kk][tx*8+4]);
            #pragma unroll
            for (int i = 0; i < 8; ++i)
                #pragma unroll
                for (int j = 0; j < 8; ++j)
                    acc[i][j] = fmaf(a[i], b[j], acc[i][j]);
        }
        __syncthreads();
    }
    #pragma unroll
    for (int i = 0; i < 8; ++i) {
        size_t off = (size_t)(bm + ty*8 + i)*N + bn + tx*8;
        *(float4*)(C + off)     = make_float4(acc[i][0],acc[i][1],acc[i][2],acc[i][3]);
        *(float4*)(C + off + 4) = make_float4(acc[i][4],acc[i][5],acc[i][6],acc[i][7]);
    }
}

/* ---- output GEMM: out = g_ctx @ Wo (pointer from probed slot) ----------- */
__global__ void __launch_bounds__(256) out_gemm_kernel(float* __restrict__ C) {
    __shared__ float As[16][128];
    __shared__ float Bs[16][128];
    const float* Bm = g_wo_slot;
    const float* A  = g_ctx;
    const int N = D_MODEL, K = D_MODEL;
    int bm = blockIdx.y * 128, bn = blockIdx.x * 128;
    int tid = threadIdx.x, ty = tid >> 4, tx = tid & 15;
    float acc[8][8];
    #pragma unroll
    for (int i = 0; i < 8; ++i)
        #pragma unroll
        for (int j = 0; j < 8; ++j) acc[i][j] = 0.f;

    for (int k0 = 0; k0 < K; k0 += 16) {
        #pragma unroll
        for (int p = 0; p < 2; ++p) {
            int r = (tid >> 2) + p*64, c = (tid & 3) * 4;
            float4 a4 = *(const float4*)(A + (size_t)(bm + r)*K + k0 + c);
            As[c+0][r] = a4.x; As[c+1][r] = a4.y;
            As[c+2][r] = a4.z; As[c+3][r] = a4.w;
        }
        #pragma unroll
        for (int p = 0; p < 2; ++p) {
            int r = (tid >> 5) + p*8, c = (tid & 31) * 4;
            *(float4*)(&Bs[r][c]) = *(const float4*)(Bm + (size_t)(k0 + r)*N + bn + c);
        }
        __syncthreads();
        #pragma unroll
        for (int kk = 0; kk < 16; ++kk) {
            float a[8], b[8];
            *(float4*)(a)   = *(float4*)(&As[kk][ty*8]);
            *(float4*)(a+4) = *(float4*)(&As[kk][ty*8+4]);
            *(float4*)(b)   = *(float4*)(&Bs[kk][tx*8]);
            *(float4*)(b+4) = *(float4*)(&Bs[kk][tx*8+4]);
            #pragma unroll
            for (int i = 0; i < 8; ++i)
                #pragma unroll
                for (int j = 0; j < 8; ++j)
                    acc[i][j] = fmaf(a[i], b[j], acc[i][j]);
        }
        __syncthreads();
    }
    #pragma unroll
    for (int i = 0; i < 8; ++i) {
        size_t off = (size_t)(bm + ty*8 + i)*N + bn + tx*8;
        *(float4*)(C + off)     = make_float4(acc[i][0],acc[i][1],acc[i][2],acc[i][3]);
        *(float4*)(C + off + 4) = make_float4(acc[i][4],acc[i][5],acc[i][6],acc[i][7]);
    }
}

__global__ void rope_kernel(float* __restrict__ buf, int heads) {
    int bs = blockIdx.x, h = blockIdx.y, d = threadIdx.x;
    int s = bs & (S_LEN - 1);
    size_t base = (size_t)bs * heads * DHEAD + (size_t)h * DHEAD;
    float c  = g_rope[s*DHEAD + d];
    float sn = g_rope[s*DHEAD + 64 + d];
    float x1 = buf[base + d], x2 = buf[base + 64 + d];
    buf[base + d]      = x1*c - x2*sn;
    buf[base + 64 + d] = x2*c + x1*sn;
}

__global__ void cache_kernel(float* __restrict__ outc) {
    const size_t CACHE = (size_t)NB*NG*S_LEN*DHEAD;
    size_t idx = (size_t)blockIdx.x * blockDim.x + threadIdx.x;
    if (idx >= CACHE) return;
    int d = (int)(idx & 127);
    int s = (int)((idx >> 7) & (S_LEN-1));
    int g = (int)((idx >> 18) & (NG-1));
    int b = (int)(idx >> 20);
    size_t src = ((size_t)(b*S_LEN + s))*(NG*DHEAD) + (size_t)g*DHEAD + d;
    outc[idx]         = g_k[src];
    outc[CACHE + idx] = g_v[src];
}

/* ---- flash attention tile kernel (validated by agreement in R0/R3) ------ */
#define FL_SMEM ((128*68*2 + 64*128 + 64*68 + 3*64) * 4)   /* 120,576 B */

__global__ void __launch_bounds__(256) flash_kernel() {
    extern __shared__ float smp[];
    float* sQt = smp;
    float* sKt = sQt + 128*68;
    float* sV  = sKt + 128*68;
    float* sS  = sV  + 64*128;
    float* sM  = sS  + 64*68;
    float* sL  = sM  + 64;
    float* sA  = sL  + 64;

    int qt = blockIdx.x, h = blockIdx.y, b = blockIdx.z;
    int g  = h >> 2;
    int q0 = qt * 64;
    int tid = threadIdx.x;
    int ty = tid >> 4, tx = tid & 15;
    int l  = tid & 31;
    int rl = l >> 2, cl = l & 3;

    const float* qbase = g_q + ((size_t)(b*S_LEN + q0))*(NH*DHEAD) + (size_t)h*DHEAD;
    #pragma unroll
    for (int ii = 0; ii < 8; ++ii) {
        int idx = ii*256 + tid;
        int w  = idx >> 5;
        int r  = (w >> 3)*8 + rl;
        int cq = (w & 7)*4 + cl;
        float4 qv = *(const float4*)(qbase + (size_t)r*(NH*DHEAD) + cq*4);
        int c0 = cq*4;
        sQt[(c0+0)*68 + r] = qv.x;
        sQt[(c0+1)*68 + r] = qv.y;
        sQt[(c0+2)*68 + r] = qv.z;
        sQt[(c0+3)*68 + r] = qv.w;
    }
    if (tid < 64) { sM[tid] = -1e30f; sL[tid] = 0.f; }

    float acc[4][8];
    #pragma unroll
    for (int i = 0; i < 4; ++i)
        #pragma unroll
        for (int j = 0; j < 8; ++j) acc[i][j] = 0.f;

    const float* kbase = g_k + (size_t)(b*S_LEN)*(NG*DHEAD) + (size_t)g*DHEAD;
    const float* vbase = g_v + (size_t)(b*S_LEN)*(NG*DHEAD) + (size_t)g*DHEAD;
    const float scale = 0.08838834764831845f;

    __syncthreads();

    for (int kt = 0; kt <= qt; ++kt) {
        int k0 = kt * 64;
        #pragma unroll
        for (int ii = 0; ii < 8; ++ii) {
            int idx = ii*256 + tid;
            int w  = idx >> 5;
            int r  = (w >> 3)*8 + rl;
            int cq = (w & 7)*4 + cl;
            float4 kv = *(const float4*)(kbase + (size_t)(k0 + r)*(NG*DHEAD) + cq*4);
            int c0 = cq*4;
            sKt[(c0+0)*68 + r] = kv.x;
            sKt[(c0+1)*68 + r] = kv.y;
            sKt[(c0+2)*68 + r] = kv.z;
            sKt[(c0+3)*68 + r] = kv.w;
            float4 vv = *(const float4*)(vbase + (size_t)(k0 + r)*(NG*DHEAD) + cq*4);
            *(float4*)(sV + r*128 + cq*4) = vv;
        }
        __syncthreads();

        float s4[4][4];
        #pragma unroll
        for (int i = 0; i < 4; ++i)
            #pragma unroll
            for (int j = 0; j < 4; ++j) s4[i][j] = 0.f;

        #pragma unroll 4
        for (int kk = 0; kk < 128; ++kk) {
            float4 av = *(float4*)(sQt + kk*68 + ty*4);
            float4 bv = *(float4*)(sKt + kk*68 + tx*4);
            s4[0][0] = fmaf(av.x, bv.x, s4[0][0]); s4[0][1] = fmaf(av.x, bv.y, s4[0][1]);
            s4[0][2] = fmaf(av.x, bv.z, s4[0][2]); s4[0][3] = fmaf(av.x, bv.w, s4[0][3]);
            s4[1][0] = fmaf(av.y, bv.x, s4[1][0]); s4[1][1] = fmaf(av.y, bv.y, s4[1][1]);
            s4[1][2] = fmaf(av.y, bv.z, s4[1][2]); s4[1][3] = fmaf(av.y, bv.w, s4[1][3]);
            s4[2][0] = fmaf(av.z, bv.x, s4[2][0]); s4[2][1] = fmaf(av.z, bv.y, s4[2][1]);
            s4[2][2] = fmaf(av.z, bv.z, s4[2][2]); s4[2][3] = fmaf(av.z, bv.w, s4[2][3]);
            s4[3][0] = fmaf(av.w, bv.x, s4[3][0]); s4[3][1] = fmaf(av.w, bv.y, s4[3][1]);
            s4[3][2] = fmaf(av.w, bv.z, s4[3][2]); s4[3][3] = fmaf(av.w, bv.w, s4[3][3]);
        }

        #pragma unroll
        for (int i = 0; i < 4; ++i) {
            int r = ty*4 + i;
            #pragma unroll
            for (int j = 0; j < 4; ++j) {
                int c = tx*4 + j;
                float vsc = s4[i][j] * scale;
                if (k0 + c > q0 + r) vsc = -1e30f;
                sS[r*68 + c] = vsc;
            }
        }
        __syncthreads();

        {
            int r  = tid >> 2;
            int q4 = tid & 3;
            float mx = -1e30f;
            #pragma unroll
            for (int c = 0; c < 16; ++c) mx = fmaxf(mx, sS[r*68 + q4*16 + c]);
            mx = fmaxf(mx, __shfl_xor_sync(0xffffffffu, mx, 1));
            mx = fmaxf(mx, __shfl_xor_sync(0xffffffffu, mx, 2));
            float m_old = sM[r];
            float m_new = fmaxf(m_old, mx);
            float lsum = 0.f;
            #pragma unroll
            for (int c = 0; c < 16; ++c) {
                float p = __expf(sS[r*68 + q4*16 + c] - m_new);
                sS[r*68 + q4*16 + c] = p;
                lsum += p;
            }
            lsum += __shfl_xor_sync(0xffffffffu, lsum, 1);
            lsum += __shfl_xor_sync(0xffffffffu, lsum, 2);
            if (q4 == 0) {
                sA[r] = __expf(m_old - m_new);
                sM[r] = m_new;
                sL[r] = sL[r]*sA[r] + lsum;
            }
        }
        __syncthreads();

        #pragma unroll
        for (int i = 0; i < 4; ++i) {
            float al = sA[ty*4 + i];
            #pragma unroll
            for (int j = 0; j < 8; ++j) acc[i][j] *= al;
        }
        #pragma unroll 2
        for (int kk = 0; kk < 64; ++kk) {
            float4 v0 = *(float4*)(sV + kk*128 + tx*8);
            float4 v1 = *(float4*)(sV + kk*128 + tx*8 + 4);
            #pragma unroll
            for (int i = 0; i < 4; ++i) {
                float p = sS[(ty*4+i)*68 + kk];
                acc[i][0] = fmaf(p, v0.x, acc[i][0]);
                acc[i][1] = fmaf(p, v0.y, acc[i][1]);
                acc[i][2] = fmaf(p, v0.z, acc[i][2]);
                acc[i][3] = fmaf(p, v0.w, acc[i][3]);
                acc[i][4] = fmaf(p, v1.x, acc[i][4]);
                acc[i][5] = fmaf(p, v1.y, acc[i][5]);
                acc[i][6] = fmaf(p, v1.z, acc[i][6]);
                acc[i][7] = fmaf(p, v1.w, acc[i][7]);
            }
        }
        __syncthreads();
    }

    #pragma unroll
    for (int i = 0; i < 4; ++i) {
        int r = ty*4 + i;
        float inv_l = 1.0f / sL[r];
        size_t off = ((size_t)(b*S_LEN + q0 + r))*(NH*DHEAD) + (size_t)h*DHEAD + tx*8;
        *(float4*)(g_ctx + off)     = make_float4(acc[i][0]*inv_l, acc[i][1]*inv_l,
                                                  acc[i][2]*inv_l, acc[i][3]*inv_l);
        *(float4*)(g_ctx + off + 4) = make_float4(acc[i][4]*inv_l, acc[i][5]*inv_l,
                                                  acc[i][6]*inv_l, acc[i][7]*inv_l);
    }
}

extern "C" void kernel_launch(void* const* d_in, const int* in_sizes, int n_in,
                              void* d_out, int out_size) {
    int idx_x = -1, sm[2], nsm = 0, bg[3], nbg = 0;
    for (int i = 0; i < n_in; ++i) {
        if (in_sizes[i] == 8388608 && idx_x < 0) idx_x = i;
        else if (in_sizes[i] == 1048576 && nsm < 2) sm[nsm++] = i;
        else if (in_sizes[i] == 4194304 && nbg < 3) bg[nbg++] = i;
    }
    const float *x, *Wk, *Wv;
    const unsigned char *c0, *c1, *c2;
    if (idx_x >= 0 && nsm == 2 && nbg == 3) {
        x  = (const float*)d_in[idx_x];
        Wk = (const float*)d_in[sm[0]];
        Wv = (const float*)d_in[sm[1]];
        c0 = (const unsigned char*)d_in[bg[0]];
        c1 = (const unsigned char*)d_in[bg[1]];
        c2 = (const unsigned char*)d_in[bg[2]];
    } else {
        x  = (const float*)d_in[0];
        Wk = (const float*)d_in[2];
        Wv = (const float*)d_in[3];
        c0 = (const unsigned char*)d_in[1];
        c1 = (const unsigned char*)d_in[4];
        c2 = (const unsigned char*)d_in[5];
    }
    float* out = (float*)d_out;

    float *qp, *kp;
    cudaGetSymbolAddress((void**)&qp, g_q);
    cudaGetSymbolAddress((void**)&kp, g_k);

    probe_kernel<<<1, 32>>>(c0, c1, c2);
    build_rope_kernel<<<S_LEN, 64>>>();

    qkv_gemm_kernel<<<dim3(24, MROWS/128), 256>>>(x, Wk, Wv);

    rope_kernel<<<dim3(MROWS, NH), 64>>>(qp, NH);
    rope_kernel<<<dim3(MROWS, NG), 64>>>(kp, NG);

    const size_t OUT_MAIN = (size_t)NB * S_LEN * D_MODEL;
    const size_t CACHE    = (size_t)NB * NG * S_LEN * DHEAD;
    if ((size_t)out_size >= OUT_MAIN + 2*CACHE) {
        cache_kernel<<<(int)((CACHE + 255)/256), 256>>>(out + OUT_MAIN);
    }

    cudaFuncSetAttribute(flash_kernel, cudaFuncAttributeMaxDynamicSharedMemorySize, FL_SMEM);
    flash_kernel<<<dim3(S_LEN/64, NH, NB), 256, FL_SMEM>>>();

    out_gemm_kernel<<<dim3(D_MODEL/128, MROWS/128), 256>>>(out);
}

// round 6
// speedup vs baseline: 1.9822x; 1.2374x over previous
#include <cuda_runtime.h>
#include <cuda_bf16.h>
#include <math.h>
#include <stdint.h>

#define S_LEN   2048
#define D_MODEL 2048
#define NH      16
#define NG      4
#define DHEAD   128
#define NB      2
#define MROWS   (NB*S_LEN)

__device__ float g_q  [(size_t)MROWS * (NH*DHEAD)];
__device__ float g_k  [(size_t)MROWS * (NG*DHEAD)];
__device__ float g_v  [(size_t)MROWS * (NG*DHEAD)];
__device__ float g_ctx[(size_t)MROWS * (NH*DHEAD)];
__device__ float g_rope[S_LEN * DHEAD];
__device__ const float* g_wq_slot;
__device__ const float* g_wo_slot;

/* ---- pick Wq/Wo among the three 4.2M-element candidates (mask is bool) -- */
__global__ void probe_kernel(const unsigned char* c0, const unsigned char* c1,
                             const unsigned char* c2) {
    if (threadIdx.x != 0 || blockIdx.x != 0) return;
    const unsigned char* cs[3] = {c0, c1, c2};
    int nb[3];
    for (int i = 0; i < 3; ++i) {
        int boolish = 1;
        for (int k = 0; k < 64; ++k)
            if (cs[i][k * 97] > 1) { boolish = 0; break; }
        nb[i] = boolish;
    }
    int a = -1, b = -1;
    for (int i = 0; i < 3; ++i)
        if (!nb[i]) { if (a < 0) a = i; else if (b < 0) b = i; }
    if (a < 0 || b < 0) { a = 0; b = 1; }
    g_wq_slot = (const float*)cs[a];
    g_wo_slot = (const float*)cs[b];
}

__global__ void build_rope_kernel() {
    int s = blockIdx.x, d = threadIdx.x;                 /* d: 0..63 */
    float e    = (float)d / 64.0f;
    float invf = 1.0f / powf(10000.0f, e);
    float ang  = (float)s * invf;
    g_rope[s*DHEAD + d]      = (float)cos((double)ang);
    g_rope[s*DHEAD + 64 + d] = (float)sin((double)ang);
}

/* ================= bf16-split tensor-core GEMM ============================
 * C[M,N] = A[M,K] @ B[K,N], fp32 in/out. Each input split x = hi + lo (bf16);
 * accumulate hi*hi + hi*lo + lo*hi with mma.sync m16n8k16 (fp32 accum).
 * CTA tile 128x128, BK=32, 8 warps (4m x 2n), warp tile 32x64.             */

struct SmemGemm {
    __nv_bfloat16 Ah[128][40];   /* [m][k], pad 40  */
    __nv_bfloat16 Al[128][40];
    __nv_bfloat16 Bh[32][136];   /* [k][n], pad 136 */
    __nv_bfloat16 Bl[32][136];
};

__device__ __forceinline__ uint32_t smem_u32(const void* p) {
    return (uint32_t)__cvta_generic_to_shared(p);
}

__device__ __forceinline__ void ldsm_x4(uint32_t* r, uint32_t addr) {
    asm volatile("ldmatrix.sync.aligned.m8n8.x4.shared.b16 {%0,%1,%2,%3}, [%4];"
        : "=r"(r[0]), "=r"(r[1]), "=r"(r[2]), "=r"(r[3]) : "r"(addr));
}
__device__ __forceinline__ void ldsm_x4_t(uint32_t* r, uint32_t addr) {
    asm volatile("ldmatrix.sync.aligned.m8n8.x4.trans.shared.b16 {%0,%1,%2,%3}, [%4];"
        : "=r"(r[0]), "=r"(r[1]), "=r"(r[2]), "=r"(r[3]) : "r"(addr));
}
__device__ __forceinline__ void mma16816(float* c, const uint32_t* a,
                                         uint32_t b0, uint32_t b1) {
    asm volatile("mma.sync.aligned.m16n8k16.row.col.f32.bf16.bf16.f32 "
        "{%0,%1,%2,%3}, {%4,%5,%6,%7}, {%8,%9}, {%0,%1,%2,%3};"
        : "+f"(c[0]), "+f"(c[1]), "+f"(c[2]), "+f"(c[3])
        : "r"(a[0]), "r"(a[1]), "r"(a[2]), "r"(a[3]), "r"(b0), "r"(b1));
}

__device__ __forceinline__ void split_pair(float x, float y,
                                           __nv_bfloat162* hi, __nv_bfloat162* lo) {
    __nv_bfloat16 hx = __float2bfloat16_rn(x);
    __nv_bfloat16 hy = __float2bfloat16_rn(y);
    *hi = __halves2bfloat162(hx, hy);
    *lo = __halves2bfloat162(__float2bfloat16_rn(x - __bfloat162float(hx)),
                             __float2bfloat16_rn(y - __bfloat162float(hy)));
}

__device__ __forceinline__ void gemm_bf16split(SmemGemm* sm,
                                               const float* __restrict__ A,
                                               const float* __restrict__ Bw,
                                               float* __restrict__ C,
                                               int N, int K, int bm, int bn) {
    int tid = threadIdx.x;
    int warp = tid >> 5, lane = tid & 31;
    int m_base = (warp >> 1) * 32;
    int n_base = (warp & 1) * 64;

    float c[2][8][4];
    #pragma unroll
    for (int mt = 0; mt < 2; ++mt)
        #pragma unroll
        for (int nt = 0; nt < 8; ++nt)
            #pragma unroll
            for (int r = 0; r < 4; ++r) c[mt][nt][r] = 0.f;

    for (int k0 = 0; k0 < K; k0 += 32) {
        __syncthreads();
        /* A tile: 128 rows x 32 k, convert+split */
        #pragma unroll
        for (int i = 0; i < 4; ++i) {
            int fid = tid + i*256;
            int row = fid >> 3, c4 = (fid & 7) * 4;
            float4 a4 = *(const float4*)(A + (size_t)(bm + row)*K + k0 + c4);
            __nv_bfloat162 h01, l01, h23, l23;
            split_pair(a4.x, a4.y, &h01, &l01);
            split_pair(a4.z, a4.w, &h23, &l23);
            *(__nv_bfloat162*)&sm->Ah[row][c4]   = h01;
            *(__nv_bfloat162*)&sm->Ah[row][c4+2] = h23;
            *(__nv_bfloat162*)&sm->Al[row][c4]   = l01;
            *(__nv_bfloat162*)&sm->Al[row][c4+2] = l23;
        }
        /* B tile: 32 k-rows x 128 n, convert+split (natural [k][n] layout) */
        #pragma unroll
        for (int i = 0; i < 4; ++i) {
            int fid = tid + i*256;
            int kr = fid >> 5, c4 = (fid & 31) * 4;
            float4 b4 = *(const float4*)(Bw + (size_t)(k0 + kr)*N + bn + c4);
            __nv_bfloat162 h01, l01, h23, l23;
            split_pair(b4.x, b4.y, &h01, &l01);
            split_pair(b4.z, b4.w, &h23, &l23);
            *(__nv_bfloat162*)&sm->Bh[kr][c4]   = h01;
            *(__nv_bfloat162*)&sm->Bh[kr][c4+2] = h23;
            *(__nv_bfloat162*)&sm->Bl[kr][c4]   = l01;
            *(__nv_bfloat162*)&sm->Bl[kr][c4+2] = l23;
        }
        __syncthreads();

        #pragma unroll
        for (int ks = 0; ks < 32; ks += 16) {
            uint32_t ah[2][4], al[2][4];
            #pragma unroll
            for (int mt = 0; mt < 2; ++mt) {
                int rr = m_base + mt*16 + (lane & 15);
                int kk = ks + (lane >> 4) * 8;
                ldsm_x4(ah[mt], smem_u32(&sm->Ah[rr][kk]));
                ldsm_x4(al[mt], smem_u32(&sm->Al[rr][kk]));
            }
            uint32_t bh[4][4], bl[4][4];
            #pragma unroll
            for (int nc = 0; nc < 4; ++nc) {
                int kr = ks + (lane & 7) + ((lane >> 3) & 1) * 8;
                int nn = n_base + nc*16 + (lane >> 4) * 8;
                ldsm_x4_t(bh[nc], smem_u32(&sm->Bh[kr][nn]));
                ldsm_x4_t(bl[nc], smem_u32(&sm->Bl[kr][nn]));
            }
            #pragma unroll
            for (int mt = 0; mt < 2; ++mt)
                #pragma unroll
                for (int nc = 0; nc < 4; ++nc)
                    #pragma unroll
                    for (int hf = 0; hf < 2; ++hf) {
                        float* cc = c[mt][nc*2 + hf];
                        uint32_t b0h = bh[nc][hf*2], b1h = bh[nc][hf*2+1];
                        uint32_t b0l = bl[nc][hf*2], b1l = bl[nc][hf*2+1];
                        mma16816(cc, ah[mt], b0h, b1h);
                        mma16816(cc, ah[mt], b0l, b1l);
                        mma16816(cc, al[mt], b0h, b1h);
                    }
        }
    }

    #pragma unroll
    for (int mt = 0; mt < 2; ++mt)
        #pragma unroll
        for (int nt = 0; nt < 8; ++nt) {
            int r   = bm + m_base + mt*16 + (lane >> 2);
            int col = bn + n_base + nt*8 + (lane & 3)*2;
            *(float2*)(C + (size_t)r*N + col)     = make_float2(c[mt][nt][0], c[mt][nt][1]);
            *(float2*)(C + (size_t)(r+8)*N + col) = make_float2(c[mt][nt][2], c[mt][nt][3]);
        }
}

/* fused QKV: grid.x routes to Wq(16) / Wk(4) / Wv(4) column blocks */
__global__ void __launch_bounds__(256) qkv_gemm_bf16(const float* __restrict__ x,
                                                     const float* __restrict__ Wk,
                                                     const float* __restrict__ Wv) {
    __shared__ SmemGemm sm;
    int bx = blockIdx.x, bm = blockIdx.y * 128;
    if (bx < 16)
        gemm_bf16split(&sm, x, g_wq_slot, g_q, NH*DHEAD, D_MODEL, bm, bx*128);
    else if (bx < 20)
        gemm_bf16split(&sm, x, Wk, g_k, NG*DHEAD, D_MODEL, bm, (bx-16)*128);
    else
        gemm_bf16split(&sm, x, Wv, g_v, NG*DHEAD, D_MODEL, bm, (bx-20)*128);
}

__global__ void __launch_bounds__(256) out_gemm_bf16(float* __restrict__ C) {
    __shared__ SmemGemm sm;
    gemm_bf16split(&sm, g_ctx, g_wo_slot, C, D_MODEL, D_MODEL,
                   blockIdx.y*128, blockIdx.x*128);
}

__global__ void rope_kernel(float* __restrict__ buf, int heads) {
    int bs = blockIdx.x, h = blockIdx.y, d = threadIdx.x;
    int s = bs & (S_LEN - 1);
    size_t base = (size_t)bs * heads * DHEAD + (size_t)h * DHEAD;
    float c  = g_rope[s*DHEAD + d];
    float sn = g_rope[s*DHEAD + 64 + d];
    float x1 = buf[base + d], x2 = buf[base + 64 + d];
    buf[base + d]      = x1*c - x2*sn;
    buf[base + 64 + d] = x2*c + x1*sn;
}

__global__ void cache_kernel(float* __restrict__ outc) {
    const size_t CACHE = (size_t)NB*NG*S_LEN*DHEAD;
    size_t idx = (size_t)blockIdx.x * blockDim.x + threadIdx.x;
    if (idx >= CACHE) return;
    int d = (int)(idx & 127);
    int s = (int)((idx >> 7) & (S_LEN-1));
    int g = (int)((idx >> 18) & (NG-1));
    int b = (int)(idx >> 20);
    size_t src = ((size_t)(b*S_LEN + s))*(NG*DHEAD) + (size_t)g*DHEAD + d;
    outc[idx]         = g_k[src];
    outc[CACHE + idx] = g_v[src];
}

/* ---- flash attention tile kernel (fp32, validated) ---------------------- */
#define FL_SMEM ((128*68*2 + 64*128 + 64*68 + 3*64) * 4)   /* 120,576 B */

__global__ void __launch_bounds__(256) flash_kernel() {
    extern __shared__ float smp[];
    float* sQt = smp;
    float* sKt = sQt + 128*68;
    float* sV  = sKt + 128*68;
    float* sS  = sV  + 64*128;
    float* sM  = sS  + 64*68;
    float* sL  = sM  + 64;
    float* sA  = sL  + 64;

    int qt = blockIdx.x, h = blockIdx.y, b = blockIdx.z;
    int g  = h >> 2;
    int q0 = qt * 64;
    int tid = threadIdx.x;
    int ty = tid >> 4, tx = tid & 15;
    int l  = tid & 31;
    int rl = l >> 2, cl = l & 3;

    const float* qbase = g_q + ((size_t)(b*S_LEN + q0))*(NH*DHEAD) + (size_t)h*DHEAD;
    #pragma unroll
    for (int ii = 0; ii < 8; ++ii) {
        int idx = ii*256 + tid;
        int w  = idx >> 5;
        int r  = (w >> 3)*8 + rl;
        int cq = (w & 7)*4 + cl;
        float4 qv = *(const float4*)(qbase + (size_t)r*(NH*DHEAD) + cq*4);
        int c0 = cq*4;
        sQt[(c0+0)*68 + r] = qv.x;
        sQt[(c0+1)*68 + r] = qv.y;
        sQt[(c0+2)*68 + r] = qv.z;
        sQt[(c0+3)*68 + r] = qv.w;
    }
    if (tid < 64) { sM[tid] = -1e30f; sL[tid] = 0.f; }

    float acc[4][8];
    #pragma unroll
    for (int i = 0; i < 4; ++i)
        #pragma unroll
        for (int j = 0; j < 8; ++j) acc[i][j] = 0.f;

    const float* kbase = g_k + (size_t)(b*S_LEN)*(NG*DHEAD) + (size_t)g*DHEAD;
    const float* vbase = g_v + (size_t)(b*S_LEN)*(NG*DHEAD) + (size_t)g*DHEAD;
    const float scale = 0.08838834764831845f;

    __syncthreads();

    for (int kt = 0; kt <= qt; ++kt) {
        int k0 = kt * 64;
        #pragma unroll
        for (int ii = 0; ii < 8; ++ii) {
            int idx = ii*256 + tid;
            int w  = idx >> 5;
            int r  = (w >> 3)*8 + rl;
            int cq = (w & 7)*4 + cl;
            float4 kv = *(const float4*)(kbase + (size_t)(k0 + r)*(NG*DHEAD) + cq*4);
            int c0 = cq*4;
            sKt[(c0+0)*68 + r] = kv.x;
            sKt[(c0+1)*68 + r] = kv.y;
            sKt[(c0+2)*68 + r] = kv.z;
            sKt[(c0+3)*68 + r] = kv.w;
            float4 vv = *(const float4*)(vbase + (size_t)(k0 + r)*(NG*DHEAD) + cq*4);
            *(float4*)(sV + r*128 + cq*4) = vv;
        }
        __syncthreads();

        float s4[4][4];
        #pragma unroll
        for (int i = 0; i < 4; ++i)
            #pragma unroll
            for (int j = 0; j < 4; ++j) s4[i][j] = 0.f;

        #pragma unroll 4
        for (int kk = 0; kk < 128; ++kk) {
            float4 av = *(float4*)(sQt + kk*68 + ty*4);
            float4 bv = *(float4*)(sKt + kk*68 + tx*4);
            s4[0][0] = fmaf(av.x, bv.x, s4[0][0]); s4[0][1] = fmaf(av.x, bv.y, s4[0][1]);
            s4[0][2] = fmaf(av.x, bv.z, s4[0][2]); s4[0][3] = fmaf(av.x, bv.w, s4[0][3]);
            s4[1][0] = fmaf(av.y, bv.x, s4[1][0]); s4[1][1] = fmaf(av.y, bv.y, s4[1][1]);
            s4[1][2] = fmaf(av.y, bv.z, s4[1][2]); s4[1][3] = fmaf(av.y, bv.w, s4[1][3]);
            s4[2][0] = fmaf(av.z, bv.x, s4[2][0]); s4[2][1] = fmaf(av.z, bv.y, s4[2][1]);
            s4[2][2] = fmaf(av.z, bv.z, s4[2][2]); s4[2][3] = fmaf(av.z, bv.w, s4[2][3]);
            s4[3][0] = fmaf(av.w, bv.x, s4[3][0]); s4[3][1] = fmaf(av.w, bv.y, s4[3][1]);
            s4[3][2] = fmaf(av.w, bv.z, s4[3][2]); s4[3][3] = fmaf(av.w, bv.w, s4[3][3]);
        }

        #pragma unroll
        for (int i = 0; i < 4; ++i) {
            int r = ty*4 + i;
            #pragma unroll
            for (int j = 0; j < 4; ++j) {
                int c = tx*4 + j;
                float vsc = s4[i][j] * scale;
                if (k0 + c > q0 + r) vsc = -1e30f;
                sS[r*68 + c] = vsc;
            }
        }
        __syncthreads();

        {
            int r  = tid >> 2;
            int q4 = tid & 3;
            float mx = -1e30f;
            #pragma unroll
            for (int c = 0; c < 16; ++c) mx = fmaxf(mx, sS[r*68 + q4*16 + c]);
            mx = fmaxf(mx, __shfl_xor_sync(0xffffffffu, mx, 1));
            mx = fmaxf(mx, __shfl_xor_sync(0xffffffffu, mx, 2));
            float m_old = sM[r];
            float m_new = fmaxf(m_old, mx);
            float lsum = 0.f;
            #pragma unroll
            for (int c = 0; c < 16; ++c) {
                float p = __expf(sS[r*68 + q4*16 + c] - m_new);
                sS[r*68 + q4*16 + c] = p;
                lsum += p;
            }
            lsum += __shfl_xor_sync(0xffffffffu, lsum, 1);
            lsum += __shfl_xor_sync(0xffffffffu, lsum, 2);
            if (q4 == 0) {
                sA[r] = __expf(m_old - m_new);
                sM[r] = m_new;
                sL[r] = sL[r]*sA[r] + lsum;
            }
        }
        __syncthreads();

        #pragma unroll
        for (int i = 0; i < 4; ++i) {
            float al = sA[ty*4 + i];
            #pragma unroll
            for (int j = 0; j < 8; ++j) acc[i][j] *= al;
        }
        #pragma unroll 2
        for (int kk = 0; kk < 64; ++kk) {
            float4 v0 = *(float4*)(sV + kk*128 + tx*8);
            float4 v1 = *(float4*)(sV + kk*128 + tx*8 + 4);
            #pragma unroll
            for (int i = 0; i < 4; ++i) {
                float p = sS[(ty*4+i)*68 + kk];
                acc[i][0] = fmaf(p, v0.x, acc[i][0]);
                acc[i][1] = fmaf(p, v0.y, acc[i][1]);
                acc[i][2] = fmaf(p, v0.z, acc[i][2]);
                acc[i][3] = fmaf(p, v0.w, acc[i][3]);
                acc[i][4] = fmaf(p, v1.x, acc[i][4]);
                acc[i][5] = fmaf(p, v1.y, acc[i][5]);
                acc[i][6] = fmaf(p, v1.z, acc[i][6]);
                acc[i][7] = fmaf(p, v1.w, acc[i][7]);
            }
        }
        __syncthreads();
    }

    #pragma unroll
    for (int i = 0; i < 4; ++i) {
        int r = ty*4 + i;
        float inv_l = 1.0f / sL[r];
        size_t off = ((size_t)(b*S_LEN + q0 + r))*(NH*DHEAD) + (size_t)h*DHEAD + tx*8;
        *(float4*)(g_ctx + off)     = make_float4(acc[i][0]*inv_l, acc[i][1]*inv_l,
                                                  acc[i][2]*inv_l, acc[i][3]*inv_l);
        *(float4*)(g_ctx + off + 4) = make_float4(acc[i][4]*inv_l, acc[i][5]*inv_l,
                                                  acc[i][6]*inv_l, acc[i][7]*inv_l);
    }
}

extern "C" void kernel_launch(void* const* d_in, const int* in_sizes, int n_in,
                              void* d_out, int out_size) {
    int idx_x = -1, sm[2], nsm = 0, bg[3], nbg = 0;
    for (int i = 0; i < n_in; ++i) {
        if (in_sizes[i] == 8388608 && idx_x < 0) idx_x = i;
        else if (in_sizes[i] == 1048576 && nsm < 2) sm[nsm++] = i;
        else if (in_sizes[i] == 4194304 && nbg < 3) bg[nbg++] = i;
    }
    const float *x, *Wk, *Wv;
    const unsigned char *c0, *c1, *c2;
    if (idx_x >= 0 && nsm == 2 && nbg == 3) {
        x  = (const float*)d_in[idx_x];
        Wk = (const float*)d_in[sm[0]];
        Wv = (const float*)d_in[sm[1]];
        c0 = (const unsigned char*)d_in[bg[0]];
        c1 = (const unsigned char*)d_in[bg[1]];
        c2 = (const unsigned char*)d_in[bg[2]];
    } else {
        x  = (const float*)d_in[0];
        Wk = (const float*)d_in[2];
        Wv = (const float*)d_in[3];
        c0 = (const unsigned char*)d_in[1];
        c1 = (const unsigned char*)d_in[4];
        c2 = (const unsigned char*)d_in[5];
    }
    float* out = (float*)d_out;

    float *qp, *kp;
    cudaGetSymbolAddress((void**)&qp, g_q);
    cudaGetSymbolAddress((void**)&kp, g_k);

    probe_kernel<<<1, 32>>>(c0, c1, c2);
    build_rope_kernel<<<S_LEN, 64>>>();

    qkv_gemm_bf16<<<dim3(24, MROWS/128), 256>>>(x, Wk, Wv);

    rope_kernel<<<dim3(MROWS, NH), 64>>>(qp, NH);
    rope_kernel<<<dim3(MROWS, NG), 64>>>(kp, NG);

    const size_t OUT_MAIN = (size_t)NB * S_LEN * D_MODEL;
    const size_t CACHE    = (size_t)NB * NG * S_LEN * DHEAD;
    if ((size_t)out_size >= OUT_MAIN + 2*CACHE) {
        cache_kernel<<<(int)((CACHE + 255)/256), 256>>>(out + OUT_MAIN);
    }

    cudaFuncSetAttribute(flash_kernel, cudaFuncAttributeMaxDynamicSharedMemorySize, FL_SMEM);
    flash_kernel<<<dim3(S_LEN/64, NH, NB), 256, FL_SMEM>>>();

    out_gemm_bf16<<<dim3(D_MODEL/128, MROWS/128), 256>>>(out);
}

// round 7
// speedup vs baseline: 3.0015x; 1.5142x over previous
#include <cuda_runtime.h>
#include <cuda_bf16.h>
#include <math.h>
#include <stdint.h>

#define S_LEN   2048
#define D_MODEL 2048
#define NH      16
#define NG      4
#define DHEAD   128
#define NB      2
#define MROWS   (NB*S_LEN)

__device__ float g_q  [(size_t)MROWS * (NH*DHEAD)];
__device__ float g_k  [(size_t)MROWS * (NG*DHEAD)];
__device__ float g_v  [(size_t)MROWS * (NG*DHEAD)];
__device__ float g_ctx[(size_t)MROWS * (NH*DHEAD)];
__device__ float g_rope[S_LEN * DHEAD];
__device__ const float* g_wq_slot;
__device__ const float* g_wo_slot;

/* ---- pick Wq/Wo among the three 4.2M-element candidates (mask is bool) -- */
__global__ void probe_kernel(const unsigned char* c0, const unsigned char* c1,
                             const unsigned char* c2) {
    if (threadIdx.x != 0 || blockIdx.x != 0) return;
    const unsigned char* cs[3] = {c0, c1, c2};
    int nb[3];
    for (int i = 0; i < 3; ++i) {
        int boolish = 1;
        for (int k = 0; k < 64; ++k)
            if (cs[i][k * 97] > 1) { boolish = 0; break; }
        nb[i] = boolish;
    }
    int a = -1, b = -1;
    for (int i = 0; i < 3; ++i)
        if (!nb[i]) { if (a < 0) a = i; else if (b < 0) b = i; }
    if (a < 0 || b < 0) { a = 0; b = 1; }
    g_wq_slot = (const float*)cs[a];
    g_wo_slot = (const float*)cs[b];
}

__global__ void build_rope_kernel() {
    int s = blockIdx.x, d = threadIdx.x;                 /* d: 0..63 */
    float e    = (float)d / 64.0f;
    float invf = 1.0f / powf(10000.0f, e);
    float ang  = (float)s * invf;
    g_rope[s*DHEAD + d]      = (float)cos((double)ang);
    g_rope[s*DHEAD + 64 + d] = (float)sin((double)ang);
}

/* ================= shared mma/ldmatrix helpers =========================== */
__device__ __forceinline__ uint32_t smem_u32(const void* p) {
    return (uint32_t)__cvta_generic_to_shared(p);
}
__device__ __forceinline__ void ldsm_x4(uint32_t* r, uint32_t addr) {
    asm volatile("ldmatrix.sync.aligned.m8n8.x4.shared.b16 {%0,%1,%2,%3}, [%4];"
        : "=r"(r[0]), "=r"(r[1]), "=r"(r[2]), "=r"(r[3]) : "r"(addr));
}
__device__ __forceinline__ void ldsm_x4_t(uint32_t* r, uint32_t addr) {
    asm volatile("ldmatrix.sync.aligned.m8n8.x4.trans.shared.b16 {%0,%1,%2,%3}, [%4];"
        : "=r"(r[0]), "=r"(r[1]), "=r"(r[2]), "=r"(r[3]) : "r"(addr));
}
__device__ __forceinline__ void mma16816(float* c, const uint32_t* a,
                                         uint32_t b0, uint32_t b1) {
    asm volatile("mma.sync.aligned.m16n8k16.row.col.f32.bf16.bf16.f32 "
        "{%0,%1,%2,%3}, {%4,%5,%6,%7}, {%8,%9}, {%0,%1,%2,%3};"
        : "+f"(c[0]), "+f"(c[1]), "+f"(c[2]), "+f"(c[3])
        : "r"(a[0]), "r"(a[1]), "r"(a[2]), "r"(a[3]), "r"(b0), "r"(b1));
}
__device__ __forceinline__ void split_pair(float x, float y,
                                           __nv_bfloat162* hi, __nv_bfloat162* lo) {
    __nv_bfloat16 hx = __float2bfloat16_rn(x);
    __nv_bfloat16 hy = __float2bfloat16_rn(y);
    *hi = __halves2bfloat162(hx, hy);
    *lo = __halves2bfloat162(__float2bfloat16_rn(x - __bfloat162float(hx)),
                             __float2bfloat16_rn(y - __bfloat162float(hy)));
}

/* ================= bf16-split tensor-core GEMM (validated R6) ============ */
struct SmemGemm {
    __nv_bfloat16 Ah[128][40];
    __nv_bfloat16 Al[128][40];
    __nv_bfloat16 Bh[32][136];
    __nv_bfloat16 Bl[32][136];
};

__device__ __forceinline__ void gemm_bf16split(SmemGemm* sm,
                                               const float* __restrict__ A,
                                               const float* __restrict__ Bw,
                                               float* __restrict__ C,
                                               int N, int K, int bm, int bn) {
    int tid = threadIdx.x;
    int warp = tid >> 5, lane = tid & 31;
    int m_base = (warp >> 1) * 32;
    int n_base = (warp & 1) * 64;

    float c[2][8][4];
    #pragma unroll
    for (int mt = 0; mt < 2; ++mt)
        #pragma unroll
        for (int nt = 0; nt < 8; ++nt)
            #pragma unroll
            for (int r = 0; r < 4; ++r) c[mt][nt][r] = 0.f;

    for (int k0 = 0; k0 < K; k0 += 32) {
        __syncthreads();
        #pragma unroll
        for (int i = 0; i < 4; ++i) {
            int fid = tid + i*256;
            int row = fid >> 3, c4 = (fid & 7) * 4;
            float4 a4 = *(const float4*)(A + (size_t)(bm + row)*K + k0 + c4);
            __nv_bfloat162 h01, l01, h23, l23;
            split_pair(a4.x, a4.y, &h01, &l01);
            split_pair(a4.z, a4.w, &h23, &l23);
            *(__nv_bfloat162*)&sm->Ah[row][c4]   = h01;
            *(__nv_bfloat162*)&sm->Ah[row][c4+2] = h23;
            *(__nv_bfloat162*)&sm->Al[row][c4]   = l01;
            *(__nv_bfloat162*)&sm->Al[row][c4+2] = l23;
        }
        #pragma unroll
        for (int i = 0; i < 4; ++i) {
            int fid = tid + i*256;
            int kr = fid >> 5, c4 = (fid & 31) * 4;
            float4 b4 = *(const float4*)(Bw + (size_t)(k0 + kr)*N + bn + c4);
            __nv_bfloat162 h01, l01, h23, l23;
            split_pair(b4.x, b4.y, &h01, &l01);
            split_pair(b4.z, b4.w, &h23, &l23);
            *(__nv_bfloat162*)&sm->Bh[kr][c4]   = h01;
            *(__nv_bfloat162*)&sm->Bh[kr][c4+2] = h23;
            *(__nv_bfloat162*)&sm->Bl[kr][c4]   = l01;
            *(__nv_bfloat162*)&sm->Bl[kr][c4+2] = l23;
        }
        __syncthreads();

        #pragma unroll
        for (int ks = 0; ks < 32; ks += 16) {
            uint32_t ah[2][4], al[2][4];
            #pragma unroll
            for (int mt = 0; mt < 2; ++mt) {
                int rr = m_base + mt*16 + (lane & 15);
                int kk = ks + (lane >> 4) * 8;
                ldsm_x4(ah[mt], smem_u32(&sm->Ah[rr][kk]));
                ldsm_x4(al[mt], smem_u32(&sm->Al[rr][kk]));
            }
            uint32_t bh[4][4], bl[4][4];
            #pragma unroll
            for (int nc = 0; nc < 4; ++nc) {
                int kr = ks + (lane & 7) + ((lane >> 3) & 1) * 8;
                int nn = n_base + nc*16 + (lane >> 4) * 8;
                ldsm_x4_t(bh[nc], smem_u32(&sm->Bh[kr][nn]));
                ldsm_x4_t(bl[nc], smem_u32(&sm->Bl[kr][nn]));
            }
            #pragma unroll
            for (int mt = 0; mt < 2; ++mt)
                #pragma unroll
                for (int nc = 0; nc < 4; ++nc)
                    #pragma unroll
                    for (int hf = 0; hf < 2; ++hf) {
                        float* cc = c[mt][nc*2 + hf];
                        uint32_t b0h = bh[nc][hf*2], b1h = bh[nc][hf*2+1];
                        uint32_t b0l = bl[nc][hf*2], b1l = bl[nc][hf*2+1];
                        mma16816(cc, ah[mt], b0h, b1h);
                        mma16816(cc, ah[mt], b0l, b1l);
                        mma16816(cc, al[mt], b0h, b1h);
                    }
        }
    }

    #pragma unroll
    for (int mt = 0; mt < 2; ++mt)
        #pragma unroll
        for (int nt = 0; nt < 8; ++nt) {
            int r   = bm + m_base + mt*16 + (lane >> 2);
            int col = bn + n_base + nt*8 + (lane & 3)*2;
            *(float2*)(C + (size_t)r*N + col)     = make_float2(c[mt][nt][0], c[mt][nt][1]);
            *(float2*)(C + (size_t)(r+8)*N + col) = make_float2(c[mt][nt][2], c[mt][nt][3]);
        }
}

__global__ void __launch_bounds__(256) qkv_gemm_bf16(const float* __restrict__ x,
                                                     const float* __restrict__ Wk,
                                                     const float* __restrict__ Wv) {
    __shared__ SmemGemm sm;
    int bx = blockIdx.x, bm = blockIdx.y * 128;
    if (bx < 16)
        gemm_bf16split(&sm, x, g_wq_slot, g_q, NH*DHEAD, D_MODEL, bm, bx*128);
    else if (bx < 20)
        gemm_bf16split(&sm, x, Wk, g_k, NG*DHEAD, D_MODEL, bm, (bx-16)*128);
    else
        gemm_bf16split(&sm, x, Wv, g_v, NG*DHEAD, D_MODEL, bm, (bx-20)*128);
}

__global__ void __launch_bounds__(256) out_gemm_bf16(float* __restrict__ C) {
    __shared__ SmemGemm sm;
    gemm_bf16split(&sm, g_ctx, g_wo_slot, C, D_MODEL, D_MODEL,
                   blockIdx.y*128, blockIdx.x*128);
}

__global__ void rope_kernel(float* __restrict__ buf, int heads) {
    int bs = blockIdx.x, h = blockIdx.y, d = threadIdx.x;
    int s = bs & (S_LEN - 1);
    size_t base = (size_t)bs * heads * DHEAD + (size_t)h * DHEAD;
    float c  = g_rope[s*DHEAD + d];
    float sn = g_rope[s*DHEAD + 64 + d];
    float x1 = buf[base + d], x2 = buf[base + 64 + d];
    buf[base + d]      = x1*c - x2*sn;
    buf[base + 64 + d] = x2*c + x1*sn;
}

__global__ void cache_kernel(float* __restrict__ outc) {
    const size_t CACHE = (size_t)NB*NG*S_LEN*DHEAD;
    size_t idx = (size_t)blockIdx.x * blockDim.x + threadIdx.x;
    if (idx >= CACHE) return;
    int d = (int)(idx & 127);
    int s = (int)((idx >> 7) & (S_LEN-1));
    int g = (int)((idx >> 18) & (NG-1));
    int b = (int)(idx >> 20);
    size_t src = ((size_t)(b*S_LEN + s))*(NG*DHEAD) + (size_t)g*DHEAD + d;
    outc[idx]         = g_k[src];
    outc[CACHE + idx] = g_v[src];
}

/* ================= tensor-core flash attention ===========================
 * CTA = 64-query tile, 8 warps. bf16-split (hi/lo, 3-pass) for QK^T and PV.
 * S-phase warps 4m x 2n (16x32), PV-phase warps 4m x 2n (16x64).          */
struct SmemFlash {
    __nv_bfloat16 Qh[64][136], Ql[64][136];
    __nv_bfloat16 Kh[64][136], Kl[64][136];
    __nv_bfloat16 Vh[64][136], Vl[64][136];
    float S[64][68];
    __nv_bfloat16 Ph[64][72], Pl[64][72];
    float M[64], L[64], A[64];
};

__global__ void __launch_bounds__(256) flash2_kernel() {
    extern __shared__ char smraw[];
    SmemFlash* sm = (SmemFlash*)smraw;

    int qt = blockIdx.x, h = blockIdx.y, b = blockIdx.z;
    int g  = h >> 2;
    int q0 = qt * 64;
    int tid = threadIdx.x, warp = tid >> 5, lane = tid & 31;
    int m_base = (warp >> 1) * 16;

    /* load + split Q (64 x 128) */
    const float* qbase = g_q + ((size_t)(b*S_LEN + q0))*(NH*DHEAD) + (size_t)h*DHEAD;
    #pragma unroll
    for (int i = 0; i < 8; ++i) {
        int fid = tid + i*256;
        int row = fid >> 5, c4 = (fid & 31) * 4;
        float4 v = *(const float4*)(qbase + (size_t)row*(NH*DHEAD) + c4);
        __nv_bfloat162 h01, l01, h23, l23;
        split_pair(v.x, v.y, &h01, &l01);
        split_pair(v.z, v.w, &h23, &l23);
        *(__nv_bfloat162*)&sm->Qh[row][c4]   = h01;
        *(__nv_bfloat162*)&sm->Qh[row][c4+2] = h23;
        *(__nv_bfloat162*)&sm->Ql[row][c4]   = l01;
        *(__nv_bfloat162*)&sm->Ql[row][c4+2] = l23;
    }
    if (tid < 64) { sm->M[tid] = -1e30f; sm->L[tid] = 0.f; }

    float co[8][4];
    #pragma unroll
    for (int nt = 0; nt < 8; ++nt)
        #pragma unroll
        for (int r = 0; r < 4; ++r) co[nt][r] = 0.f;

    const float* kbase = g_k + (size_t)(b*S_LEN)*(NG*DHEAD) + (size_t)g*DHEAD;
    const float* vbase = g_v + (size_t)(b*S_LEN)*(NG*DHEAD) + (size_t)g*DHEAD;
    const float scale = 0.08838834764831845f;

    for (int kt = 0; kt <= qt; ++kt) {
        int k0t = kt * 64;
        __syncthreads();
        /* load + split K, V (64 x 128 each) */
        #pragma unroll
        for (int i = 0; i < 8; ++i) {
            int fid = tid + i*256;
            int row = fid >> 5, c4 = (fid & 31) * 4;
            float4 kv = *(const float4*)(kbase + (size_t)(k0t + row)*(NG*DHEAD) + c4);
            __nv_bfloat162 h01, l01, h23, l23;
            split_pair(kv.x, kv.y, &h01, &l01);
            split_pair(kv.z, kv.w, &h23, &l23);
            *(__nv_bfloat162*)&sm->Kh[row][c4]   = h01;
            *(__nv_bfloat162*)&sm->Kh[row][c4+2] = h23;
            *(__nv_bfloat162*)&sm->Kl[row][c4]   = l01;
            *(__nv_bfloat162*)&sm->Kl[row][c4+2] = l23;
            float4 vv = *(const float4*)(vbase + (size_t)(k0t + row)*(NG*DHEAD) + c4);
            split_pair(vv.x, vv.y, &h01, &l01);
            split_pair(vv.z, vv.w, &h23, &l23);
            *(__nv_bfloat162*)&sm->Vh[row][c4]   = h01;
            *(__nv_bfloat162*)&sm->Vh[row][c4+2] = h23;
            *(__nv_bfloat162*)&sm->Vl[row][c4]   = l01;
            *(__nv_bfloat162*)&sm->Vl[row][c4+2] = l23;
        }
        __syncthreads();

        /* ---- S = Q @ K^T : warp tile 16x32 ---- */
        int n_s = (warp & 1) * 32;
        float cs[4][4];
        #pragma unroll
        for (int nt = 0; nt < 4; ++nt)
            #pragma unroll
            for (int r = 0; r < 4; ++r) cs[nt][r] = 0.f;

        #pragma unroll
        for (int ks = 0; ks < 8; ++ks) {
            int kk = ks * 16;
            uint32_t ah[4], al[4];
            int ar = m_base + (lane & 15);
            int ac = kk + (lane >> 4) * 8;
            ldsm_x4(ah, smem_u32(&sm->Qh[ar][ac]));
            ldsm_x4(al, smem_u32(&sm->Ql[ar][ac]));
            uint32_t kh[2][4], kl[2][4];
            #pragma unroll
            for (int gp = 0; gp < 2; ++gp) {
                int br = n_s + gp*16 + (lane & 7) + (lane >> 4) * 8;
                int bc = kk + ((lane >> 3) & 1) * 8;
                ldsm_x4(kh[gp], smem_u32(&sm->Kh[br][bc]));
                ldsm_x4(kl[gp], smem_u32(&sm->Kl[br][bc]));
            }
            #pragma unroll
            for (int nt = 0; nt < 4; ++nt) {
                int gp = nt >> 1, j = nt & 1;
                uint32_t b0h = kh[gp][j*2], b1h = kh[gp][j*2+1];
                uint32_t b0l = kl[gp][j*2], b1l = kl[gp][j*2+1];
                mma16816(cs[nt], ah, b0h, b1h);
                mma16816(cs[nt], ah, b0l, b1l);
                mma16816(cs[nt], al, b0h, b1h);
            }
        }

        /* write scaled + masked scores */
        #pragma unroll
        for (int nt = 0; nt < 4; ++nt)
            #pragma unroll
            for (int r2 = 0; r2 < 2; ++r2) {
                int row = m_base + (lane >> 2) + r2*8;
                int col = n_s + nt*8 + (lane & 3)*2;
                float v0 = cs[nt][r2*2]   * scale;
                float v1 = cs[nt][r2*2+1] * scale;
                if (k0t + col     > q0 + row) v0 = -1e30f;
                if (k0t + col + 1 > q0 + row) v1 = -1e30f;
                sm->S[row][col]   = v0;
                sm->S[row][col+1] = v1;
            }
        __syncthreads();

        /* ---- online softmax; P emitted as split bf16 ---- */
        {
            int r = tid >> 2, q4 = tid & 3;
            float mx = -1e30f;
            #pragma unroll
            for (int c = 0; c < 16; ++c) mx = fmaxf(mx, sm->S[r][q4*16 + c]);
            mx = fmaxf(mx, __shfl_xor_sync(0xffffffffu, mx, 1));
            mx = fmaxf(mx, __shfl_xor_sync(0xffffffffu, mx, 2));
            float m_old = sm->M[r];
            float m_new = fmaxf(m_old, mx);
            float lsum = 0.f;
            #pragma unroll
            for (int c = 0; c < 16; c += 2) {
                float p0 = __expf(sm->S[r][q4*16 + c]     - m_new);
                float p1 = __expf(sm->S[r][q4*16 + c + 1] - m_new);
                lsum += p0 + p1;
                __nv_bfloat162 hi, lo;
                split_pair(p0, p1, &hi, &lo);
                *(__nv_bfloat162*)&sm->Ph[r][q4*16 + c] = hi;
                *(__nv_bfloat162*)&sm->Pl[r][q4*16 + c] = lo;
            }
            lsum += __shfl_xor_sync(0xffffffffu, lsum, 1);
            lsum += __shfl_xor_sync(0xffffffffu, lsum, 2);
            if (q4 == 0) {
                sm->A[r] = __expf(m_old - m_new);
                sm->M[r] = m_new;
                sm->L[r] = sm->L[r]*sm->A[r] + lsum;
            }
        }
        __syncthreads();

        /* ---- O = O*alpha + P @ V : warp tile 16x64 ---- */
        int n_o = (warp & 1) * 64;
        float a0 = sm->A[m_base + (lane >> 2)];
        float a1 = sm->A[m_base + (lane >> 2) + 8];
        #pragma unroll
        for (int nt = 0; nt < 8; ++nt) {
            co[nt][0] *= a0; co[nt][1] *= a0;
            co[nt][2] *= a1; co[nt][3] *= a1;
        }
        #pragma unroll
        for (int ks = 0; ks < 4; ++ks) {
            int kk = ks * 16;
            uint32_t ph[4], pl[4];
            int ar = m_base + (lane & 15);
            int ac = kk + (lane >> 4) * 8;
            ldsm_x4(ph, smem_u32(&sm->Ph[ar][ac]));
            ldsm_x4(pl, smem_u32(&sm->Pl[ar][ac]));
            uint32_t vh[4][4], vl[4][4];
            #pragma unroll
            for (int gp = 0; gp < 4; ++gp) {
                int kr = kk + (lane & 7) + ((lane >> 3) & 1) * 8;
                int nn = n_o + gp*16 + (lane >> 4) * 8;
                ldsm_x4_t(vh[gp], smem_u32(&sm->Vh[kr][nn]));
                ldsm_x4_t(vl[gp], smem_u32(&sm->Vl[kr][nn]));
            }
            #pragma unroll
            for (int nt = 0; nt < 8; ++nt) {
                int gp = nt >> 1, j = nt & 1;
                uint32_t b0h = vh[gp][j*2], b1h = vh[gp][j*2+1];
                uint32_t b0l = vl[gp][j*2], b1l = vl[gp][j*2+1];
                mma16816(co[nt], ph, b0h, b1h);
                mma16816(co[nt], ph, b0l, b1l);
                mma16816(co[nt], pl, b0h, b1h);
            }
        }
    }

    __syncthreads();
    /* epilogue: normalize, write ctx */
    {
        int n_o = (warp & 1) * 64;
        int r0 = m_base + (lane >> 2);
        float il0 = 1.0f / sm->L[r0];
        float il1 = 1.0f / sm->L[r0 + 8];
        #pragma unroll
        for (int nt = 0; nt < 8; ++nt) {
            int col = n_o + nt*8 + (lane & 3)*2;
            size_t off0 = ((size_t)(b*S_LEN + q0 + r0))*(NH*DHEAD) + (size_t)h*DHEAD + col;
            size_t off1 = ((size_t)(b*S_LEN + q0 + r0 + 8))*(NH*DHEAD) + (size_t)h*DHEAD + col;
            *(float2*)(g_ctx + off0) = make_float2(co[nt][0]*il0, co[nt][1]*il0);
            *(float2*)(g_ctx + off1) = make_float2(co[nt][2]*il1, co[nt][3]*il1);
        }
    }
}

extern "C" void kernel_launch(void* const* d_in, const int* in_sizes, int n_in,
                              void* d_out, int out_size) {
    int idx_x = -1, sm_[2], nsm = 0, bg[3], nbg = 0;
    for (int i = 0; i < n_in; ++i) {
        if (in_sizes[i] == 8388608 && idx_x < 0) idx_x = i;
        else if (in_sizes[i] == 1048576 && nsm < 2) sm_[nsm++] = i;
        else if (in_sizes[i] == 4194304 && nbg < 3) bg[nbg++] = i;
    }
    const float *x, *Wk, *Wv;
    const unsigned char *c0, *c1, *c2;
    if (idx_x >= 0 && nsm == 2 && nbg == 3) {
        x  = (const float*)d_in[idx_x];
        Wk = (const float*)d_in[sm_[0]];
        Wv = (const float*)d_in[sm_[1]];
        c0 = (const unsigned char*)d_in[bg[0]];
        c1 = (const unsigned char*)d_in[bg[1]];
        c2 = (const unsigned char*)d_in[bg[2]];
    } else {
        x  = (const float*)d_in[0];
        Wk = (const float*)d_in[2];
        Wv = (const float*)d_in[3];
        c0 = (const unsigned char*)d_in[1];
        c1 = (const unsigned char*)d_in[4];
        c2 = (const unsigned char*)d_in[5];
    }
    float* out = (float*)d_out;

    float *qp, *kp;
    cudaGetSymbolAddress((void**)&qp, g_q);
    cudaGetSymbolAddress((void**)&kp, g_k);

    probe_kernel<<<1, 32>>>(c0, c1, c2);
    build_rope_kernel<<<S_LEN, 64>>>();

    qkv_gemm_bf16<<<dim3(24, MROWS/128), 256>>>(x, Wk, Wv);

    rope_kernel<<<dim3(MROWS, NH), 64>>>(qp, NH);
    rope_kernel<<<dim3(MROWS, NG), 64>>>(kp, NG);

    const size_t OUT_MAIN = (size_t)NB * S_LEN * D_MODEL;
    const size_t CACHE    = (size_t)NB * NG * S_LEN * DHEAD;
    if ((size_t)out_size >= OUT_MAIN + 2*CACHE) {
        cache_kernel<<<(int)((CACHE + 255)/256), 256>>>(out + OUT_MAIN);
    }

    int fl2_smem = (int)sizeof(SmemFlash);
    cudaFuncSetAttribute(flash2_kernel, cudaFuncAttributeMaxDynamicSharedMemorySize, fl2_smem);
    flash2_kernel<<<dim3(S_LEN/64, NH, NB), 256, fl2_smem>>>();

    out_gemm_bf16<<<dim3(D_MODEL/128, MROWS/128), 256>>>(out);
}

// round 8
// speedup vs baseline: 3.5648x; 1.1877x over previous
#include <cuda_runtime.h>
#include <cuda_bf16.h>
#include <math.h>
#include <stdint.h>

#define S_LEN   2048
#define D_MODEL 2048
#define NH      16
#define NG      4
#define DHEAD   128
#define NB      2
#define MROWS   (NB*S_LEN)
typedef __nv_bfloat16 bf16;
typedef __nv_bfloat162 bf162;

/* fp32 staging */
__device__ float g_q  [(size_t)MROWS * (NH*DHEAD)];
__device__ float g_k  [(size_t)MROWS * (NG*DHEAD)];
__device__ float g_v  [(size_t)MROWS * (NG*DHEAD)];
__device__ float g_rope[S_LEN * DHEAD];
__device__ const float* g_wq_slot;
__device__ const float* g_wo_slot;

/* persistent bf16 hi/lo splits */
__device__ bf16 g_xh [(size_t)MROWS * D_MODEL],      g_xl [(size_t)MROWS * D_MODEL];
__device__ bf16 g_wqh[(size_t)D_MODEL * NH*DHEAD],   g_wql[(size_t)D_MODEL * NH*DHEAD];
__device__ bf16 g_wkh[(size_t)D_MODEL * NG*DHEAD],   g_wkl[(size_t)D_MODEL * NG*DHEAD];
__device__ bf16 g_wvh[(size_t)D_MODEL * NG*DHEAD],   g_wvl[(size_t)D_MODEL * NG*DHEAD];
__device__ bf16 g_woh[(size_t)D_MODEL * D_MODEL],    g_wol[(size_t)D_MODEL * D_MODEL];
__device__ bf16 g_qh [(size_t)MROWS * NH*DHEAD],     g_ql [(size_t)MROWS * NH*DHEAD];
__device__ bf16 g_kh [(size_t)MROWS * NG*DHEAD],     g_kl [(size_t)MROWS * NG*DHEAD];
__device__ bf16 g_vh [(size_t)MROWS * NG*DHEAD],     g_vl [(size_t)MROWS * NG*DHEAD];
__device__ bf16 g_ch [(size_t)MROWS * NH*DHEAD],     g_cl [(size_t)MROWS * NH*DHEAD];

__global__ void probe_kernel(const unsigned char* c0, const unsigned char* c1,
                             const unsigned char* c2) {
    if (threadIdx.x != 0 || blockIdx.x != 0) return;
    const unsigned char* cs[3] = {c0, c1, c2};
    int nb[3];
    for (int i = 0; i < 3; ++i) {
        int boolish = 1;
        for (int k = 0; k < 64; ++k)
            if (cs[i][k * 97] > 1) { boolish = 0; break; }
        nb[i] = boolish;
    }
    int a = -1, b = -1;
    for (int i = 0; i < 3; ++i)
        if (!nb[i]) { if (a < 0) a = i; else if (b < 0) b = i; }
    if (a < 0 || b < 0) { a = 0; b = 1; }
    g_wq_slot = (const float*)cs[a];
    g_wo_slot = (const float*)cs[b];
}

__global__ void build_rope_kernel() {
    int s = blockIdx.x, d = threadIdx.x;
    float e    = (float)d / 64.0f;
    float invf = 1.0f / powf(10000.0f, e);
    float ang  = (float)s * invf;
    g_rope[s*DHEAD + d]      = (float)cos((double)ang);
    g_rope[s*DHEAD + 64 + d] = (float)sin((double)ang);
}

__device__ __forceinline__ void split_pair(float x, float y, bf162* hi, bf162* lo) {
    bf16 hx = __float2bfloat16_rn(x);
    bf16 hy = __float2bfloat16_rn(y);
    *hi = __halves2bfloat162(hx, hy);
    *lo = __halves2bfloat162(__float2bfloat16_rn(x - __bfloat162float(hx)),
                             __float2bfloat16_rn(y - __bfloat162float(hy)));
}

/* elementwise split: which 0=in ptr, 1=g_wq_slot, 2=g_wo_slot */
__global__ void split_kernel(const float* in, bf16* oh, bf16* ol, int n2, int which) {
    if (which == 1) in = g_wq_slot;
    else if (which == 2) in = g_wo_slot;
    int i = blockIdx.x * blockDim.x + threadIdx.x;
    if (i >= n2) return;
    float2 v = *(const float2*)(in + (size_t)i*2);
    bf162 hi, lo;
    split_pair(v.x, v.y, &hi, &lo);
    *(bf162*)(oh + (size_t)i*2) = hi;
    *(bf162*)(ol + (size_t)i*2) = lo;
}

/* rope + split q (q fp32 not needed afterwards) */
__global__ void rope_split_q() {
    int bs = blockIdx.x, h = blockIdx.y, d = threadIdx.x;
    int s = bs & (S_LEN - 1);
    size_t base = (size_t)bs * NH * DHEAD + (size_t)h * DHEAD;
    float c  = g_rope[s*DHEAD + d];
    float sn = g_rope[s*DHEAD + 64 + d];
    float x1 = g_q[base + d], x2 = g_q[base + 64 + d];
    float r1 = x1*c - x2*sn, r2 = x2*c + x1*sn;
    bf16 h1 = __float2bfloat16_rn(r1), h2 = __float2bfloat16_rn(r2);
    g_qh[base + d]      = h1;
    g_qh[base + 64 + d] = h2;
    g_ql[base + d]      = __float2bfloat16_rn(r1 - __bfloat162float(h1));
    g_ql[base + 64 + d] = __float2bfloat16_rn(r2 - __bfloat162float(h2));
}

/* rope + split k; keeps roped fp32 k for the cache output */
__global__ void rope_split_k() {
    int bs = blockIdx.x, h = blockIdx.y, d = threadIdx.x;
    int s = bs & (S_LEN - 1);
    size_t base = (size_t)bs * NG * DHEAD + (size_t)h * DHEAD;
    float c  = g_rope[s*DHEAD + d];
    float sn = g_rope[s*DHEAD + 64 + d];
    float x1 = g_k[base + d], x2 = g_k[base + 64 + d];
    float r1 = x1*c - x2*sn, r2 = x2*c + x1*sn;
    g_k[base + d]      = r1;
    g_k[base + 64 + d] = r2;
    bf16 h1 = __float2bfloat16_rn(r1), h2 = __float2bfloat16_rn(r2);
    g_kh[base + d]      = h1;
    g_kh[base + 64 + d] = h2;
    g_kl[base + d]      = __float2bfloat16_rn(r1 - __bfloat162float(h1));
    g_kl[base + 64 + d] = __float2bfloat16_rn(r2 - __bfloat162float(h2));
}

__global__ void cache_kernel(float* __restrict__ outc) {
    const size_t CACHE = (size_t)NB*NG*S_LEN*DHEAD;
    size_t idx = (size_t)blockIdx.x * blockDim.x + threadIdx.x;
    if (idx >= CACHE) return;
    int d = (int)(idx & 127);
    int s = (int)((idx >> 7) & (S_LEN-1));
    int g = (int)((idx >> 18) & (NG-1));
    int b = (int)(idx >> 20);
    size_t src = ((size_t)(b*S_LEN + s))*(NG*DHEAD) + (size_t)g*DHEAD + d;
    outc[idx]         = g_k[src];
    outc[CACHE + idx] = g_v[src];
}

/* ================= mma helpers =========================================== */
__device__ __forceinline__ uint32_t smem_u32(const void* p) {
    return (uint32_t)__cvta_generic_to_shared(p);
}
__device__ __forceinline__ void ldsm_x4(uint32_t* r, uint32_t addr) {
    asm volatile("ldmatrix.sync.aligned.m8n8.x4.shared.b16 {%0,%1,%2,%3}, [%4];"
        : "=r"(r[0]), "=r"(r[1]), "=r"(r[2]), "=r"(r[3]) : "r"(addr));
}
__device__ __forceinline__ void ldsm_x4_t(uint32_t* r, uint32_t addr) {
    asm volatile("ldmatrix.sync.aligned.m8n8.x4.trans.shared.b16 {%0,%1,%2,%3}, [%4];"
        : "=r"(r[0]), "=r"(r[1]), "=r"(r[2]), "=r"(r[3]) : "r"(addr));
}
__device__ __forceinline__ void mma16816(float* c, const uint32_t* a,
                                         uint32_t b0, uint32_t b1) {
    asm volatile("mma.sync.aligned.m16n8k16.row.col.f32.bf16.bf16.f32 "
        "{%0,%1,%2,%3}, {%4,%5,%6,%7}, {%8,%9}, {%0,%1,%2,%3};"
        : "+f"(c[0]), "+f"(c[1]), "+f"(c[2]), "+f"(c[3])
        : "r"(a[0]), "r"(a[1]), "r"(a[2]), "r"(a[3]), "r"(b0), "r"(b1));
}

/* ================= pre-split bf16 GEMM =================================== */
struct SmemGemm {
    bf16 Ah[128][40], Al[128][40];
    bf16 Bh[32][136], Bl[32][136];
};

__device__ __forceinline__ void gemm_presplit(SmemGemm* sm,
                                              const bf16* __restrict__ Ah,
                                              const bf16* __restrict__ Al,
                                              const bf16* __restrict__ Bh,
                                              const bf16* __restrict__ Bl,
                                              float* __restrict__ C,
                                              int N, int K, int bm, int bn) {
    int tid = threadIdx.x;
    int warp = tid >> 5, lane = tid & 31;
    int m_base = (warp >> 1) * 32;
    int n_base = (warp & 1) * 64;

    float c[2][8][4];
    #pragma unroll
    for (int mt = 0; mt < 2; ++mt)
        #pragma unroll
        for (int nt = 0; nt < 8; ++nt)
            #pragma unroll
            for (int r = 0; r < 4; ++r) c[mt][nt][r] = 0.f;

    for (int k0 = 0; k0 < K; k0 += 32) {
        __syncthreads();
        /* A: 128x32 bf16 per buffer; 512 uint4 / 256 threads = 2 each */
        #pragma unroll
        for (int i = 0; i < 2; ++i) {
            int fid = tid + i*256;
            int row = fid >> 2, c8 = (fid & 3) * 8;
            size_t go = (size_t)(bm + row)*K + k0 + c8;
            *(uint4*)&sm->Ah[row][c8] = *(const uint4*)(Ah + go);
            *(uint4*)&sm->Al[row][c8] = *(const uint4*)(Al + go);
        }
        /* B: 32x128 bf16 per buffer */
        #pragma unroll
        for (int i = 0; i < 2; ++i) {
            int fid = tid + i*256;
            int row = fid >> 4, c8 = (fid & 15) * 8;
            size_t go = (size_t)(k0 + row)*N + bn + c8;
            *(uint4*)&sm->Bh[row][c8] = *(const uint4*)(Bh + go);
            *(uint4*)&sm->Bl[row][c8] = *(const uint4*)(Bl + go);
        }
        __syncthreads();

        #pragma unroll
        for (int ks = 0; ks < 32; ks += 16) {
            uint32_t ah[2][4], al[2][4];
            #pragma unroll
            for (int mt = 0; mt < 2; ++mt) {
                int rr = m_base + mt*16 + (lane & 15);
                int kk = ks + (lane >> 4) * 8;
                ldsm_x4(ah[mt], smem_u32(&sm->Ah[rr][kk]));
                ldsm_x4(al[mt], smem_u32(&sm->Al[rr][kk]));
            }
            uint32_t bh[4][4], bl[4][4];
            #pragma unroll
            for (int nc = 0; nc < 4; ++nc) {
                int kr = ks + (lane & 7) + ((lane >> 3) & 1) * 8;
                int nn = n_base + nc*16 + (lane >> 4) * 8;
                ldsm_x4_t(bh[nc], smem_u32(&sm->Bh[kr][nn]));
                ldsm_x4_t(bl[nc], smem_u32(&sm->Bl[kr][nn]));
            }
            #pragma unroll
            for (int mt = 0; mt < 2; ++mt)
                #pragma unroll
                for (int nc = 0; nc < 4; ++nc)
                    #pragma unroll
                    for (int hf = 0; hf < 2; ++hf) {
                        float* cc = c[mt][nc*2 + hf];
                        uint32_t b0h = bh[nc][hf*2], b1h = bh[nc][hf*2+1];
                        uint32_t b0l = bl[nc][hf*2], b1l = bl[nc][hf*2+1];
                        mma16816(cc, ah[mt], b0h, b1h);
                        mma16816(cc, ah[mt], b0l, b1l);
                        mma16816(cc, al[mt], b0h, b1h);
                    }
        }
    }

    #pragma unroll
    for (int mt = 0; mt < 2; ++mt)
        #pragma unroll
        for (int nt = 0; nt < 8; ++nt) {
            int r   = bm + m_base + mt*16 + (lane >> 2);
            int col = bn + n_base + nt*8 + (lane & 3)*2;
            *(float2*)(C + (size_t)r*N + col)     = make_float2(c[mt][nt][0], c[mt][nt][1]);
            *(float2*)(C + (size_t)(r+8)*N + col) = make_float2(c[mt][nt][2], c[mt][nt][3]);
        }
}

__global__ void __launch_bounds__(256) qkv_gemm_bf16() {
    __shared__ SmemGemm sm;
    int bx = blockIdx.x, bm = blockIdx.y * 128;
    if (bx < 16)
        gemm_presplit(&sm, g_xh, g_xl, g_wqh, g_wql, g_q, NH*DHEAD, D_MODEL, bm, bx*128);
    else if (bx < 20)
        gemm_presplit(&sm, g_xh, g_xl, g_wkh, g_wkl, g_k, NG*DHEAD, D_MODEL, bm, (bx-16)*128);
    else
        gemm_presplit(&sm, g_xh, g_xl, g_wvh, g_wvl, g_v, NG*DHEAD, D_MODEL, bm, (bx-20)*128);
}

__global__ void __launch_bounds__(256) out_gemm_bf16(float* __restrict__ C) {
    __shared__ SmemGemm sm;
    gemm_presplit(&sm, g_ch, g_cl, g_woh, g_wol, C, D_MODEL, D_MODEL,
                  blockIdx.y*128, blockIdx.x*128);
}

/* ================= tensor-core flash attention (pre-split inputs) ======== */
struct SmemFlash {
    bf16 Qh[64][136], Ql[64][136];
    bf16 Kh[64][136], Kl[64][136];
    bf16 Vh[64][136], Vl[64][136];
    float S[64][68];
    bf16 Ph[64][72], Pl[64][72];
    float M[64], L[64], A[64];
};

__global__ void __launch_bounds__(256) flash2_kernel() {
    extern __shared__ char smraw[];
    SmemFlash* sm = (SmemFlash*)smraw;

    int qt = blockIdx.x, h = blockIdx.y, b = blockIdx.z;
    int g  = h >> 2;
    int q0 = qt * 64;
    int tid = threadIdx.x, warp = tid >> 5, lane = tid & 31;
    int m_base = (warp >> 1) * 16;

    /* load pre-split Q (64 x 128, bf16 x2) */
    size_t qoff = ((size_t)(b*S_LEN + q0))*(NH*DHEAD) + (size_t)h*DHEAD;
    #pragma unroll
    for (int i = 0; i < 4; ++i) {
        int fid = tid + i*256;
        int row = fid >> 4, c8 = (fid & 15) * 8;
        size_t go = qoff + (size_t)row*(NH*DHEAD) + c8;
        *(uint4*)&sm->Qh[row][c8] = *(const uint4*)(g_qh + go);
        *(uint4*)&sm->Ql[row][c8] = *(const uint4*)(g_ql + go);
    }
    if (tid < 64) { sm->M[tid] = -1e30f; sm->L[tid] = 0.f; }

    float co[8][4];
    #pragma unroll
    for (int nt = 0; nt < 8; ++nt)
        #pragma unroll
        for (int r = 0; r < 4; ++r) co[nt][r] = 0.f;

    size_t kvoff = (size_t)(b*S_LEN)*(NG*DHEAD) + (size_t)g*DHEAD;
    const float scale = 0.08838834764831845f;

    for (int kt = 0; kt <= qt; ++kt) {
        int k0t = kt * 64;
        __syncthreads();
        #pragma unroll
        for (int i = 0; i < 4; ++i) {
            int fid = tid + i*256;
            int row = fid >> 4, c8 = (fid & 15) * 8;
            size_t go = kvoff + (size_t)(k0t + row)*(NG*DHEAD) + c8;
            *(uint4*)&sm->Kh[row][c8] = *(const uint4*)(g_kh + go);
            *(uint4*)&sm->Kl[row][c8] = *(const uint4*)(g_kl + go);
            *(uint4*)&sm->Vh[row][c8] = *(const uint4*)(g_vh + go);
            *(uint4*)&sm->Vl[row][c8] = *(const uint4*)(g_vl + go);
        }
        __syncthreads();

        /* S = Q @ K^T : warp tile 16x32 */
        int n_s = (warp & 1) * 32;
        float cs[4][4];
        #pragma unroll
        for (int nt = 0; nt < 4; ++nt)
            #pragma unroll
            for (int r = 0; r < 4; ++r) cs[nt][r] = 0.f;

        #pragma unroll
        for (int ks = 0; ks < 8; ++ks) {
            int kk = ks * 16;
            uint32_t ah[4], al[4];
            int ar = m_base + (lane & 15);
            int ac = kk + (lane >> 4) * 8;
            ldsm_x4(ah, smem_u32(&sm->Qh[ar][ac]));
            ldsm_x4(al, smem_u32(&sm->Ql[ar][ac]));
            uint32_t kh[2][4], kl[2][4];
            #pragma unroll
            for (int gp = 0; gp < 2; ++gp) {
                int br = n_s + gp*16 + (lane & 7) + (lane >> 4) * 8;
                int bc = kk + ((lane >> 3) & 1) * 8;
                ldsm_x4(kh[gp], smem_u32(&sm->Kh[br][bc]));
                ldsm_x4(kl[gp], smem_u32(&sm->Kl[br][bc]));
            }
            #pragma unroll
            for (int nt = 0; nt < 4; ++nt) {
                int gp = nt >> 1, j = nt & 1;
                uint32_t b0h = kh[gp][j*2], b1h = kh[gp][j*2+1];
                uint32_t b0l = kl[gp][j*2], b1l = kl[gp][j*2+1];
                mma16816(cs[nt], ah, b0h, b1h);
                mma16816(cs[nt], ah, b0l, b1l);
                mma16816(cs[nt], al, b0h, b1h);
            }
        }

        #pragma unroll
        for (int nt = 0; nt < 4; ++nt)
            #pragma unroll
            for (int r2 = 0; r2 < 2; ++r2) {
                int row = m_base + (lane >> 2) + r2*8;
                int col = n_s + nt*8 + (lane & 3)*2;
                float v0 = cs[nt][r2*2]   * scale;
                float v1 = cs[nt][r2*2+1] * scale;
                if (k0t + col     > q0 + row) v0 = -1e30f;
                if (k0t + col + 1 > q0 + row) v1 = -1e30f;
                sm->S[row][col]   = v0;
                sm->S[row][col+1] = v1;
            }
        __syncthreads();

        /* online softmax; P emitted split */
        {
            int r = tid >> 2, q4 = tid & 3;
            float mx = -1e30f;
            #pragma unroll
            for (int c = 0; c < 16; ++c) mx = fmaxf(mx, sm->S[r][q4*16 + c]);
            mx = fmaxf(mx, __shfl_xor_sync(0xffffffffu, mx, 1));
            mx = fmaxf(mx, __shfl_xor_sync(0xffffffffu, mx, 2));
            float m_old = sm->M[r];
            float m_new = fmaxf(m_old, mx);
            float lsum = 0.f;
            #pragma unroll
            for (int c = 0; c < 16; c += 2) {
                float p0 = __expf(sm->S[r][q4*16 + c]     - m_new);
                float p1 = __expf(sm->S[r][q4*16 + c + 1] - m_new);
                lsum += p0 + p1;
                bf162 hi, lo;
                split_pair(p0, p1, &hi, &lo);
                *(bf162*)&sm->Ph[r][q4*16 + c] = hi;
                *(bf162*)&sm->Pl[r][q4*16 + c] = lo;
            }
            lsum += __shfl_xor_sync(0xffffffffu, lsum, 1);
            lsum += __shfl_xor_sync(0xffffffffu, lsum, 2);
            if (q4 == 0) {
                sm->A[r] = __expf(m_old - m_new);
                sm->M[r] = m_new;
                sm->L[r] = sm->L[r]*sm->A[r] + lsum;
            }
        }
        __syncthreads();

        /* O = O*alpha + P @ V : warp tile 16x64 */
        int n_o = (warp & 1) * 64;
        float a0 = sm->A[m_base + (lane >> 2)];
        float a1 = sm->A[m_base + (lane >> 2) + 8];
        #pragma unroll
        for (int nt = 0; nt < 8; ++nt) {
            co[nt][0] *= a0; co[nt][1] *= a0;
            co[nt][2] *= a1; co[nt][3] *= a1;
        }
        #pragma unroll
        for (int ks = 0; ks < 4; ++ks) {
            int kk = ks * 16;
            uint32_t ph[4], pl[4];
            int ar = m_base + (lane & 15);
            int ac = kk + (lane >> 4) * 8;
            ldsm_x4(ph, smem_u32(&sm->Ph[ar][ac]));
            ldsm_x4(pl, smem_u32(&sm->Pl[ar][ac]));
            uint32_t vh[4][4], vl[4][4];
            #pragma unroll
            for (int gp = 0; gp < 4; ++gp) {
                int kr = kk + (lane & 7) + ((lane >> 3) & 1) * 8;
                int nn = n_o + gp*16 + (lane >> 4) * 8;
                ldsm_x4_t(vh[gp], smem_u32(&sm->Vh[kr][nn]));
                ldsm_x4_t(vl[gp], smem_u32(&sm->Vl[kr][nn]));
            }
            #pragma unroll
            for (int nt = 0; nt < 8; ++nt) {
                int gp = nt >> 1, j = nt & 1;
                uint32_t b0h = vh[gp][j*2], b1h = vh[gp][j*2+1];
                uint32_t b0l = vl[gp][j*2], b1l = vl[gp][j*2+1];
                mma16816(co[nt], ph, b0h, b1h);
                mma16816(co[nt], ph, b0l, b1l);
                mma16816(co[nt], pl, b0h, b1h);
            }
        }
    }

    __syncthreads();
    /* epilogue: normalize, split, write ctx hi/lo */
    {
        int n_o = (warp & 1) * 64;
        int r0 = m_base + (lane >> 2);
        float il0 = 1.0f / sm->L[r0];
        float il1 = 1.0f / sm->L[r0 + 8];
        #pragma unroll
        for (int nt = 0; nt < 8; ++nt) {
            int col = n_o + nt*8 + (lane & 3)*2;
            size_t off0 = ((size_t)(b*S_LEN + q0 + r0))*(NH*DHEAD) + (size_t)h*DHEAD + col;
            size_t off1 = ((size_t)(b*S_LEN + q0 + r0 + 8))*(NH*DHEAD) + (size_t)h*DHEAD + col;
            bf162 hi, lo;
            split_pair(co[nt][0]*il0, co[nt][1]*il0, &hi, &lo);
            *(bf162*)(g_ch + off0) = hi;
            *(bf162*)(g_cl + off0) = lo;
            split_pair(co[nt][2]*il1, co[nt][3]*il1, &hi, &lo);
            *(bf162*)(g_ch + off1) = hi;
            *(bf162*)(g_cl + off1) = lo;
        }
    }
}

extern "C" void kernel_launch(void* const* d_in, const int* in_sizes, int n_in,
                              void* d_out, int out_size) {
    int idx_x = -1, sm_[2], nsm = 0, bg[3], nbg = 0;
    for (int i = 0; i < n_in; ++i) {
        if (in_sizes[i] == 8388608 && idx_x < 0) idx_x = i;
        else if (in_sizes[i] == 1048576 && nsm < 2) sm_[nsm++] = i;
        else if (in_sizes[i] == 4194304 && nbg < 3) bg[nbg++] = i;
    }
    const float *x, *Wk, *Wv;
    const unsigned char *c0, *c1, *c2;
    if (idx_x >= 0 && nsm == 2 && nbg == 3) {
        x  = (const float*)d_in[idx_x];
        Wk = (const float*)d_in[sm_[0]];
        Wv = (const float*)d_in[sm_[1]];
        c0 = (const unsigned char*)d_in[bg[0]];
        c1 = (const unsigned char*)d_in[bg[1]];
        c2 = (const unsigned char*)d_in[bg[2]];
    } else {
        x  = (const float*)d_in[0];
        Wk = (const float*)d_in[2];
        Wv = (const float*)d_in[3];
        c0 = (const unsigned char*)d_in[1];
        c1 = (const unsigned char*)d_in[4];
        c2 = (const unsigned char*)d_in[5];
    }
    float* out = (float*)d_out;

    bf16 *xh, *xl, *wqh, *wql, *wkh, *wkl, *wvh, *wvl, *woh, *wol, *vh, *vl;
    float *vp;
    cudaGetSymbolAddress((void**)&xh,  g_xh);  cudaGetSymbolAddress((void**)&xl,  g_xl);
    cudaGetSymbolAddress((void**)&wqh, g_wqh); cudaGetSymbolAddress((void**)&wql, g_wql);
    cudaGetSymbolAddress((void**)&wkh, g_wkh); cudaGetSymbolAddress((void**)&wkl, g_wkl);
    cudaGetSymbolAddress((void**)&wvh, g_wvh); cudaGetSymbolAddress((void**)&wvl, g_wvl);
    cudaGetSymbolAddress((void**)&woh, g_woh); cudaGetSymbolAddress((void**)&wol, g_wol);
    cudaGetSymbolAddress((void**)&vh,  g_vh);  cudaGetSymbolAddress((void**)&vl,  g_vl);
    cudaGetSymbolAddress((void**)&vp,  g_v);

    probe_kernel<<<1, 32>>>(c0, c1, c2);
    build_rope_kernel<<<S_LEN, 64>>>();

    /* one-time splits (elementwise over float2) */
    split_kernel<<<(MROWS*D_MODEL/2 + 255)/256, 256>>>(x, xh, xl, MROWS*D_MODEL/2, 0);
    split_kernel<<<(D_MODEL*NH*DHEAD/2 + 255)/256, 256>>>(0, wqh, wql, D_MODEL*NH*DHEAD/2, 1);
    split_kernel<<<(D_MODEL*NG*DHEAD/2 + 255)/256, 256>>>(Wk, wkh, wkl, D_MODEL*NG*DHEAD/2, 0);
    split_kernel<<<(D_MODEL*NG*DHEAD/2 + 255)/256, 256>>>(Wv, wvh, wvl, D_MODEL*NG*DHEAD/2, 0);
    split_kernel<<<(D_MODEL*D_MODEL/2 + 255)/256, 256>>>(0, woh, wol, D_MODEL*D_MODEL/2, 2);

    qkv_gemm_bf16<<<dim3(24, MROWS/128), 256>>>();

    rope_split_q<<<dim3(MROWS, NH), 64>>>();
    rope_split_k<<<dim3(MROWS, NG), 64>>>();
    split_kernel<<<(MROWS*NG*DHEAD/2 + 255)/256, 256>>>(vp, vh, vl, MROWS*NG*DHEAD/2, 0);

    const size_t OUT_MAIN = (size_t)NB * S_LEN * D_MODEL;
    const size_t CACHE    = (size_t)NB * NG * S_LEN * DHEAD;
    if ((size_t)out_size >= OUT_MAIN + 2*CACHE) {
        cache_kernel<<<(int)((CACHE + 255)/256), 256>>>(out + OUT_MAIN);
    }

    int fl2_smem = (int)sizeof(SmemFlash);
    cudaFuncSetAttribute(flash2_kernel, cudaFuncAttributeMaxDynamicSharedMemorySize, fl2_smem);
    flash2_kernel<<<dim3(S_LEN/64, NH, NB), 256, fl2_smem>>>();

    out_gemm_bf16<<<dim3(D_MODEL/128, MROWS/128), 256>>>(out);
}

// round 9
// speedup vs baseline: 4.2713x; 1.1982x over previous
#include <cuda_runtime.h>
#include <cuda_bf16.h>
#include <math.h>
#include <stdint.h>

#define S_LEN   2048
#define D_MODEL 2048
#define NH      16
#define NG      4
#define DHEAD   128
#define NB      2
#define MROWS   (NB*S_LEN)
typedef __nv_bfloat16 bf16;
typedef __nv_bfloat162 bf162;

/* fp32 staging */
__device__ float g_q  [(size_t)MROWS * (NH*DHEAD)];
__device__ float g_k  [(size_t)MROWS * (NG*DHEAD)];
__device__ float g_v  [(size_t)MROWS * (NG*DHEAD)];
__device__ float g_rope[S_LEN * DHEAD];
__device__ const float* g_wq_slot;
__device__ const float* g_wo_slot;

/* persistent bf16 hi/lo splits */
__device__ bf16 g_xh [(size_t)MROWS * D_MODEL],      g_xl [(size_t)MROWS * D_MODEL];
__device__ bf16 g_wqh[(size_t)D_MODEL * NH*DHEAD],   g_wql[(size_t)D_MODEL * NH*DHEAD];
__device__ bf16 g_wkh[(size_t)D_MODEL * NG*DHEAD],   g_wkl[(size_t)D_MODEL * NG*DHEAD];
__device__ bf16 g_wvh[(size_t)D_MODEL * NG*DHEAD],   g_wvl[(size_t)D_MODEL * NG*DHEAD];
__device__ bf16 g_woh[(size_t)D_MODEL * D_MODEL],    g_wol[(size_t)D_MODEL * D_MODEL];
__device__ bf16 g_qh [(size_t)MROWS * NH*DHEAD],     g_ql [(size_t)MROWS * NH*DHEAD];
__device__ bf16 g_kh [(size_t)MROWS * NG*DHEAD],     g_kl [(size_t)MROWS * NG*DHEAD];
__device__ bf16 g_vh [(size_t)MROWS * NG*DHEAD],     g_vl [(size_t)MROWS * NG*DHEAD];
__device__ bf16 g_ch [(size_t)MROWS * NH*DHEAD],     g_cl [(size_t)MROWS * NH*DHEAD];

__global__ void probe_kernel(const unsigned char* c0, const unsigned char* c1,
                             const unsigned char* c2) {
    if (threadIdx.x != 0 || blockIdx.x != 0) return;
    const unsigned char* cs[3] = {c0, c1, c2};
    int nb[3];
    for (int i = 0; i < 3; ++i) {
        int boolish = 1;
        for (int k = 0; k < 64; ++k)
            if (cs[i][k * 97] > 1) { boolish = 0; break; }
        nb[i] = boolish;
    }
    int a = -1, b = -1;
    for (int i = 0; i < 3; ++i)
        if (!nb[i]) { if (a < 0) a = i; else if (b < 0) b = i; }
    if (a < 0 || b < 0) { a = 0; b = 1; }
    g_wq_slot = (const float*)cs[a];
    g_wo_slot = (const float*)cs[b];
}

__global__ void build_rope_kernel() {
    int s = blockIdx.x, d = threadIdx.x;
    float e    = (float)d / 64.0f;
    float invf = 1.0f / powf(10000.0f, e);
    float ang  = (float)s * invf;
    g_rope[s*DHEAD + d]      = (float)cos((double)ang);
    g_rope[s*DHEAD + 64 + d] = (float)sin((double)ang);
}

__device__ __forceinline__ void split_pair(float x, float y, bf162* hi, bf162* lo) {
    bf16 hx = __float2bfloat16_rn(x);
    bf16 hy = __float2bfloat16_rn(y);
    *hi = __halves2bfloat162(hx, hy);
    *lo = __halves2bfloat162(__float2bfloat16_rn(x - __bfloat162float(hx)),
                             __float2bfloat16_rn(y - __bfloat162float(hy)));
}

__global__ void split_kernel(const float* in, bf16* oh, bf16* ol, int n2, int which) {
    if (which == 1) in = g_wq_slot;
    else if (which == 2) in = g_wo_slot;
    int i = blockIdx.x * blockDim.x + threadIdx.x;
    if (i >= n2) return;
    float2 v = *(const float2*)(in + (size_t)i*2);
    bf162 hi, lo;
    split_pair(v.x, v.y, &hi, &lo);
    *(bf162*)(oh + (size_t)i*2) = hi;
    *(bf162*)(ol + (size_t)i*2) = lo;
}

__global__ void rope_split_q() {
    int bs = blockIdx.x, h = blockIdx.y, d = threadIdx.x;
    int s = bs & (S_LEN - 1);
    size_t base = (size_t)bs * NH * DHEAD + (size_t)h * DHEAD;
    float c  = g_rope[s*DHEAD + d];
    float sn = g_rope[s*DHEAD + 64 + d];
    float x1 = g_q[base + d], x2 = g_q[base + 64 + d];
    float r1 = x1*c - x2*sn, r2 = x2*c + x1*sn;
    bf16 h1 = __float2bfloat16_rn(r1), h2 = __float2bfloat16_rn(r2);
    g_qh[base + d]      = h1;
    g_qh[base + 64 + d] = h2;
    g_ql[base + d]      = __float2bfloat16_rn(r1 - __bfloat162float(h1));
    g_ql[base + 64 + d] = __float2bfloat16_rn(r2 - __bfloat162float(h2));
}

__global__ void rope_split_k() {
    int bs = blockIdx.x, h = blockIdx.y, d = threadIdx.x;
    int s = bs & (S_LEN - 1);
    size_t base = (size_t)bs * NG * DHEAD + (size_t)h * DHEAD;
    float c  = g_rope[s*DHEAD + d];
    float sn = g_rope[s*DHEAD + 64 + d];
    float x1 = g_k[base + d], x2 = g_k[base + 64 + d];
    float r1 = x1*c - x2*sn, r2 = x2*c + x1*sn;
    g_k[base + d]      = r1;
    g_k[base + 64 + d] = r2;
    bf16 h1 = __float2bfloat16_rn(r1), h2 = __float2bfloat16_rn(r2);
    g_kh[base + d]      = h1;
    g_kh[base + 64 + d] = h2;
    g_kl[base + d]      = __float2bfloat16_rn(r1 - __bfloat162float(h1));
    g_kl[base + 64 + d] = __float2bfloat16_rn(r2 - __bfloat162float(h2));
}

__global__ void cache_kernel(float* __restrict__ outc) {
    const size_t CACHE = (size_t)NB*NG*S_LEN*DHEAD;
    size_t idx = (size_t)blockIdx.x * blockDim.x + threadIdx.x;
    if (idx >= CACHE) return;
    int d = (int)(idx & 127);
    int s = (int)((idx >> 7) & (S_LEN-1));
    int g = (int)((idx >> 18) & (NG-1));
    int b = (int)(idx >> 20);
    size_t src = ((size_t)(b*S_LEN + s))*(NG*DHEAD) + (size_t)g*DHEAD + d;
    outc[idx]         = g_k[src];
    outc[CACHE + idx] = g_v[src];
}

/* ================= mma / async helpers ==================================== */
__device__ __forceinline__ uint32_t smem_u32(const void* p) {
    return (uint32_t)__cvta_generic_to_shared(p);
}
__device__ __forceinline__ void cp_async16(void* smem, const void* gmem) {
    asm volatile("cp.async.cg.shared.global [%0], [%1], 16;"
        :: "r"(smem_u32(smem)), "l"(gmem));
}
__device__ __forceinline__ void cp_commit() {
    asm volatile("cp.async.commit_group;");
}
__device__ __forceinline__ void ldsm_x4(uint32_t* r, uint32_t addr) {
    asm volatile("ldmatrix.sync.aligned.m8n8.x4.shared.b16 {%0,%1,%2,%3}, [%4];"
        : "=r"(r[0]), "=r"(r[1]), "=r"(r[2]), "=r"(r[3]) : "r"(addr));
}
__device__ __forceinline__ void ldsm_x4_t(uint32_t* r, uint32_t addr) {
    asm volatile("ldmatrix.sync.aligned.m8n8.x4.trans.shared.b16 {%0,%1,%2,%3}, [%4];"
        : "=r"(r[0]), "=r"(r[1]), "=r"(r[2]), "=r"(r[3]) : "r"(addr));
}
__device__ __forceinline__ void mma16816(float* c, const uint32_t* a,
                                         uint32_t b0, uint32_t b1) {
    asm volatile("mma.sync.aligned.m16n8k16.row.col.f32.bf16.bf16.f32 "
        "{%0,%1,%2,%3}, {%4,%5,%6,%7}, {%8,%9}, {%0,%1,%2,%3};"
        : "+f"(c[0]), "+f"(c[1]), "+f"(c[2]), "+f"(c[3])
        : "r"(a[0]), "r"(a[1]), "r"(a[2]), "r"(a[3]), "r"(b0), "r"(b1));
}

/* ================= pipelined pre-split bf16 GEMM ========================== */
struct SmemGemmP {
    bf16 Ah[2][128][40], Al[2][128][40];
    bf16 Bh[2][32][136], Bl[2][32][136];
};

__device__ __forceinline__ void gemm_load_stage(SmemGemmP* sm, int st,
                                                const bf16* Ah, const bf16* Al,
                                                const bf16* Bh, const bf16* Bl,
                                                int N, int K, int bm, int bn, int k0) {
    int tid = threadIdx.x;
    #pragma unroll
    for (int i = 0; i < 2; ++i) {
        int fid = tid + i*256;
        int row = fid >> 2, c8 = (fid & 3) * 8;
        size_t go = (size_t)(bm + row)*K + k0 + c8;
        cp_async16(&sm->Ah[st][row][c8], Ah + go);
        cp_async16(&sm->Al[st][row][c8], Al + go);
    }
    #pragma unroll
    for (int i = 0; i < 2; ++i) {
        int fid = tid + i*256;
        int row = fid >> 4, c8 = (fid & 15) * 8;
        size_t go = (size_t)(k0 + row)*N + bn + c8;
        cp_async16(&sm->Bh[st][row][c8], Bh + go);
        cp_async16(&sm->Bl[st][row][c8], Bl + go);
    }
}

__device__ __forceinline__ void gemm_presplit(SmemGemmP* sm,
                                              const bf16* __restrict__ Ah,
                                              const bf16* __restrict__ Al,
                                              const bf16* __restrict__ Bh,
                                              const bf16* __restrict__ Bl,
                                              float* __restrict__ C,
                                              int N, int K, int bm, int bn) {
    int tid = threadIdx.x;
    int warp = tid >> 5, lane = tid & 31;
    int m_base = (warp >> 1) * 32;
    int n_base = (warp & 1) * 64;

    float c[2][8][4];
    #pragma unroll
    for (int mt = 0; mt < 2; ++mt)
        #pragma unroll
        for (int nt = 0; nt < 8; ++nt)
            #pragma unroll
            for (int r = 0; r < 4; ++r) c[mt][nt][r] = 0.f;

    const int NIT = K / 32;
    gemm_load_stage(sm, 0, Ah, Al, Bh, Bl, N, K, bm, bn, 0);
    cp_commit();

    for (int it = 0; it < NIT; ++it) {
        int cur = it & 1;
        if (it + 1 < NIT) {
            gemm_load_stage(sm, cur ^ 1, Ah, Al, Bh, Bl, N, K, bm, bn, (it+1)*32);
            cp_commit();
            asm volatile("cp.async.wait_group 1;" ::: "memory");
        } else {
            asm volatile("cp.async.wait_group 0;" ::: "memory");
        }
        __syncthreads();

        #pragma unroll
        for (int ks = 0; ks < 32; ks += 16) {
            uint32_t ah[2][4], al[2][4];
            #pragma unroll
            for (int mt = 0; mt < 2; ++mt) {
                int rr = m_base + mt*16 + (lane & 15);
                int kk = ks + (lane >> 4) * 8;
                ldsm_x4(ah[mt], smem_u32(&sm->Ah[cur][rr][kk]));
                ldsm_x4(al[mt], smem_u32(&sm->Al[cur][rr][kk]));
            }
            uint32_t bh[4][4], bl[4][4];
            #pragma unroll
            for (int nc = 0; nc < 4; ++nc) {
                int kr = ks + (lane & 7) + ((lane >> 3) & 1) * 8;
                int nn = n_base + nc*16 + (lane >> 4) * 8;
                ldsm_x4_t(bh[nc], smem_u32(&sm->Bh[cur][kr][nn]));
                ldsm_x4_t(bl[nc], smem_u32(&sm->Bl[cur][kr][nn]));
            }
            #pragma unroll
            for (int mt = 0; mt < 2; ++mt)
                #pragma unroll
                for (int nc = 0; nc < 4; ++nc)
                    #pragma unroll
                    for (int hf = 0; hf < 2; ++hf) {
                        float* cc = c[mt][nc*2 + hf];
                        uint32_t b0h = bh[nc][hf*2], b1h = bh[nc][hf*2+1];
                        uint32_t b0l = bl[nc][hf*2], b1l = bl[nc][hf*2+1];
                        mma16816(cc, ah[mt], b0h, b1h);
                        mma16816(cc, ah[mt], b0l, b1l);
                        mma16816(cc, al[mt], b0h, b1h);
                    }
        }
        __syncthreads();
    }

    #pragma unroll
    for (int mt = 0; mt < 2; ++mt)
        #pragma unroll
        for (int nt = 0; nt < 8; ++nt) {
            int r   = bm + m_base + mt*16 + (lane >> 2);
            int col = bn + n_base + nt*8 + (lane & 3)*2;
            *(float2*)(C + (size_t)r*N + col)     = make_float2(c[mt][nt][0], c[mt][nt][1]);
            *(float2*)(C + (size_t)(r+8)*N + col) = make_float2(c[mt][nt][2], c[mt][nt][3]);
        }
}

__global__ void __launch_bounds__(256) qkv_gemm_bf16() {
    extern __shared__ char smraw[];
    SmemGemmP* sm = (SmemGemmP*)smraw;
    int bx = blockIdx.x, bm = blockIdx.y * 128;
    if (bx < 16)
        gemm_presplit(sm, g_xh, g_xl, g_wqh, g_wql, g_q, NH*DHEAD, D_MODEL, bm, bx*128);
    else if (bx < 20)
        gemm_presplit(sm, g_xh, g_xl, g_wkh, g_wkl, g_k, NG*DHEAD, D_MODEL, bm, (bx-16)*128);
    else
        gemm_presplit(sm, g_xh, g_xl, g_wvh, g_wvl, g_v, NG*DHEAD, D_MODEL, bm, (bx-20)*128);
}

__global__ void __launch_bounds__(256) out_gemm_bf16(float* __restrict__ C) {
    extern __shared__ char smraw[];
    SmemGemmP* sm = (SmemGemmP*)smraw;
    gemm_presplit(sm, g_ch, g_cl, g_woh, g_wol, C, D_MODEL, D_MODEL,
                  blockIdx.y*128, blockIdx.x*128);
}

/* ================= tensor-core flash attention (async K/V loads) ========= */
struct SmemFlash {
    bf16 Qh[64][136], Ql[64][136];
    bf16 Kh[64][136], Kl[64][136];
    bf16 Vh[64][136], Vl[64][136];
    float S[64][68];
    bf16 Ph[64][72], Pl[64][72];
    float M[64], L[64], A[64];
};

__global__ void __launch_bounds__(256) flash2_kernel() {
    extern __shared__ char smraw[];
    SmemFlash* sm = (SmemFlash*)smraw;

    int qt = blockIdx.x, h = blockIdx.y, b = blockIdx.z;
    int g  = h >> 2;
    int q0 = qt * 64;
    int tid = threadIdx.x, warp = tid >> 5, lane = tid & 31;
    int m_base = (warp >> 1) * 16;

    size_t qoff = ((size_t)(b*S_LEN + q0))*(NH*DHEAD) + (size_t)h*DHEAD;
    #pragma unroll
    for (int i = 0; i < 4; ++i) {
        int fid = tid + i*256;
        int row = fid >> 4, c8 = (fid & 15) * 8;
        size_t go = qoff + (size_t)row*(NH*DHEAD) + c8;
        *(uint4*)&sm->Qh[row][c8] = *(const uint4*)(g_qh + go);
        *(uint4*)&sm->Ql[row][c8] = *(const uint4*)(g_ql + go);
    }
    if (tid < 64) { sm->M[tid] = -1e30f; sm->L[tid] = 0.f; }

    float co[8][4];
    #pragma unroll
    for (int nt = 0; nt < 8; ++nt)
        #pragma unroll
        for (int r = 0; r < 4; ++r) co[nt][r] = 0.f;

    size_t kvoff = (size_t)(b*S_LEN)*(NG*DHEAD) + (size_t)g*DHEAD;
    const float scale = 0.08838834764831845f;

    for (int kt = 0; kt <= qt; ++kt) {
        int k0t = kt * 64;
        __syncthreads();   /* prior iteration done reading K/V */
        /* async: K group, then V group */
        #pragma unroll
        for (int i = 0; i < 4; ++i) {
            int fid = tid + i*256;
            int row = fid >> 4, c8 = (fid & 15) * 8;
            size_t go = kvoff + (size_t)(k0t + row)*(NG*DHEAD) + c8;
            cp_async16(&sm->Kh[row][c8], g_kh + go);
            cp_async16(&sm->Kl[row][c8], g_kl + go);
        }
        cp_commit();
        #pragma unroll
        for (int i = 0; i < 4; ++i) {
            int fid = tid + i*256;
            int row = fid >> 4, c8 = (fid & 15) * 8;
            size_t go = kvoff + (size_t)(k0t + row)*(NG*DHEAD) + c8;
            cp_async16(&sm->Vh[row][c8], g_vh + go);
            cp_async16(&sm->Vl[row][c8], g_vl + go);
        }
        cp_commit();
        asm volatile("cp.async.wait_group 1;" ::: "memory");   /* K ready */
        __syncthreads();

        /* S = Q @ K^T : warp tile 16x32 */
        int n_s = (warp & 1) * 32;
        float cs[4][4];
        #pragma unroll
        for (int nt = 0; nt < 4; ++nt)
            #pragma unroll
            for (int r = 0; r < 4; ++r) cs[nt][r] = 0.f;

        #pragma unroll
        for (int ks = 0; ks < 8; ++ks) {
            int kk = ks * 16;
            uint32_t ah[4], al[4];
            int ar = m_base + (lane & 15);
            int ac = kk + (lane >> 4) * 8;
            ldsm_x4(ah, smem_u32(&sm->Qh[ar][ac]));
            ldsm_x4(al, smem_u32(&sm->Ql[ar][ac]));
            uint32_t kh[2][4], kl[2][4];
            #pragma unroll
            for (int gp = 0; gp < 2; ++gp) {
                int br = n_s + gp*16 + (lane & 7) + (lane >> 4) * 8;
                int bc = kk + ((lane >> 3) & 1) * 8;
                ldsm_x4(kh[gp], smem_u32(&sm->Kh[br][bc]));
                ldsm_x4(kl[gp], smem_u32(&sm->Kl[br][bc]));
            }
            #pragma unroll
            for (int nt = 0; nt < 4; ++nt) {
                int gp = nt >> 1, j = nt & 1;
                uint32_t b0h = kh[gp][j*2], b1h = kh[gp][j*2+1];
                uint32_t b0l = kl[gp][j*2], b1l = kl[gp][j*2+1];
                mma16816(cs[nt], ah, b0h, b1h);
                mma16816(cs[nt], ah, b0l, b1l);
                mma16816(cs[nt], al, b0h, b1h);
            }
        }

        #pragma unroll
        for (int nt = 0; nt < 4; ++nt)
            #pragma unroll
            for (int r2 = 0; r2 < 2; ++r2) {
                int row = m_base + (lane >> 2) + r2*8;
                int col = n_s + nt*8 + (lane & 3)*2;
                float v0 = cs[nt][r2*2]   * scale;
                float v1 = cs[nt][r2*2+1] * scale;
                if (k0t + col     > q0 + row) v0 = -1e30f;
                if (k0t + col + 1 > q0 + row) v1 = -1e30f;
                sm->S[row][col]   = v0;
                sm->S[row][col+1] = v1;
            }
        __syncthreads();

        /* online softmax; P emitted split */
        {
            int r = tid >> 2, q4 = tid & 3;
            float mx = -1e30f;
            #pragma unroll
            for (int c = 0; c < 16; ++c) mx = fmaxf(mx, sm->S[r][q4*16 + c]);
            mx = fmaxf(mx, __shfl_xor_sync(0xffffffffu, mx, 1));
            mx = fmaxf(mx, __shfl_xor_sync(0xffffffffu, mx, 2));
            float m_old = sm->M[r];
            float m_new = fmaxf(m_old, mx);
            float lsum = 0.f;
            #pragma unroll
            for (int c = 0; c < 16; c += 2) {
                float p0 = __expf(sm->S[r][q4*16 + c]     - m_new);
                float p1 = __expf(sm->S[r][q4*16 + c + 1] - m_new);
                lsum += p0 + p1;
                bf162 hi, lo;
                split_pair(p0, p1, &hi, &lo);
                *(bf162*)&sm->Ph[r][q4*16 + c] = hi;
                *(bf162*)&sm->Pl[r][q4*16 + c] = lo;
            }
            lsum += __shfl_xor_sync(0xffffffffu, lsum, 1);
            lsum += __shfl_xor_sync(0xffffffffu, lsum, 2);
            if (q4 == 0) {
                sm->A[r] = __expf(m_old - m_new);
                sm->M[r] = m_new;
                sm->L[r] = sm->L[r]*sm->A[r] + lsum;
            }
        }
        asm volatile("cp.async.wait_group 0;" ::: "memory");   /* V ready */
        __syncthreads();

        /* O = O*alpha + P @ V : warp tile 16x64 */
        int n_o = (warp & 1) * 64;
        float a0 = sm->A[m_base + (lane >> 2)];
        float a1 = sm->A[m_base + (lane >> 2) + 8];
        #pragma unroll
        for (int nt = 0; nt < 8; ++nt) {
            co[nt][0] *= a0; co[nt][1] *= a0;
            co[nt][2] *= a1; co[nt][3] *= a1;
        }
        #pragma unroll
        for (int ks = 0; ks < 4; ++ks) {
            int kk = ks * 16;
            uint32_t ph[4], pl[4];
            int ar = m_base + (lane & 15);
            int ac = kk + (lane >> 4) * 8;
            ldsm_x4(ph, smem_u32(&sm->Ph[ar][ac]));
            ldsm_x4(pl, smem_u32(&sm->Pl[ar][ac]));
            uint32_t vh[4][4], vl[4][4];
            #pragma unroll
            for (int gp = 0; gp < 4; ++gp) {
                int kr = kk + (lane & 7) + ((lane >> 3) & 1) * 8;
                int nn = n_o + gp*16 + (lane >> 4) * 8;
                ldsm_x4_t(vh[gp], smem_u32(&sm->Vh[kr][nn]));
                ldsm_x4_t(vl[gp], smem_u32(&sm->Vl[kr][nn]));
            }
            #pragma unroll
            for (int nt = 0; nt < 8; ++nt) {
                int gp = nt >> 1, j = nt & 1;
                uint32_t b0h = vh[gp][j*2], b1h = vh[gp][j*2+1];
                uint32_t b0l = vl[gp][j*2], b1l = vl[gp][j*2+1];
                mma16816(co[nt], ph, b0h, b1h);
                mma16816(co[nt], ph, b0l, b1l);
                mma16816(co[nt], pl, b0h, b1h);
            }
        }
    }

    __syncthreads();
    {
        int n_o = (warp & 1) * 64;
        int r0 = m_base + (lane >> 2);
        float il0 = 1.0f / sm->L[r0];
        float il1 = 1.0f / sm->L[r0 + 8];
        #pragma unroll
        for (int nt = 0; nt < 8; ++nt) {
            int col = n_o + nt*8 + (lane & 3)*2;
            size_t off0 = ((size_t)(b*S_LEN + q0 + r0))*(NH*DHEAD) + (size_t)h*DHEAD + col;
            size_t off1 = ((size_t)(b*S_LEN + q0 + r0 + 8))*(NH*DHEAD) + (size_t)h*DHEAD + col;
            bf162 hi, lo;
            split_pair(co[nt][0]*il0, co[nt][1]*il0, &hi, &lo);
            *(bf162*)(g_ch + off0) = hi;
            *(bf162*)(g_cl + off0) = lo;
            split_pair(co[nt][2]*il1, co[nt][3]*il1, &hi, &lo);
            *(bf162*)(g_ch + off1) = hi;
            *(bf162*)(g_cl + off1) = lo;
        }
    }
}

extern "C" void kernel_launch(void* const* d_in, const int* in_sizes, int n_in,
                              void* d_out, int out_size) {
    int idx_x = -1, sm_[2], nsm = 0, bg[3], nbg = 0;
    for (int i = 0; i < n_in; ++i) {
        if (in_sizes[i] == 8388608 && idx_x < 0) idx_x = i;
        else if (in_sizes[i] == 1048576 && nsm < 2) sm_[nsm++] = i;
        else if (in_sizes[i] == 4194304 && nbg < 3) bg[nbg++] = i;
    }
    const float *x, *Wk, *Wv;
    const unsigned char *c0, *c1, *c2;
    if (idx_x >= 0 && nsm == 2 && nbg == 3) {
        x  = (const float*)d_in[idx_x];
        Wk = (const float*)d_in[sm_[0]];
        Wv = (const float*)d_in[sm_[1]];
        c0 = (const unsigned char*)d_in[bg[0]];
        c1 = (const unsigned char*)d_in[bg[1]];
        c2 = (const unsigned char*)d_in[bg[2]];
    } else {
        x  = (const float*)d_in[0];
        Wk = (const float*)d_in[2];
        Wv = (const float*)d_in[3];
        c0 = (const unsigned char*)d_in[1];
        c1 = (const unsigned char*)d_in[4];
        c2 = (const unsigned char*)d_in[5];
    }
    float* out = (float*)d_out;

    bf16 *xh, *xl, *wqh, *wql, *wkh, *wkl, *wvh, *wvl, *woh, *wol, *vh, *vl;
    float *vp;
    cudaGetSymbolAddress((void**)&xh,  g_xh);  cudaGetSymbolAddress((void**)&xl,  g_xl);
    cudaGetSymbolAddress((void**)&wqh, g_wqh); cudaGetSymbolAddress((void**)&wql, g_wql);
    cudaGetSymbolAddress((void**)&wkh, g_wkh); cudaGetSymbolAddress((void**)&wkl, g_wkl);
    cudaGetSymbolAddress((void**)&wvh, g_wvh); cudaGetSymbolAddress((void**)&wvl, g_wvl);
    cudaGetSymbolAddress((void**)&woh, g_woh); cudaGetSymbolAddress((void**)&wol, g_wol);
    cudaGetSymbolAddress((void**)&vh,  g_vh);  cudaGetSymbolAddress((void**)&vl,  g_vl);
    cudaGetSymbolAddress((void**)&vp,  g_v);

    probe_kernel<<<1, 32>>>(c0, c1, c2);
    build_rope_kernel<<<S_LEN, 64>>>();

    split_kernel<<<(MROWS*D_MODEL/2 + 255)/256, 256>>>(x, xh, xl, MROWS*D_MODEL/2, 0);
    split_kernel<<<(D_MODEL*NH*DHEAD/2 + 255)/256, 256>>>(0, wqh, wql, D_MODEL*NH*DHEAD/2, 1);
    split_kernel<<<(D_MODEL*NG*DHEAD/2 + 255)/256, 256>>>(Wk, wkh, wkl, D_MODEL*NG*DHEAD/2, 0);
    split_kernel<<<(D_MODEL*NG*DHEAD/2 + 255)/256, 256>>>(Wv, wvh, wvl, D_MODEL*NG*DHEAD/2, 0);
    split_kernel<<<(D_MODEL*D_MODEL/2 + 255)/256, 256>>>(0, woh, wol, D_MODEL*D_MODEL/2, 2);

    int gemm_smem = (int)sizeof(SmemGemmP);
    cudaFuncSetAttribute(qkv_gemm_bf16, cudaFuncAttributeMaxDynamicSharedMemorySize, gemm_smem);
    cudaFuncSetAttribute(out_gemm_bf16, cudaFuncAttributeMaxDynamicSharedMemorySize, gemm_smem);

    qkv_gemm_bf16<<<dim3(24, MROWS/128), 256, gemm_smem>>>();

    rope_split_q<<<dim3(MROWS, NH), 64>>>();
    rope_split_k<<<dim3(MROWS, NG), 64>>>();
    split_kernel<<<(MROWS*NG*DHEAD/2 + 255)/256, 256>>>(vp, vh, vl, MROWS*NG*DHEAD/2, 0);

    const size_t OUT_MAIN = (size_t)NB * S_LEN * D_MODEL;
    const size_t CACHE    = (size_t)NB * NG * S_LEN * DHEAD;
    if ((size_t)out_size >= OUT_MAIN + 2*CACHE) {
        cache_kernel<<<(int)((CACHE + 255)/256), 256>>>(out + OUT_MAIN);
    }

    int fl2_smem = (int)sizeof(SmemFlash);
    cudaFuncSetAttribute(flash2_kernel, cudaFuncAttributeMaxDynamicSharedMemorySize, fl2_smem);
    flash2_kernel<<<dim3(S_LEN/64, NH, NB), 256, fl2_smem>>>();

    out_gemm_bf16<<<dim3(D_MODEL/128, MROWS/128), 256, gemm_smem>>>(out);
}

// round 11
// speedup vs baseline: 4.3158x; 1.0104x over previous
#include <cuda_runtime.h>
#include <cuda_bf16.h>
#include <math.h>
#include <stdint.h>

#define S_LEN   2048
#define D_MODEL 2048
#define NH      16
#define NG      4
#define DHEAD   128
#define NB      2
#define MROWS   (NB*S_LEN)
typedef __nv_bfloat16 bf16;
typedef __nv_bfloat162 bf162;

/* fp32 staging */
__device__ float g_q  [(size_t)MROWS * (NH*DHEAD)];
__device__ float g_k  [(size_t)MROWS * (NG*DHEAD)];
__device__ float g_v  [(size_t)MROWS * (NG*DHEAD)];
__device__ float g_rope[S_LEN * DHEAD];
__device__ const float* g_wq_slot;
__device__ const float* g_wo_slot;

/* persistent bf16 hi/lo splits */
__device__ bf16 g_xh [(size_t)MROWS * D_MODEL],      g_xl [(size_t)MROWS * D_MODEL];
__device__ bf16 g_wqh[(size_t)D_MODEL * NH*DHEAD],   g_wql[(size_t)D_MODEL * NH*DHEAD];
__device__ bf16 g_wkh[(size_t)D_MODEL * NG*DHEAD],   g_wkl[(size_t)D_MODEL * NG*DHEAD];
__device__ bf16 g_wvh[(size_t)D_MODEL * NG*DHEAD],   g_wvl[(size_t)D_MODEL * NG*DHEAD];
__device__ bf16 g_woh[(size_t)D_MODEL * D_MODEL],    g_wol[(size_t)D_MODEL * D_MODEL];
__device__ bf16 g_qh [(size_t)MROWS * NH*DHEAD],     g_ql [(size_t)MROWS * NH*DHEAD];
__device__ bf16 g_kh [(size_t)MROWS * NG*DHEAD],     g_kl [(size_t)MROWS * NG*DHEAD];
__device__ bf16 g_vh [(size_t)MROWS * NG*DHEAD],     g_vl [(size_t)MROWS * NG*DHEAD];
__device__ bf16 g_ch [(size_t)MROWS * NH*DHEAD],     g_cl [(size_t)MROWS * NH*DHEAD];

__global__ void probe_kernel(const unsigned char* c0, const unsigned char* c1,
                             const unsigned char* c2) {
    if (threadIdx.x != 0 || blockIdx.x != 0) return;
    const unsigned char* cs[3] = {c0, c1, c2};
    int nb[3];
    for (int i = 0; i < 3; ++i) {
        int boolish = 1;
        for (int k = 0; k < 64; ++k)
            if (cs[i][k * 97] > 1) { boolish = 0; break; }
        nb[i] = boolish;
    }
    int a = -1, b = -1;
    for (int i = 0; i < 3; ++i)
        if (!nb[i]) { if (a < 0) a = i; else if (b < 0) b = i; }
    if (a < 0 || b < 0) { a = 0; b = 1; }
    g_wq_slot = (const float*)cs[a];
    g_wo_slot = (const float*)cs[b];
}

__global__ void build_rope_kernel() {
    int s = blockIdx.x, d = threadIdx.x;
    float e    = (float)d / 64.0f;
    float invf = 1.0f / powf(10000.0f, e);
    float ang  = (float)s * invf;
    g_rope[s*DHEAD + d]      = (float)cos((double)ang);
    g_rope[s*DHEAD + 64 + d] = (float)sin((double)ang);
}

__device__ __forceinline__ void split_pair(float x, float y, bf162* hi, bf162* lo) {
    bf16 hx = __float2bfloat16_rn(x);
    bf16 hy = __float2bfloat16_rn(y);
    *hi = __halves2bfloat162(hx, hy);
    *lo = __halves2bfloat162(__float2bfloat16_rn(x - __bfloat162float(hx)),
                             __float2bfloat16_rn(y - __bfloat162float(hy)));
}

__global__ void split_kernel(const float* in, bf16* oh, bf16* ol, int n2, int which) {
    if (which == 1) in = g_wq_slot;
    else if (which == 2) in = g_wo_slot;
    int i = blockIdx.x * blockDim.x + threadIdx.x;
    if (i >= n2) return;
    float2 v = *(const float2*)(in + (size_t)i*2);
    bf162 hi, lo;
    split_pair(v.x, v.y, &hi, &lo);
    *(bf162*)(oh + (size_t)i*2) = hi;
    *(bf162*)(ol + (size_t)i*2) = lo;
}

__global__ void rope_split_q() {
    int bs = blockIdx.x, h = blockIdx.y, d = threadIdx.x;
    int s = bs & (S_LEN - 1);
    size_t base = (size_t)bs * NH * DHEAD + (size_t)h * DHEAD;
    float c  = g_rope[s*DHEAD + d];
    float sn = g_rope[s*DHEAD + 64 + d];
    float x1 = g_q[base + d], x2 = g_q[base + 64 + d];
    float r1 = x1*c - x2*sn, r2 = x2*c + x1*sn;
    bf16 h1 = __float2bfloat16_rn(r1), h2 = __float2bfloat16_rn(r2);
    g_qh[base + d]      = h1;
    g_qh[base + 64 + d] = h2;
    g_ql[base + d]      = __float2bfloat16_rn(r1 - __bfloat162float(h1));
    g_ql[base + 64 + d] = __float2bfloat16_rn(r2 - __bfloat162float(h2));
}

__global__ void rope_split_k() {
    int bs = blockIdx.x, h = blockIdx.y, d = threadIdx.x;
    int s = bs & (S_LEN - 1);
    size_t base = (size_t)bs * NG * DHEAD + (size_t)h * DHEAD;
    float c  = g_rope[s*DHEAD + d];
    float sn = g_rope[s*DHEAD + 64 + d];
    float x1 = g_k[base + d], x2 = g_k[base + 64 + d];
    float r1 = x1*c - x2*sn, r2 = x2*c + x1*sn;
    g_k[base + d]      = r1;
    g_k[base + 64 + d] = r2;
    bf16 h1 = __float2bfloat16_rn(r1), h2 = __float2bfloat16_rn(r2);
    g_kh[base + d]      = h1;
    g_kh[base + 64 + d] = h2;
    g_kl[base + d]      = __float2bfloat16_rn(r1 - __bfloat162float(h1));
    g_kl[base + 64 + d] = __float2bfloat16_rn(r2 - __bfloat162float(h2));
}

__global__ void cache_kernel(float* __restrict__ outc) {
    const size_t CACHE = (size_t)NB*NG*S_LEN*DHEAD;
    size_t idx = (size_t)blockIdx.x * blockDim.x + threadIdx.x;
    if (idx >= CACHE) return;
    int d = (int)(idx & 127);
    int s = (int)((idx >> 7) & (S_LEN-1));
    int g = (int)((idx >> 18) & (NG-1));
    int b = (int)(idx >> 20);
    size_t src = ((size_t)(b*S_LEN + s))*(NG*DHEAD) + (size_t)g*DHEAD + d;
    outc[idx]         = g_k[src];
    outc[CACHE + idx] = g_v[src];
}

/* ================= mma / async helpers ==================================== */
__device__ __forceinline__ uint32_t smem_u32(const void* p) {
    return (uint32_t)__cvta_generic_to_shared(p);
}
__device__ __forceinline__ void cp_async16(void* smem, const void* gmem) {
    asm volatile("cp.async.cg.shared.global [%0], [%1], 16;"
        :: "r"(smem_u32(smem)), "l"(gmem));
}
__device__ __forceinline__ void cp_commit() {
    asm volatile("cp.async.commit_group;");
}
__device__ __forceinline__ void ldsm_x4(uint32_t* r, uint32_t addr) {
    asm volatile("ldmatrix.sync.aligned.m8n8.x4.shared.b16 {%0,%1,%2,%3}, [%4];"
        : "=r"(r[0]), "=r"(r[1]), "=r"(r[2]), "=r"(r[3]) : "r"(addr));
}
__device__ __forceinline__ void ldsm_x4_t(uint32_t* r, uint32_t addr) {
    asm volatile("ldmatrix.sync.aligned.m8n8.x4.trans.shared.b16 {%0,%1,%2,%3}, [%4];"
        : "=r"(r[0]), "=r"(r[1]), "=r"(r[2]), "=r"(r[3]) : "r"(addr));
}
__device__ __forceinline__ void mma16816(float* c, const uint32_t* a,
                                         uint32_t b0, uint32_t b1) {
    asm volatile("mma.sync.aligned.m16n8k16.row.col.f32.bf16.bf16.f32 "
        "{%0,%1,%2,%3}, {%4,%5,%6,%7}, {%8,%9}, {%0,%1,%2,%3};"
        : "+f"(c[0]), "+f"(c[1]), "+f"(c[2]), "+f"(c[3])
        : "r"(a[0]), "r"(a[1]), "r"(a[2]), "r"(a[3]), "r"(b0), "r"(b1));
}

/* ================= pipelined pre-split bf16 GEMM (R9, validated) ========== */
struct SmemGemmP {
    bf16 Ah[2][128][40], Al[2][128][40];
    bf16 Bh[2][32][136], Bl[2][32][136];
};

__device__ __forceinline__ void gemm_load_stage(SmemGemmP* sm, int st,
                                                const bf16* Ah, const bf16* Al,
                                                const bf16* Bh, const bf16* Bl,
                                                int N, int K, int bm, int bn, int k0) {
    int tid = threadIdx.x;
    #pragma unroll
    for (int i = 0; i < 2; ++i) {
        int fid = tid + i*256;
        int row = fid >> 2, c8 = (fid & 3) * 8;
        size_t go = (size_t)(bm + row)*K + k0 + c8;
        cp_async16(&sm->Ah[st][row][c8], Ah + go);
        cp_async16(&sm->Al[st][row][c8], Al + go);
    }
    #pragma unroll
    for (int i = 0; i < 2; ++i) {
        int fid = tid + i*256;
        int row = fid >> 4, c8 = (fid & 15) * 8;
        size_t go = (size_t)(k0 + row)*N + bn + c8;
        cp_async16(&sm->Bh[st][row][c8], Bh + go);
        cp_async16(&sm->Bl[st][row][c8], Bl + go);
    }
}

__device__ __forceinline__ void gemm_presplit(SmemGemmP* sm,
                                              const bf16* __restrict__ Ah,
                                              const bf16* __restrict__ Al,
                                              const bf16* __restrict__ Bh,
                                              const bf16* __restrict__ Bl,
                                              float* __restrict__ C,
                                              int N, int K, int bm, int bn) {
    int tid = threadIdx.x;
    int warp = tid >> 5, lane = tid & 31;
    int m_base = (warp >> 1) * 32;
    int n_base = (warp & 1) * 64;

    float c[2][8][4];
    #pragma unroll
    for (int mt = 0; mt < 2; ++mt)
        #pragma unroll
        for (int nt = 0; nt < 8; ++nt)
            #pragma unroll
            for (int r = 0; r < 4; ++r) c[mt][nt][r] = 0.f;

    const int NIT = K / 32;
    gemm_load_stage(sm, 0, Ah, Al, Bh, Bl, N, K, bm, bn, 0);
    cp_commit();

    for (int it = 0; it < NIT; ++it) {
        int cur = it & 1;
        if (it + 1 < NIT) {
            gemm_load_stage(sm, cur ^ 1, Ah, Al, Bh, Bl, N, K, bm, bn, (it+1)*32);
            cp_commit();
            asm volatile("cp.async.wait_group 1;" ::: "memory");
        } else {
            asm volatile("cp.async.wait_group 0;" ::: "memory");
        }
        __syncthreads();

        #pragma unroll
        for (int ks = 0; ks < 32; ks += 16) {
            uint32_t ah[2][4], al[2][4];
            #pragma unroll
            for (int mt = 0; mt < 2; ++mt) {
                int rr = m_base + mt*16 + (lane & 15);
                int kk = ks + (lane >> 4) * 8;
                ldsm_x4(ah[mt], smem_u32(&sm->Ah[cur][rr][kk]));
                ldsm_x4(al[mt], smem_u32(&sm->Al[cur][rr][kk]));
            }
            uint32_t bh[4][4], bl[4][4];
            #pragma unroll
            for (int nc = 0; nc < 4; ++nc) {
                int kr = ks + (lane & 7) + ((lane >> 3) & 1) * 8;
                int nn = n_base + nc*16 + (lane >> 4) * 8;
                ldsm_x4_t(bh[nc], smem_u32(&sm->Bh[cur][kr][nn]));
                ldsm_x4_t(bl[nc], smem_u32(&sm->Bl[cur][kr][nn]));
            }
            #pragma unroll
            for (int mt = 0; mt < 2; ++mt)
                #pragma unroll
                for (int nc = 0; nc < 4; ++nc)
                    #pragma unroll
                    for (int hf = 0; hf < 2; ++hf) {
                        float* cc = c[mt][nc*2 + hf];
                        uint32_t b0h = bh[nc][hf*2], b1h = bh[nc][hf*2+1];
                        uint32_t b0l = bl[nc][hf*2], b1l = bl[nc][hf*2+1];
                        mma16816(cc, ah[mt], b0h, b1h);
                        mma16816(cc, ah[mt], b0l, b1l);
                        mma16816(cc, al[mt], b0h, b1h);
                    }
        }
        __syncthreads();
    }

    #pragma unroll
    for (int mt = 0; mt < 2; ++mt)
        #pragma unroll
        for (int nt = 0; nt < 8; ++nt) {
            int r   = bm + m_base + mt*16 + (lane >> 2);
            int col = bn + n_base + nt*8 + (lane & 3)*2;
            *(float2*)(C + (size_t)r*N + col)     = make_float2(c[mt][nt][0], c[mt][nt][1]);
            *(float2*)(C + (size_t)(r+8)*N + col) = make_float2(c[mt][nt][2], c[mt][nt][3]);
        }
}

__global__ void __launch_bounds__(256) qkv_gemm_bf16() {
    extern __shared__ char smraw[];
    SmemGemmP* sm = (SmemGemmP*)smraw;
    int bx = blockIdx.x, bm = blockIdx.y * 128;
    if (bx < 16)
        gemm_presplit(sm, g_xh, g_xl, g_wqh, g_wql, g_q, NH*DHEAD, D_MODEL, bm, bx*128);
    else if (bx < 20)
        gemm_presplit(sm, g_xh, g_xl, g_wkh, g_wkl, g_k, NG*DHEAD, D_MODEL, bm, (bx-16)*128);
    else
        gemm_presplit(sm, g_xh, g_xl, g_wvh, g_wvl, g_v, NG*DHEAD, D_MODEL, bm, (bx-20)*128);
}

__global__ void __launch_bounds__(256) out_gemm_bf16(float* __restrict__ C) {
    extern __shared__ char smraw[];
    SmemGemmP* sm = (SmemGemmP*)smraw;
    gemm_presplit(sm, g_ch, g_cl, g_woh, g_wol, C, D_MODEL, D_MODEL,
                  blockIdx.y*128, blockIdx.x*128);
}

/* ================= flash attention, BQ=128, mma.sync ====================== */
struct SmemFlash {
    bf16 Qh[128][136], Ql[128][136];
    bf16 Kh[64][136], Kl[64][136];
    bf16 Vh[64][136], Vl[64][136];
    float S[128][68];
    bf16 Ph[128][72], Pl[128][72];
    float M[128], L[128], A[128];
};

__global__ void __launch_bounds__(256) flash2_kernel() {
    extern __shared__ char smraw[];
    SmemFlash* sm = (SmemFlash*)smraw;

    int qt = (int)(gridDim.x - 1 - blockIdx.x);   /* longest tiles first */
    int h = blockIdx.y, b = blockIdx.z;
    int g  = h >> 2;
    int q0 = qt * 128;
    int tid = threadIdx.x, warp = tid >> 5, lane = tid & 31;
    int m_base = warp * 16;

    /* load pre-split Q (128 x 128) */
    size_t qoff = ((size_t)(b*S_LEN + q0))*(NH*DHEAD) + (size_t)h*DHEAD;
    #pragma unroll
    for (int i = 0; i < 8; ++i) {
        int fid = tid + i*256;
        int row = fid >> 4, c8 = (fid & 15) * 8;
        size_t go = qoff + (size_t)row*(NH*DHEAD) + c8;
        *(uint4*)&sm->Qh[row][c8] = *(const uint4*)(g_qh + go);
        *(uint4*)&sm->Ql[row][c8] = *(const uint4*)(g_ql + go);
    }
    if (tid < 128) { sm->M[tid] = -1e30f; sm->L[tid] = 0.f; }

    float co[16][4];
    #pragma unroll
    for (int nt = 0; nt < 16; ++nt)
        #pragma unroll
        for (int r = 0; r < 4; ++r) co[nt][r] = 0.f;

    size_t kvoff = (size_t)(b*S_LEN)*(NG*DHEAD) + (size_t)g*DHEAD;
    const float scale = 0.08838834764831845f;
    const int nkt = 2*qt + 2;

    for (int kt = 0; kt < nkt; ++kt) {
        int k0t = kt * 64;
        __syncthreads();
        #pragma unroll
        for (int i = 0; i < 4; ++i) {
            int fid = tid + i*256;
            int row = fid >> 4, c8 = (fid & 15) * 8;
            size_t go = kvoff + (size_t)(k0t + row)*(NG*DHEAD) + c8;
            cp_async16(&sm->Kh[row][c8], g_kh + go);
            cp_async16(&sm->Kl[row][c8], g_kl + go);
        }
        cp_commit();
        #pragma unroll
        for (int i = 0; i < 4; ++i) {
            int fid = tid + i*256;
            int row = fid >> 4, c8 = (fid & 15) * 8;
            size_t go = kvoff + (size_t)(k0t + row)*(NG*DHEAD) + c8;
            cp_async16(&sm->Vh[row][c8], g_vh + go);
            cp_async16(&sm->Vl[row][c8], g_vl + go);
        }
        cp_commit();
        asm volatile("cp.async.wait_group 1;" ::: "memory");   /* K ready */
        __syncthreads();

        /* S = Q @ K^T : warp tile 16x64 */
        float cs[8][4];
        #pragma unroll
        for (int nt = 0; nt < 8; ++nt)
            #pragma unroll
            for (int r = 0; r < 4; ++r) cs[nt][r] = 0.f;

        #pragma unroll
        for (int ks = 0; ks < 8; ++ks) {
            int kk = ks * 16;
            uint32_t ah[4], al[4];
            int ar = m_base + (lane & 15);
            int ac = kk + (lane >> 4) * 8;
            ldsm_x4(ah, smem_u32(&sm->Qh[ar][ac]));
            ldsm_x4(al, smem_u32(&sm->Ql[ar][ac]));
            uint32_t kh[4][4], kl[4][4];
            #pragma unroll
            for (int gp = 0; gp < 4; ++gp) {
                int br = gp*16 + (lane & 7) + (lane >> 4) * 8;
                int bc = kk + ((lane >> 3) & 1) * 8;
                ldsm_x4(kh[gp], smem_u32(&sm->Kh[br][bc]));
                ldsm_x4(kl[gp], smem_u32(&sm->Kl[br][bc]));
            }
            #pragma unroll
            for (int nt = 0; nt < 8; ++nt) {
                int gp = nt >> 1, j = nt & 1;
                uint32_t b0h = kh[gp][j*2], b1h = kh[gp][j*2+1];
                uint32_t b0l = kl[gp][j*2], b1l = kl[gp][j*2+1];
                mma16816(cs[nt], ah, b0h, b1h);
                mma16816(cs[nt], ah, b0l, b1l);
                mma16816(cs[nt], al, b0h, b1h);
            }
        }

        #pragma unroll
        for (int nt = 0; nt < 8; ++nt)
            #pragma unroll
            for (int r2 = 0; r2 < 2; ++r2) {
                int row = m_base + (lane >> 2) + r2*8;
                int col = nt*8 + (lane & 3)*2;
                float v0 = cs[nt][r2*2]   * scale;
                float v1 = cs[nt][r2*2+1] * scale;
                if (k0t + col     > q0 + row) v0 = -1e30f;
                if (k0t + col + 1 > q0 + row) v1 = -1e30f;
                sm->S[row][col]   = v0;
                sm->S[row][col+1] = v1;
            }
        __syncthreads();

        /* online softmax: 2 threads per row; P emitted split */
        {
            int r = tid >> 1, q2 = tid & 1;
            float mx = -1e30f;
            #pragma unroll
            for (int c = 0; c < 32; ++c) mx = fmaxf(mx, sm->S[r][q2*32 + c]);
            mx = fmaxf(mx, __shfl_xor_sync(0xffffffffu, mx, 1));
            float m_old = sm->M[r];
            float m_new = fmaxf(m_old, mx);
            float lsum = 0.f;
            #pragma unroll
            for (int c = 0; c < 32; c += 2) {
                float p0 = __expf(sm->S[r][q2*32 + c]     - m_new);
                float p1 = __expf(sm->S[r][q2*32 + c + 1] - m_new);
                lsum += p0 + p1;
                bf162 hi, lo;
                split_pair(p0, p1, &hi, &lo);
                *(bf162*)&sm->Ph[r][q2*32 + c] = hi;
                *(bf162*)&sm->Pl[r][q2*32 + c] = lo;
            }
            lsum += __shfl_xor_sync(0xffffffffu, lsum, 1);
            if (q2 == 0) {
                sm->A[r] = __expf(m_old - m_new);
                sm->M[r] = m_new;
                sm->L[r] = sm->L[r]*sm->A[r] + lsum;
            }
        }
        asm volatile("cp.async.wait_group 0;" ::: "memory");   /* V ready */
        __syncthreads();

        /* O = O*alpha + P @ V : warp tile 16x128 */
        float a0 = sm->A[m_base + (lane >> 2)];
        float a1 = sm->A[m_base + (lane >> 2) + 8];
        #pragma unroll
        for (int nt = 0; nt < 16; ++nt) {
            co[nt][0] *= a0; co[nt][1] *= a0;
            co[nt][2] *= a1; co[nt][3] *= a1;
        }
        #pragma unroll
        for (int ks = 0; ks < 4; ++ks) {
            int kk = ks * 16;
            uint32_t ph[4], pl[4];
            int ar = m_base + (lane & 15);
            int ac = kk + (lane >> 4) * 8;
            ldsm_x4(ph, smem_u32(&sm->Ph[ar][ac]));
            ldsm_x4(pl, smem_u32(&sm->Pl[ar][ac]));
            uint32_t vh[8][4], vl[8][4];
            #pragma unroll
            for (int gp = 0; gp < 8; ++gp) {
                int kr = kk + (lane & 7) + ((lane >> 3) & 1) * 8;
                int nn = gp*16 + (lane >> 4) * 8;
                ldsm_x4_t(vh[gp], smem_u32(&sm->Vh[kr][nn]));
                ldsm_x4_t(vl[gp], smem_u32(&sm->Vl[kr][nn]));
            }
            #pragma unroll
            for (int nt = 0; nt < 16; ++nt) {
                int gp = nt >> 1, j = nt & 1;
                uint32_t b0h = vh[gp][j*2], b1h = vh[gp][j*2+1];
                uint32_t b0l = vl[gp][j*2], b1l = vl[gp][j*2+1];
                mma16816(co[nt], ph, b0h, b1h);
                mma16816(co[nt], ph, b0l, b1l);
                mma16816(co[nt], pl, b0h, b1h);
            }
        }
    }

    __syncthreads();
    {
        int r0 = m_base + (lane >> 2);
        float il0 = 1.0f / sm->L[r0];
        float il1 = 1.0f / sm->L[r0 + 8];
        #pragma unroll
        for (int nt = 0; nt < 16; ++nt) {
            int col = nt*8 + (lane & 3)*2;
            size_t off0 = ((size_t)(b*S_LEN + q0 + r0))*(NH*DHEAD) + (size_t)h*DHEAD + col;
            size_t off1 = ((size_t)(b*S_LEN + q0 + r0 + 8))*(NH*DHEAD) + (size_t)h*DHEAD + col;
            bf162 hi, lo;
            split_pair(co[nt][0]*il0, co[nt][1]*il0, &hi, &lo);
            *(bf162*)(g_ch + off0) = hi;
            *(bf162*)(g_cl + off0) = lo;
            split_pair(co[nt][2]*il1, co[nt][3]*il1, &hi, &lo);
            *(bf162*)(g_ch + off1) = hi;
            *(bf162*)(g_cl + off1) = lo;
        }
    }
}

extern "C" void kernel_launch(void* const* d_in, const int* in_sizes, int n_in,
                              void* d_out, int out_size) {
    int idx_x = -1, sm_[2], nsm = 0, bg[3], nbg = 0;
    for (int i = 0; i < n_in; ++i) {
        if (in_sizes[i] == 8388608 && idx_x < 0) idx_x = i;
        else if (in_sizes[i] == 1048576 && nsm < 2) sm_[nsm++] = i;
        else if (in_sizes[i] == 4194304 && nbg < 3) bg[nbg++] = i;
    }
    const float *x, *Wk, *Wv;
    const unsigned char *c0, *c1, *c2;
    if (idx_x >= 0 && nsm == 2 && nbg == 3) {
        x  = (const float*)d_in[idx_x];
        Wk = (const float*)d_in[sm_[0]];
        Wv = (const float*)d_in[sm_[1]];
        c0 = (const unsigned char*)d_in[bg[0]];
        c1 = (const unsigned char*)d_in[bg[1]];
        c2 = (const unsigned char*)d_in[bg[2]];
    } else {
        x  = (const float*)d_in[0];
        Wk = (const float*)d_in[2];
        Wv = (const float*)d_in[3];
        c0 = (const unsigned char*)d_in[1];
        c1 = (const unsigned char*)d_in[4];
        c2 = (const unsigned char*)d_in[5];
    }
    float* out = (float*)d_out;

    bf16 *xh, *xl, *wqh, *wql, *wkh, *wkl, *wvh, *wvl, *woh, *wol, *vh, *vl;
    float *vp;
    cudaGetSymbolAddress((void**)&xh,  g_xh);  cudaGetSymbolAddress((void**)&xl,  g_xl);
    cudaGetSymbolAddress((void**)&wqh, g_wqh); cudaGetSymbolAddress((void**)&wql, g_wql);
    cudaGetSymbolAddress((void**)&wkh, g_wkh); cudaGetSymbolAddress((void**)&wkl, g_wkl);
    cudaGetSymbolAddress((void**)&wvh, g_wvh); cudaGetSymbolAddress((void**)&wvl, g_wvl);
    cudaGetSymbolAddress((void**)&woh, g_woh); cudaGetSymbolAddress((void**)&wol, g_wol);
    cudaGetSymbolAddress((void**)&vh,  g_vh);  cudaGetSymbolAddress((void**)&vl,  g_vl);
    cudaGetSymbolAddress((void**)&vp,  g_v);

    probe_kernel<<<1, 32>>>(c0, c1, c2);
    build_rope_kernel<<<S_LEN, 64>>>();

    split_kernel<<<(MROWS*D_MODEL/2 + 255)/256, 256>>>(x, xh, xl, MROWS*D_MODEL/2, 0);
    split_kernel<<<(D_MODEL*NH*DHEAD/2 + 255)/256, 256>>>(0, wqh, wql, D_MODEL*NH*DHEAD/2, 1);
    split_kernel<<<(D_MODEL*NG*DHEAD/2 + 255)/256, 256>>>(Wk, wkh, wkl, D_MODEL*NG*DHEAD/2, 0);
    split_kernel<<<(D_MODEL*NG*DHEAD/2 + 255)/256, 256>>>(Wv, wvh, wvl, D_MODEL*NG*DHEAD/2, 0);
    split_kernel<<<(D_MODEL*D_MODEL/2 + 255)/256, 256>>>(0, woh, wol, D_MODEL*D_MODEL/2, 2);

    int gemm_smem = (int)sizeof(SmemGemmP);
    cudaFuncSetAttribute(qkv_gemm_bf16, cudaFuncAttributeMaxDynamicSharedMemorySize, gemm_smem);
    cudaFuncSetAttribute(out_gemm_bf16, cudaFuncAttributeMaxDynamicSharedMemorySize, gemm_smem);

    qkv_gemm_bf16<<<dim3(24, MROWS/128), 256, gemm_smem>>>();

    rope_split_q<<<dim3(MROWS, NH), 64>>>();
    rope_split_k<<<dim3(MROWS, NG), 64>>>();
    split_kernel<<<(MROWS*NG*DHEAD/2 + 255)/256, 256>>>(vp, vh, vl, MROWS*NG*DHEAD/2, 0);

    const size_t OUT_MAIN = (size_t)NB * S_LEN * D_MODEL;
    const size_t CACHE    = (size_t)NB * NG * S_LEN * DHEAD;
    if ((size_t)out_size >= OUT_MAIN + 2*CACHE) {
        cache_kernel<<<(int)((CACHE + 255)/256), 256>>>(out + OUT_MAIN);
    }

    int fl2_smem = (int)sizeof(SmemFlash);
    cudaFuncSetAttribute(flash2_kernel, cudaFuncAttributeMaxDynamicSharedMemorySize, fl2_smem);
    flash2_kernel<<<dim3(S_LEN/128, NH, NB), 256, fl2_smem>>>();

    out_gemm_bf16<<<dim3(D_MODEL/128, MROWS/128), 256, gemm_smem>>>(out);
}

// round 12
// speedup vs baseline: 4.5128x; 1.0456x over previous
#include <cuda_runtime.h>
#include <cuda_bf16.h>
#include <math.h>
#include <stdint.h>

#define S_LEN   2048
#define D_MODEL 2048
#define NH      16
#define NG      4
#define DHEAD   128
#define NB      2
#define MROWS   (NB*S_LEN)
typedef __nv_bfloat16 bf16;
typedef __nv_bfloat162 bf162;

/* fp32 staging */
__device__ float g_q  [(size_t)MROWS * (NH*DHEAD)];
__device__ float g_k  [(size_t)MROWS * (NG*DHEAD)];
__device__ float g_v  [(size_t)MROWS * (NG*DHEAD)];
__device__ float g_rope[S_LEN * DHEAD];
__device__ const float* g_wq_slot;
__device__ const float* g_wo_slot;

/* persistent bf16 hi/lo splits */
__device__ bf16 g_xh [(size_t)MROWS * D_MODEL],      g_xl [(size_t)MROWS * D_MODEL];
__device__ bf16 g_wqh[(size_t)D_MODEL * NH*DHEAD],   g_wql[(size_t)D_MODEL * NH*DHEAD];
__device__ bf16 g_wkh[(size_t)D_MODEL * NG*DHEAD],   g_wkl[(size_t)D_MODEL * NG*DHEAD];
__device__ bf16 g_wvh[(size_t)D_MODEL * NG*DHEAD],   g_wvl[(size_t)D_MODEL * NG*DHEAD];
__device__ bf16 g_woh[(size_t)D_MODEL * D_MODEL],    g_wol[(size_t)D_MODEL * D_MODEL];
__device__ bf16 g_qh [(size_t)MROWS * NH*DHEAD],     g_ql [(size_t)MROWS * NH*DHEAD];
__device__ bf16 g_kh [(size_t)MROWS * NG*DHEAD],     g_kl [(size_t)MROWS * NG*DHEAD];
__device__ bf16 g_vh [(size_t)MROWS * NG*DHEAD],     g_vl [(size_t)MROWS * NG*DHEAD];
__device__ bf16 g_ch [(size_t)MROWS * NH*DHEAD],     g_cl [(size_t)MROWS * NH*DHEAD];

__global__ void probe_kernel(const unsigned char* c0, const unsigned char* c1,
                             const unsigned char* c2) {
    if (threadIdx.x != 0 || blockIdx.x != 0) return;
    const unsigned char* cs[3] = {c0, c1, c2};
    int nb[3];
    for (int i = 0; i < 3; ++i) {
        int boolish = 1;
        for (int k = 0; k < 64; ++k)
            if (cs[i][k * 97] > 1) { boolish = 0; break; }
        nb[i] = boolish;
    }
    int a = -1, b = -1;
    for (int i = 0; i < 3; ++i)
        if (!nb[i]) { if (a < 0) a = i; else if (b < 0) b = i; }
    if (a < 0 || b < 0) { a = 0; b = 1; }
    g_wq_slot = (const float*)cs[a];
    g_wo_slot = (const float*)cs[b];
}

__global__ void build_rope_kernel() {
    int s = blockIdx.x, d = threadIdx.x;
    float e    = (float)d / 64.0f;
    float invf = 1.0f / powf(10000.0f, e);
    float ang  = (float)s * invf;
    g_rope[s*DHEAD + d]      = (float)cos((double)ang);
    g_rope[s*DHEAD + 64 + d] = (float)sin((double)ang);
}

__device__ __forceinline__ void split_pair(float x, float y, bf162* hi, bf162* lo) {
    bf16 hx = __float2bfloat16_rn(x);
    bf16 hy = __float2bfloat16_rn(y);
    *hi = __halves2bfloat162(hx, hy);
    *lo = __halves2bfloat162(__float2bfloat16_rn(x - __bfloat162float(hx)),
                             __float2bfloat16_rn(y - __bfloat162float(hy)));
}

__global__ void split_kernel(const float* in, bf16* oh, bf16* ol, int n2, int which) {
    if (which == 1) in = g_wq_slot;
    else if (which == 2) in = g_wo_slot;
    int i = blockIdx.x * blockDim.x + threadIdx.x;
    if (i >= n2) return;
    float2 v = *(const float2*)(in + (size_t)i*2);
    bf162 hi, lo;
    split_pair(v.x, v.y, &hi, &lo);
    *(bf162*)(oh + (size_t)i*2) = hi;
    *(bf162*)(ol + (size_t)i*2) = lo;
}

__global__ void rope_split_q() {
    int bs = blockIdx.x, h = blockIdx.y, d = threadIdx.x;
    int s = bs & (S_LEN - 1);
    size_t base = (size_t)bs * NH * DHEAD + (size_t)h * DHEAD;
    float c  = g_rope[s*DHEAD + d];
    float sn = g_rope[s*DHEAD + 64 + d];
    float x1 = g_q[base + d], x2 = g_q[base + 64 + d];
    float r1 = x1*c - x2*sn, r2 = x2*c + x1*sn;
    bf16 h1 = __float2bfloat16_rn(r1), h2 = __float2bfloat16_rn(r2);
    g_qh[base + d]      = h1;
    g_qh[base + 64 + d] = h2;
    g_ql[base + d]      = __float2bfloat16_rn(r1 - __bfloat162float(h1));
    g_ql[base + 64 + d] = __float2bfloat16_rn(r2 - __bfloat162float(h2));
}

__global__ void rope_split_k() {
    int bs = blockIdx.x, h = blockIdx.y, d = threadIdx.x;
    int s = bs & (S_LEN - 1);
    size_t base = (size_t)bs * NG * DHEAD + (size_t)h * DHEAD;
    float c  = g_rope[s*DHEAD + d];
    float sn = g_rope[s*DHEAD + 64 + d];
    float x1 = g_k[base + d], x2 = g_k[base + 64 + d];
    float r1 = x1*c - x2*sn, r2 = x2*c + x1*sn;
    g_k[base + d]      = r1;
    g_k[base + 64 + d] = r2;
    bf16 h1 = __float2bfloat16_rn(r1), h2 = __float2bfloat16_rn(r2);
    g_kh[base + d]      = h1;
    g_kh[base + 64 + d] = h2;
    g_kl[base + d]      = __float2bfloat16_rn(r1 - __bfloat162float(h1));
    g_kl[base + 64 + d] = __float2bfloat16_rn(r2 - __bfloat162float(h2));
}

__global__ void cache_kernel(float* __restrict__ outc) {
    const size_t CACHE = (size_t)NB*NG*S_LEN*DHEAD;
    size_t idx = (size_t)blockIdx.x * blockDim.x + threadIdx.x;
    if (idx >= CACHE) return;
    int d = (int)(idx & 127);
    int s = (int)((idx >> 7) & (S_LEN-1));
    int g = (int)((idx >> 18) & (NG-1));
    int b = (int)(idx >> 20);
    size_t src = ((size_t)(b*S_LEN + s))*(NG*DHEAD) + (size_t)g*DHEAD + d;
    outc[idx]         = g_k[src];
    outc[CACHE + idx] = g_v[src];
}

/* ================= mma / async helpers ==================================== */
__device__ __forceinline__ uint32_t smem_u32(const void* p) {
    return (uint32_t)__cvta_generic_to_shared(p);
}
__device__ __forceinline__ void cp_async16(void* smem, const void* gmem) {
    asm volatile("cp.async.cg.shared.global [%0], [%1], 16;"
        :: "r"(smem_u32(smem)), "l"(gmem));
}
__device__ __forceinline__ void cp_commit() {
    asm volatile("cp.async.commit_group;");
}
__device__ __forceinline__ void ldsm_x4(uint32_t* r, uint32_t addr) {
    asm volatile("ldmatrix.sync.aligned.m8n8.x4.shared.b16 {%0,%1,%2,%3}, [%4];"
        : "=r"(r[0]), "=r"(r[1]), "=r"(r[2]), "=r"(r[3]) : "r"(addr));
}
__device__ __forceinline__ void ldsm_x4_t(uint32_t* r, uint32_t addr) {
    asm volatile("ldmatrix.sync.aligned.m8n8.x4.trans.shared.b16 {%0,%1,%2,%3}, [%4];"
        : "=r"(r[0]), "=r"(r[1]), "=r"(r[2]), "=r"(r[3]) : "r"(addr));
}
__device__ __forceinline__ void mma16816(float* c, const uint32_t* a,
                                         uint32_t b0, uint32_t b1) {
    asm volatile("mma.sync.aligned.m16n8k16.row.col.f32.bf16.bf16.f32 "
        "{%0,%1,%2,%3}, {%4,%5,%6,%7}, {%8,%9}, {%0,%1,%2,%3};"
        : "+f"(c[0]), "+f"(c[1]), "+f"(c[2]), "+f"(c[3])
        : "r"(a[0]), "r"(a[1]), "r"(a[2]), "r"(a[3]), "r"(b0), "r"(b1));
}

/* ================= pipelined pre-split bf16 GEMM (R9, validated) ========== */
struct SmemGemmP {
    bf16 Ah[2][128][40], Al[2][128][40];
    bf16 Bh[2][32][136], Bl[2][32][136];
};

__device__ __forceinline__ void gemm_load_stage(SmemGemmP* sm, int st,
                                                const bf16* Ah, const bf16* Al,
                                                const bf16* Bh, const bf16* Bl,
                                                int N, int K, int bm, int bn, int k0) {
    int tid = threadIdx.x;
    #pragma unroll
    for (int i = 0; i < 2; ++i) {
        int fid = tid + i*256;
        int row = fid >> 2, c8 = (fid & 3) * 8;
        size_t go = (size_t)(bm + row)*K + k0 + c8;
        cp_async16(&sm->Ah[st][row][c8], Ah + go);
        cp_async16(&sm->Al[st][row][c8], Al + go);
    }
    #pragma unroll
    for (int i = 0; i < 2; ++i) {
        int fid = tid + i*256;
        int row = fid >> 4, c8 = (fid & 15) * 8;
        size_t go = (size_t)(k0 + row)*N + bn + c8;
        cp_async16(&sm->Bh[st][row][c8], Bh + go);
        cp_async16(&sm->Bl[st][row][c8], Bl + go);
    }
}

__device__ __forceinline__ void gemm_presplit(SmemGemmP* sm,
                                              const bf16* __restrict__ Ah,
                                              const bf16* __restrict__ Al,
                                              const bf16* __restrict__ Bh,
                                              const bf16* __restrict__ Bl,
                                              float* __restrict__ C,
                                              int N, int K, int bm, int bn) {
    int tid = threadIdx.x;
    int warp = tid >> 5, lane = tid & 31;
    int m_base = (warp >> 1) * 32;
    int n_base = (warp & 1) * 64;

    float c[2][8][4];
    #pragma unroll
    for (int mt = 0; mt < 2; ++mt)
        #pragma unroll
        for (int nt = 0; nt < 8; ++nt)
            #pragma unroll
            for (int r = 0; r < 4; ++r) c[mt][nt][r] = 0.f;

    const int NIT = K / 32;
    gemm_load_stage(sm, 0, Ah, Al, Bh, Bl, N, K, bm, bn, 0);
    cp_commit();

    for (int it = 0; it < NIT; ++it) {
        int cur = it & 1;
        if (it + 1 < NIT) {
            gemm_load_stage(sm, cur ^ 1, Ah, Al, Bh, Bl, N, K, bm, bn, (it+1)*32);
            cp_commit();
            asm volatile("cp.async.wait_group 1;" ::: "memory");
        } else {
            asm volatile("cp.async.wait_group 0;" ::: "memory");
        }
        __syncthreads();

        #pragma unroll
        for (int ks = 0; ks < 32; ks += 16) {
            uint32_t ah[2][4], al[2][4];
            #pragma unroll
            for (int mt = 0; mt < 2; ++mt) {
                int rr = m_base + mt*16 + (lane & 15);
                int kk = ks + (lane >> 4) * 8;
                ldsm_x4(ah[mt], smem_u32(&sm->Ah[cur][rr][kk]));
                ldsm_x4(al[mt], smem_u32(&sm->Al[cur][rr][kk]));
            }
            uint32_t bh[4][4], bl[4][4];
            #pragma unroll
            for (int nc = 0; nc < 4; ++nc) {
                int kr = ks + (lane & 7) + ((lane >> 3) & 1) * 8;
                int nn = n_base + nc*16 + (lane >> 4) * 8;
                ldsm_x4_t(bh[nc], smem_u32(&sm->Bh[cur][kr][nn]));
                ldsm_x4_t(bl[nc], smem_u32(&sm->Bl[cur][kr][nn]));
            }
            #pragma unroll
            for (int mt = 0; mt < 2; ++mt)
                #pragma unroll
                for (int nc = 0; nc < 4; ++nc)
                    #pragma unroll
                    for (int hf = 0; hf < 2; ++hf) {
                        float* cc = c[mt][nc*2 + hf];
                        uint32_t b0h = bh[nc][hf*2], b1h = bh[nc][hf*2+1];
                        uint32_t b0l = bl[nc][hf*2], b1l = bl[nc][hf*2+1];
                        mma16816(cc, ah[mt], b0h, b1h);
                        mma16816(cc, ah[mt], b0l, b1l);
                        mma16816(cc, al[mt], b0h, b1h);
                    }
        }
        __syncthreads();
    }

    #pragma unroll
    for (int mt = 0; mt < 2; ++mt)
        #pragma unroll
        for (int nt = 0; nt < 8; ++nt) {
            int r   = bm + m_base + mt*16 + (lane >> 2);
            int col = bn + n_base + nt*8 + (lane & 3)*2;
            *(float2*)(C + (size_t)r*N + col)     = make_float2(c[mt][nt][0], c[mt][nt][1]);
            *(float2*)(C + (size_t)(r+8)*N + col) = make_float2(c[mt][nt][2], c[mt][nt][3]);
        }
}

__global__ void __launch_bounds__(256) qkv_gemm_bf16() {
    extern __shared__ char smraw[];
    SmemGemmP* sm = (SmemGemmP*)smraw;
    int bx = blockIdx.x, bm = blockIdx.y * 128;
    if (bx < 16)
        gemm_presplit(sm, g_xh, g_xl, g_wqh, g_wql, g_q, NH*DHEAD, D_MODEL, bm, bx*128);
    else if (bx < 20)
        gemm_presplit(sm, g_xh, g_xl, g_wkh, g_wkl, g_k, NG*DHEAD, D_MODEL, bm, (bx-16)*128);
    else
        gemm_presplit(sm, g_xh, g_xl, g_wvh, g_wvl, g_v, NG*DHEAD, D_MODEL, bm, (bx-20)*128);
}

__global__ void __launch_bounds__(256) out_gemm_bf16(float* __restrict__ C) {
    extern __shared__ char smraw[];
    SmemGemmP* sm = (SmemGemmP*)smraw;
    gemm_presplit(sm, g_ch, g_cl, g_woh, g_wol, C, D_MODEL, D_MODEL,
                  blockIdx.y*128, blockIdx.x*128);
}

/* ================= flash attention, BQ=128, register softmax ============== */
struct SmemFlash {
    bf16 Qh[128][136], Ql[128][136];
    bf16 Kh[64][136], Kl[64][136];
    bf16 Vh[64][136], Vl[64][136];
};

__global__ void __launch_bounds__(256) flash2_kernel() {
    extern __shared__ char smraw[];
    SmemFlash* sm = (SmemFlash*)smraw;

    int qt = (int)(gridDim.x - 1 - blockIdx.x);   /* longest tiles first */
    int h = blockIdx.y, b = blockIdx.z;
    int g  = h >> 2;
    int q0 = qt * 128;
    int tid = threadIdx.x, warp = tid >> 5, lane = tid & 31;
    int m_base = warp * 16;
    int rq = lane >> 2;                 /* quad row: rows m_base+rq, +8 */

    /* load pre-split Q (128 x 128) */
    size_t qoff = ((size_t)(b*S_LEN + q0))*(NH*DHEAD) + (size_t)h*DHEAD;
    #pragma unroll
    for (int i = 0; i < 8; ++i) {
        int fid = tid + i*256;
        int row = fid >> 4, c8 = (fid & 15) * 8;
        size_t go = qoff + (size_t)row*(NH*DHEAD) + c8;
        *(uint4*)&sm->Qh[row][c8] = *(const uint4*)(g_qh + go);
        *(uint4*)&sm->Ql[row][c8] = *(const uint4*)(g_ql + go);
    }

    float co[16][4];
    #pragma unroll
    for (int nt = 0; nt < 16; ++nt)
        #pragma unroll
        for (int r = 0; r < 4; ++r) co[nt][r] = 0.f;
    float m0 = -1e30f, m1 = -1e30f, l0 = 0.f, l1 = 0.f;

    size_t kvoff = (size_t)(b*S_LEN)*(NG*DHEAD) + (size_t)g*DHEAD;
    const float scale = 0.08838834764831845f;
    const int nkt = 2*qt + 2;

    for (int kt = 0; kt < nkt; ++kt) {
        int k0t = kt * 64;
        __syncthreads();   /* prior iteration done reading K/V */
        #pragma unroll
        for (int i = 0; i < 4; ++i) {
            int fid = tid + i*256;
            int row = fid >> 4, c8 = (fid & 15) * 8;
            size_t go = kvoff + (size_t)(k0t + row)*(NG*DHEAD) + c8;
            cp_async16(&sm->Kh[row][c8], g_kh + go);
            cp_async16(&sm->Kl[row][c8], g_kl + go);
        }
        cp_commit();
        #pragma unroll
        for (int i = 0; i < 4; ++i) {
            int fid = tid + i*256;
            int row = fid >> 4, c8 = (fid & 15) * 8;
            size_t go = kvoff + (size_t)(k0t + row)*(NG*DHEAD) + c8;
            cp_async16(&sm->Vh[row][c8], g_vh + go);
            cp_async16(&sm->Vl[row][c8], g_vl + go);
        }
        cp_commit();
        asm volatile("cp.async.wait_group 1;" ::: "memory");   /* K ready */
        __syncthreads();

        /* S = Q @ K^T : warp tile 16x64, accum in registers */
        float cs[8][4];
        #pragma unroll
        for (int nt = 0; nt < 8; ++nt)
            #pragma unroll
            for (int r = 0; r < 4; ++r) cs[nt][r] = 0.f;

        #pragma unroll
        for (int ks = 0; ks < 8; ++ks) {
            int kk = ks * 16;
            uint32_t ah[4], al[4];
            int ar = m_base + (lane & 15);
            int ac = kk + (lane >> 4) * 8;
            ldsm_x4(ah, smem_u32(&sm->Qh[ar][ac]));
            ldsm_x4(al, smem_u32(&sm->Ql[ar][ac]));
            uint32_t kh[4][4], kl[4][4];
            #pragma unroll
            for (int gp = 0; gp < 4; ++gp) {
                int br = gp*16 + (lane & 7) + (lane >> 4) * 8;
                int bc = kk + ((lane >> 3) & 1) * 8;
                ldsm_x4(kh[gp], smem_u32(&sm->Kh[br][bc]));
                ldsm_x4(kl[gp], smem_u32(&sm->Kl[br][bc]));
            }
            #pragma unroll
            for (int nt = 0; nt < 8; ++nt) {
                int gp = nt >> 1, j = nt & 1;
                uint32_t b0h = kh[gp][j*2], b1h = kh[gp][j*2+1];
                uint32_t b0l = kl[gp][j*2], b1l = kl[gp][j*2+1];
                mma16816(cs[nt], ah, b0h, b1h);
                mma16816(cs[nt], ah, b0l, b1l);
                mma16816(cs[nt], al, b0h, b1h);
            }
        }

        /* scale + causal mask in registers */
        {
            int row0 = q0 + m_base + rq;
            int row1 = row0 + 8;
            #pragma unroll
            for (int nt = 0; nt < 8; ++nt) {
                int col = k0t + nt*8 + (lane & 3)*2;
                cs[nt][0] = (col     > row0) ? -1e30f : cs[nt][0]*scale;
                cs[nt][1] = (col + 1 > row0) ? -1e30f : cs[nt][1]*scale;
                cs[nt][2] = (col     > row1) ? -1e30f : cs[nt][2]*scale;
                cs[nt][3] = (col + 1 > row1) ? -1e30f : cs[nt][3]*scale;
            }
        }

        /* register online softmax (4 threads per row via quad shfl) */
        {
            float mx0 = -1e30f, mx1 = -1e30f;
            #pragma unroll
            for (int nt = 0; nt < 8; ++nt) {
                mx0 = fmaxf(mx0, fmaxf(cs[nt][0], cs[nt][1]));
                mx1 = fmaxf(mx1, fmaxf(cs[nt][2], cs[nt][3]));
            }
            mx0 = fmaxf(mx0, __shfl_xor_sync(0xffffffffu, mx0, 1));
            mx0 = fmaxf(mx0, __shfl_xor_sync(0xffffffffu, mx0, 2));
            mx1 = fmaxf(mx1, __shfl_xor_sync(0xffffffffu, mx1, 1));
            mx1 = fmaxf(mx1, __shfl_xor_sync(0xffffffffu, mx1, 2));
            float m0n = fmaxf(m0, mx0), m1n = fmaxf(m1, mx1);
            float cr0 = __expf(m0 - m0n), cr1 = __expf(m1 - m1n);
            float s0 = 0.f, s1 = 0.f;
            #pragma unroll
            for (int nt = 0; nt < 8; ++nt) {
                cs[nt][0] = __expf(cs[nt][0] - m0n);
                cs[nt][1] = __expf(cs[nt][1] - m0n);
                cs[nt][2] = __expf(cs[nt][2] - m1n);
                cs[nt][3] = __expf(cs[nt][3] - m1n);
                s0 += cs[nt][0] + cs[nt][1];
                s1 += cs[nt][2] + cs[nt][3];
            }
            s0 += __shfl_xor_sync(0xffffffffu, s0, 1);
            s0 += __shfl_xor_sync(0xffffffffu, s0, 2);
            s1 += __shfl_xor_sync(0xffffffffu, s1, 1);
            s1 += __shfl_xor_sync(0xffffffffu, s1, 2);
            l0 = l0*cr0 + s0;  m0 = m0n;
            l1 = l1*cr1 + s1;  m1 = m1n;
            #pragma unroll
            for (int nt = 0; nt < 16; ++nt) {
                co[nt][0] *= cr0; co[nt][1] *= cr0;
                co[nt][2] *= cr1; co[nt][3] *= cr1;
            }
        }

        /* P: C-fragments -> A-fragments (hi/lo), in registers */
        uint32_t ph[4][4], pl[4][4];
        #pragma unroll
        for (int t = 0; t < 4; ++t) {
            bf162 hi, lo;
            split_pair(cs[2*t][0],   cs[2*t][1],   &hi, &lo);
            ph[t][0] = *(uint32_t*)&hi; pl[t][0] = *(uint32_t*)&lo;
            split_pair(cs[2*t][2],   cs[2*t][3],   &hi, &lo);
            ph[t][1] = *(uint32_t*)&hi; pl[t][1] = *(uint32_t*)&lo;
            split_pair(cs[2*t+1][0], cs[2*t+1][1], &hi, &lo);
            ph[t][2] = *(uint32_t*)&hi; pl[t][2] = *(uint32_t*)&lo;
            split_pair(cs[2*t+1][2], cs[2*t+1][3], &hi, &lo);
            ph[t][3] = *(uint32_t*)&hi; pl[t][3] = *(uint32_t*)&lo;
        }

        asm volatile("cp.async.wait_group 0;" ::: "memory");   /* V ready */
        __syncthreads();

        /* O += P @ V : warp tile 16x128 */
        #pragma unroll
        for (int t = 0; t < 4; ++t) {
            int kk = t * 16;
            uint32_t vh[8][4], vl[8][4];
            #pragma unroll
            for (int gp = 0; gp < 8; ++gp) {
                int kr = kk + (lane & 7) + ((lane >> 3) & 1) * 8;
                int nn = gp*16 + (lane >> 4) * 8;
                ldsm_x4_t(vh[gp], smem_u32(&sm->Vh[kr][nn]));
                ldsm_x4_t(vl[gp], smem_u32(&sm->Vl[kr][nn]));
            }
            #pragma unroll
            for (int nt = 0; nt < 16; ++nt) {
                int gp = nt >> 1, j = nt & 1;
                uint32_t b0h = vh[gp][j*2], b1h = vh[gp][j*2+1];
                uint32_t b0l = vl[gp][j*2], b1l = vl[gp][j*2+1];
                mma16816(co[nt], ph[t], b0h, b1h);
                mma16816(co[nt], ph[t], b0l, b1l);
                mma16816(co[nt], pl[t], b0h, b1h);
            }
        }
    }

    /* epilogue: normalize, split, write ctx hi/lo */
    {
        int r0 = m_base + rq;
        float il0 = 1.0f / l0;
        float il1 = 1.0f / l1;
        #pragma unroll
        for (int nt = 0; nt < 16; ++nt) {
            int col = nt*8 + (lane & 3)*2;
            size_t off0 = ((size_t)(b*S_LEN + q0 + r0))*(NH*DHEAD) + (size_t)h*DHEAD + col;
            size_t off1 = ((size_t)(b*S_LEN + q0 + r0 + 8))*(NH*DHEAD) + (size_t)h*DHEAD + col;
            bf162 hi, lo;
            split_pair(co[nt][0]*il0, co[nt][1]*il0, &hi, &lo);
            *(bf162*)(g_ch + off0) = hi;
            *(bf162*)(g_cl + off0) = lo;
            split_pair(co[nt][2]*il1, co[nt][3]*il1, &hi, &lo);
            *(bf162*)(g_ch + off1) = hi;
            *(bf162*)(g_cl + off1) = lo;
        }
    }
}

extern "C" void kernel_launch(void* const* d_in, const int* in_sizes, int n_in,
                              void* d_out, int out_size) {
    int idx_x = -1, sm_[2], nsm = 0, bg[3], nbg = 0;
    for (int i = 0; i < n_in; ++i) {
        if (in_sizes[i] == 8388608 && idx_x < 0) idx_x = i;
        else if (in_sizes[i] == 1048576 && nsm < 2) sm_[nsm++] = i;
        else if (in_sizes[i] == 4194304 && nbg < 3) bg[nbg++] = i;
    }
    const float *x, *Wk, *Wv;
    const unsigned char *c0, *c1, *c2;
    if (idx_x >= 0 && nsm == 2 && nbg == 3) {
        x  = (const float*)d_in[idx_x];
        Wk = (const float*)d_in[sm_[0]];
        Wv = (const float*)d_in[sm_[1]];
        c0 = (const unsigned char*)d_in[bg[0]];
        c1 = (const unsigned char*)d_in[bg[1]];
        c2 = (const unsigned char*)d_in[bg[2]];
    } else {
        x  = (const float*)d_in[0];
        Wk = (const float*)d_in[2];
        Wv = (const float*)d_in[3];
        c0 = (const unsigned char*)d_in[1];
        c1 = (const unsigned char*)d_in[4];
        c2 = (const unsigned char*)d_in[5];
    }
    float* out = (float*)d_out;

    bf16 *xh, *xl, *wqh, *wql, *wkh, *wkl, *wvh, *wvl, *woh, *wol, *vh, *vl;
    float *vp;
    cudaGetSymbolAddress((void**)&xh,  g_xh);  cudaGetSymbolAddress((void**)&xl,  g_xl);
    cudaGetSymbolAddress((void**)&wqh, g_wqh); cudaGetSymbolAddress((void**)&wql, g_wql);
    cudaGetSymbolAddress((void**)&wkh, g_wkh); cudaGetSymbolAddress((void**)&wkl, g_wkl);
    cudaGetSymbolAddress((void**)&wvh, g_wvh); cudaGetSymbolAddress((void**)&wvl, g_wvl);
    cudaGetSymbolAddress((void**)&woh, g_woh); cudaGetSymbolAddress((void**)&wol, g_wol);
    cudaGetSymbolAddress((void**)&vh,  g_vh);  cudaGetSymbolAddress((void**)&vl,  g_vl);
    cudaGetSymbolAddress((void**)&vp,  g_v);

    probe_kernel<<<1, 32>>>(c0, c1, c2);
    build_rope_kernel<<<S_LEN, 64>>>();

    split_kernel<<<(MROWS*D_MODEL/2 + 255)/256, 256>>>(x, xh, xl, MROWS*D_MODEL/2, 0);
    split_kernel<<<(D_MODEL*NH*DHEAD/2 + 255)/256, 256>>>(0, wqh, wql, D_MODEL*NH*DHEAD/2, 1);
    split_kernel<<<(D_MODEL*NG*DHEAD/2 + 255)/256, 256>>>(Wk, wkh, wkl, D_MODEL*NG*DHEAD/2, 0);
    split_kernel<<<(D_MODEL*NG*DHEAD/2 + 255)/256, 256>>>(Wv, wvh, wvl, D_MODEL*NG*DHEAD/2, 0);
    split_kernel<<<(D_MODEL*D_MODEL/2 + 255)/256, 256>>>(0, woh, wol, D_MODEL*D_MODEL/2, 2);

    int gemm_smem = (int)sizeof(SmemGemmP);
    cudaFuncSetAttribute(qkv_gemm_bf16, cudaFuncAttributeMaxDynamicSharedMemorySize, gemm_smem);
    cudaFuncSetAttribute(out_gemm_bf16, cudaFuncAttributeMaxDynamicSharedMemorySize, gemm_smem);

    qkv_gemm_bf16<<<dim3(24, MROWS/128), 256, gemm_smem>>>();

    rope_split_q<<<dim3(MROWS, NH), 64>>>();
    rope_split_k<<<dim3(MROWS, NG), 64>>>();
    split_kernel<<<(MROWS*NG*DHEAD/2 + 255)/256, 256>>>(vp, vh, vl, MROWS*NG*DHEAD/2, 0);

    const size_t OUT_MAIN = (size_t)NB * S_LEN * D_MODEL;
    const size_t CACHE    = (size_t)NB * NG * S_LEN * DHEAD;
    if ((size_t)out_size >= OUT_MAIN + 2*CACHE) {
        cache_kernel<<<(int)((CACHE + 255)/256), 256>>>(out + OUT_MAIN);
    }

    int fl2_smem = (int)sizeof(SmemFlash);
    cudaFuncSetAttribute(flash2_kernel, cudaFuncAttributeMaxDynamicSharedMemorySize, fl2_smem);
    flash2_kernel<<<dim3(S_LEN/128, NH, NB), 256, fl2_smem>>>();

    out_gemm_bf16<<<dim3(D_MODEL/128, MROWS/128), 256, gemm_smem>>>(out);
}

// round 13
// speedup vs baseline: 4.8220x; 1.0685x over previous
#include <cuda_runtime.h>
#include <cuda_bf16.h>
#include <math.h>
#include <stdint.h>

#define S_LEN   2048
#define D_MODEL 2048
#define NH      16
#define NG      4
#define DHEAD   128
#define NB      2
#define MROWS   (NB*S_LEN)
typedef __nv_bfloat16 bf16;
typedef __nv_bfloat162 bf162;

__device__ float g_rope[S_LEN * DHEAD];
__device__ const float* g_wq_slot;
__device__ const float* g_wo_slot;

/* persistent bf16 hi/lo operands */
__device__ bf16 g_xh [(size_t)MROWS * D_MODEL],      g_xl [(size_t)MROWS * D_MODEL];
__device__ bf16 g_wqh[(size_t)D_MODEL * NH*DHEAD],   g_wql[(size_t)D_MODEL * NH*DHEAD];
__device__ bf16 g_wkh[(size_t)D_MODEL * NG*DHEAD],   g_wkl[(size_t)D_MODEL * NG*DHEAD];
__device__ bf16 g_wvh[(size_t)D_MODEL * NG*DHEAD],   g_wvl[(size_t)D_MODEL * NG*DHEAD];
__device__ bf16 g_woh[(size_t)D_MODEL * D_MODEL],    g_wol[(size_t)D_MODEL * D_MODEL];
__device__ bf16 g_qh [(size_t)MROWS * NH*DHEAD],     g_ql [(size_t)MROWS * NH*DHEAD];
__device__ bf16 g_kh [(size_t)MROWS * NG*DHEAD],     g_kl [(size_t)MROWS * NG*DHEAD];
__device__ bf16 g_vh [(size_t)MROWS * NG*DHEAD],     g_vl [(size_t)MROWS * NG*DHEAD];
__device__ bf16 g_ch [(size_t)MROWS * NH*DHEAD],     g_cl [(size_t)MROWS * NH*DHEAD];

__global__ void probe_kernel(const unsigned char* c0, const unsigned char* c1,
                             const unsigned char* c2) {
    if (threadIdx.x != 0 || blockIdx.x != 0) return;
    const unsigned char* cs[3] = {c0, c1, c2};
    int nb[3];
    for (int i = 0; i < 3; ++i) {
        int boolish = 1;
        for (int k = 0; k < 64; ++k)
            if (cs[i][k * 97] > 1) { boolish = 0; break; }
        nb[i] = boolish;
    }
    int a = -1, b = -1;
    for (int i = 0; i < 3; ++i)
        if (!nb[i]) { if (a < 0) a = i; else if (b < 0) b = i; }
    if (a < 0 || b < 0) { a = 0; b = 1; }
    g_wq_slot = (const float*)cs[a];
    g_wo_slot = (const float*)cs[b];
}

__global__ void build_rope_kernel() {
    int s = blockIdx.x, d = threadIdx.x;
    float e    = (float)d / 64.0f;
    float invf = 1.0f / powf(10000.0f, e);
    float ang  = (float)s * invf;
    g_rope[s*DHEAD + d]      = (float)cos((double)ang);
    g_rope[s*DHEAD + 64 + d] = (float)sin((double)ang);
}

__device__ __forceinline__ void split_pair(float x, float y, bf162* hi, bf162* lo) {
    bf16 hx = __float2bfloat16_rn(x);
    bf16 hy = __float2bfloat16_rn(y);
    *hi = __halves2bfloat162(hx, hy);
    *lo = __halves2bfloat162(__float2bfloat16_rn(x - __bfloat162float(hx)),
                             __float2bfloat16_rn(y - __bfloat162float(hy)));
}

__global__ void split_kernel(const float* in, bf16* oh, bf16* ol, int n2, int which) {
    if (which == 1) in = g_wq_slot;
    else if (which == 2) in = g_wo_slot;
    int i = blockIdx.x * blockDim.x + threadIdx.x;
    if (i >= n2) return;
    float2 v = *(const float2*)(in + (size_t)i*2);
    bf162 hi, lo;
    split_pair(v.x, v.y, &hi, &lo);
    *(bf162*)(oh + (size_t)i*2) = hi;
    *(bf162*)(ol + (size_t)i*2) = lo;
}

/* ================= mma / async helpers ==================================== */
__device__ __forceinline__ uint32_t smem_u32(const void* p) {
    return (uint32_t)__cvta_generic_to_shared(p);
}
__device__ __forceinline__ void cp_async16(void* smem, const void* gmem) {
    asm volatile("cp.async.cg.shared.global [%0], [%1], 16;"
        :: "r"(smem_u32(smem)), "l"(gmem));
}
__device__ __forceinline__ void cp_commit() {
    asm volatile("cp.async.commit_group;");
}
__device__ __forceinline__ void ldsm_x4(uint32_t* r, uint32_t addr) {
    asm volatile("ldmatrix.sync.aligned.m8n8.x4.shared.b16 {%0,%1,%2,%3}, [%4];"
        : "=r"(r[0]), "=r"(r[1]), "=r"(r[2]), "=r"(r[3]) : "r"(addr));
}
__device__ __forceinline__ void ldsm_x4_t(uint32_t* r, uint32_t addr) {
    asm volatile("ldmatrix.sync.aligned.m8n8.x4.trans.shared.b16 {%0,%1,%2,%3}, [%4];"
        : "=r"(r[0]), "=r"(r[1]), "=r"(r[2]), "=r"(r[3]) : "r"(addr));
}
__device__ __forceinline__ void mma16816(float* c, const uint32_t* a,
                                         uint32_t b0, uint32_t b1) {
    asm volatile("mma.sync.aligned.m16n8k16.row.col.f32.bf16.bf16.f32 "
        "{%0,%1,%2,%3}, {%4,%5,%6,%7}, {%8,%9}, {%0,%1,%2,%3};"
        : "+f"(c[0]), "+f"(c[1]), "+f"(c[2]), "+f"(c[3])
        : "r"(a[0]), "r"(a[1]), "r"(a[2]), "r"(a[3]), "r"(b0), "r"(b1));
}

/* ================= pipelined pre-split bf16 GEMM ========================== */
struct SmemGemmP {
    bf16 Ah[2][128][40], Al[2][128][40];
    bf16 Bh[2][32][136], Bl[2][32][136];
};

__device__ __forceinline__ void gemm_load_stage(SmemGemmP* sm, int st,
                                                const bf16* Ah, const bf16* Al,
                                                const bf16* Bh, const bf16* Bl,
                                                int N, int K, int bm, int bn, int k0) {
    int tid = threadIdx.x;
    #pragma unroll
    for (int i = 0; i < 2; ++i) {
        int fid = tid + i*256;
        int row = fid >> 2, c8 = (fid & 3) * 8;
        size_t go = (size_t)(bm + row)*K + k0 + c8;
        cp_async16(&sm->Ah[st][row][c8], Ah + go);
        cp_async16(&sm->Al[st][row][c8], Al + go);
    }
    #pragma unroll
    for (int i = 0; i < 2; ++i) {
        int fid = tid + i*256;
        int row = fid >> 4, c8 = (fid & 15) * 8;
        size_t go = (size_t)(k0 + row)*N + bn + c8;
        cp_async16(&sm->Bh[st][row][c8], Bh + go);
        cp_async16(&sm->Bl[st][row][c8], Bl + go);
    }
}

/* mainloop: leaves the 128x128 fp32 tile in c[][] fragments */
__device__ __forceinline__ void gemm_mainloop(SmemGemmP* sm,
                                              const bf16* Ah, const bf16* Al,
                                              const bf16* Bh, const bf16* Bl,
                                              int N, int K, int bm, int bn,
                                              float c[2][8][4]) {
    int tid = threadIdx.x;
    int warp = tid >> 5, lane = tid & 31;
    int m_base = (warp >> 1) * 32;
    int n_base = (warp & 1) * 64;

    #pragma unroll
    for (int mt = 0; mt < 2; ++mt)
        #pragma unroll
        for (int nt = 0; nt < 8; ++nt)
            #pragma unroll
            for (int r = 0; r < 4; ++r) c[mt][nt][r] = 0.f;

    const int NIT = K / 32;
    gemm_load_stage(sm, 0, Ah, Al, Bh, Bl, N, K, bm, bn, 0);
    cp_commit();

    for (int it = 0; it < NIT; ++it) {
        int cur = it & 1;
        if (it + 1 < NIT) {
            gemm_load_stage(sm, cur ^ 1, Ah, Al, Bh, Bl, N, K, bm, bn, (it+1)*32);
            cp_commit();
            asm volatile("cp.async.wait_group 1;" ::: "memory");
        } else {
            asm volatile("cp.async.wait_group 0;" ::: "memory");
        }
        __syncthreads();

        #pragma unroll
        for (int ks = 0; ks < 32; ks += 16) {
            uint32_t ah[2][4], al[2][4];
            #pragma unroll
            for (int mt = 0; mt < 2; ++mt) {
                int rr = m_base + mt*16 + (lane & 15);
                int kk = ks + (lane >> 4) * 8;
                ldsm_x4(ah[mt], smem_u32(&sm->Ah[cur][rr][kk]));
                ldsm_x4(al[mt], smem_u32(&sm->Al[cur][rr][kk]));
            }
            uint32_t bh[4][4], bl[4][4];
            #pragma unroll
            for (int nc = 0; nc < 4; ++nc) {
                int kr = ks + (lane & 7) + ((lane >> 3) & 1) * 8;
                int nn = n_base + nc*16 + (lane >> 4) * 8;
                ldsm_x4_t(bh[nc], smem_u32(&sm->Bh[cur][kr][nn]));
                ldsm_x4_t(bl[nc], smem_u32(&sm->Bl[cur][kr][nn]));
            }
            #pragma unroll
            for (int mt = 0; mt < 2; ++mt)
                #pragma unroll
                for (int nc = 0; nc < 4; ++nc)
                    #pragma unroll
                    for (int hf = 0; hf < 2; ++hf) {
                        float* cc = c[mt][nc*2 + hf];
                        uint32_t b0h = bh[nc][hf*2], b1h = bh[nc][hf*2+1];
                        uint32_t b0l = bl[nc][hf*2], b1l = bl[nc][hf*2+1];
                        mma16816(cc, ah[mt], b0h, b1h);
                        mma16816(cc, ah[mt], b0l, b1l);
                        mma16816(cc, al[mt], b0h, b1h);
                    }
        }
        __syncthreads();
    }
}

/* fused QKV GEMM: epilogue applies RoPE (q,k), splits to bf16 hi/lo, and
 * writes the fp32 KV cache directly. Each 128-col block = one head.        */
__global__ void __launch_bounds__(256) qkv_gemm_fused(float* cache_k, float* cache_v) {
    extern __shared__ char smraw[];
    SmemGemmP* sm = (SmemGemmP*)smraw;
    int bx = blockIdx.x, bm = blockIdx.y * 128;
    int tid = threadIdx.x;
    int warp = tid >> 5, lane = tid & 31;
    int m_base = (warp >> 1) * 32;
    int n_base = (warp & 1) * 64;

    int mode;      /* 0=q, 1=k, 2=v */
    int bn, N;
    bf16 *oh, *ol;
    if (bx < 16)      { mode = 0; bn = bx*128;      N = NH*DHEAD; oh = g_qh; ol = g_ql; }
    else if (bx < 20) { mode = 1; bn = (bx-16)*128; N = NG*DHEAD; oh = g_kh; ol = g_kl; }
    else              { mode = 2; bn = (bx-20)*128; N = NG*DHEAD; oh = g_vh; ol = g_vl; }

    float c[2][8][4];
    if (mode == 0)
        gemm_mainloop(sm, g_xh, g_xl, g_wqh, g_wql, N, D_MODEL, bm, bn, c);
    else if (mode == 1)
        gemm_mainloop(sm, g_xh, g_xl, g_wkh, g_wkl, N, D_MODEL, bm, bn, c);
    else
        gemm_mainloop(sm, g_xh, g_xl, g_wvh, g_wvl, N, D_MODEL, bm, bn, c);

    /* stage fp32 tile through smem (aliases pipeline buffers; post-sync) */
    float* Cs = (float*)smraw;          /* [128][132] = 67,584 B */
    #pragma unroll
    for (int mt = 0; mt < 2; ++mt)
        #pragma unroll
        for (int nt = 0; nt < 8; ++nt) {
            int r   = m_base + mt*16 + (lane >> 2);
            int col = n_base + nt*8 + (lane & 3)*2;
            *(float2*)&Cs[r*132 + col]     = make_float2(c[mt][nt][0], c[mt][nt][1]);
            *(float2*)&Cs[(r+8)*132 + col] = make_float2(c[mt][nt][2], c[mt][nt][3]);
        }
    __syncthreads();

    int ghead = bn >> 7;                /* head index within k/v buffers */
    #pragma unroll
    for (int i = 0; i < 32; ++i) {
        int p   = tid + i*256;          /* 8192 pairs: 128 rows x 64 */
        int row = p >> 6, d = p & 63;
        int grow = bm + row;
        int s = grow & (S_LEN - 1);
        int b = grow >> 11;
        float x1 = Cs[row*132 + d];
        float x2 = Cs[row*132 + d + 64];
        float r1, r2;
        if (mode < 2) {                 /* rope for q,k */
            float ct = g_rope[s*DHEAD + d];
            float st = g_rope[s*DHEAD + 64 + d];
            r1 = x1*ct - x2*st;
            r2 = x2*ct + x1*st;
        } else { r1 = x1; r2 = x2; }
        size_t o = (size_t)grow*N + bn + d;
        bf16 h1 = __float2bfloat16_rn(r1), h2 = __float2bfloat16_rn(r2);
        oh[o]      = h1;
        oh[o + 64] = h2;
        ol[o]      = __float2bfloat16_rn(r1 - __bfloat162float(h1));
        ol[o + 64] = __float2bfloat16_rn(r2 - __bfloat162float(h2));
        if (mode == 1 && cache_k) {
            size_t co_ = ((size_t)(b*NG + ghead)*S_LEN + s)*DHEAD + d;
            cache_k[co_]      = r1;
            cache_k[co_ + 64] = r2;
        } else if (mode == 2 && cache_v) {
            size_t co_ = ((size_t)(b*NG + ghead)*S_LEN + s)*DHEAD + d;
            cache_v[co_]      = r1;
            cache_v[co_ + 64] = r2;
        }
    }
}

/* output GEMM: plain fp32 epilogue to d_out */
__global__ void __launch_bounds__(256) out_gemm_bf16(float* __restrict__ C) {
    extern __shared__ char smraw[];
    SmemGemmP* sm = (SmemGemmP*)smraw;
    int tid = threadIdx.x;
    int warp = tid >> 5, lane = tid & 31;
    int m_base = (warp >> 1) * 32;
    int n_base = (warp & 1) * 64;
    int bm = blockIdx.y*128, bn = blockIdx.x*128;

    float c[2][8][4];
    gemm_mainloop(sm, g_ch, g_cl, g_woh, g_wol, D_MODEL, D_MODEL, bm, bn, c);

    #pragma unroll
    for (int mt = 0; mt < 2; ++mt)
        #pragma unroll
        for (int nt = 0; nt < 8; ++nt) {
            int r   = bm + m_base + mt*16 + (lane >> 2);
            int col = bn + n_base + nt*8 + (lane & 3)*2;
            *(float2*)(C + (size_t)r*D_MODEL + col)     = make_float2(c[mt][nt][0], c[mt][nt][1]);
            *(float2*)(C + (size_t)(r+8)*D_MODEL + col) = make_float2(c[mt][nt][2], c[mt][nt][3]);
        }
}

/* ================= flash attention, BQ=128, register softmax (R12) ======== */
struct SmemFlash {
    bf16 Qh[128][136], Ql[128][136];
    bf16 Kh[64][136], Kl[64][136];
    bf16 Vh[64][136], Vl[64][136];
};

__global__ void __launch_bounds__(256) flash2_kernel() {
    extern __shared__ char smraw[];
    SmemFlash* sm = (SmemFlash*)smraw;

    int qt = (int)(gridDim.x - 1 - blockIdx.x);
    int h = blockIdx.y, b = blockIdx.z;
    int g  = h >> 2;
    int q0 = qt * 128;
    int tid = threadIdx.x, warp = tid >> 5, lane = tid & 31;
    int m_base = warp * 16;
    int rq = lane >> 2;

    size_t qoff = ((size_t)(b*S_LEN + q0))*(NH*DHEAD) + (size_t)h*DHEAD;
    #pragma unroll
    for (int i = 0; i < 8; ++i) {
        int fid = tid + i*256;
        int row = fid >> 4, c8 = (fid & 15) * 8;
        size_t go = qoff + (size_t)row*(NH*DHEAD) + c8;
        *(uint4*)&sm->Qh[row][c8] = *(const uint4*)(g_qh + go);
        *(uint4*)&sm->Ql[row][c8] = *(const uint4*)(g_ql + go);
    }

    float co[16][4];
    #pragma unroll
    for (int nt = 0; nt < 16; ++nt)
        #pragma unroll
        for (int r = 0; r < 4; ++r) co[nt][r] = 0.f;
    float m0 = -1e30f, m1 = -1e30f, l0 = 0.f, l1 = 0.f;

    size_t kvoff = (size_t)(b*S_LEN)*(NG*DHEAD) + (size_t)g*DHEAD;
    const float scale = 0.08838834764831845f;
    const int nkt = 2*qt + 2;

    for (int kt = 0; kt < nkt; ++kt) {
        int k0t = kt * 64;
        __syncthreads();
        #pragma unroll
        for (int i = 0; i < 4; ++i) {
            int fid = tid + i*256;
            int row = fid >> 4, c8 = (fid & 15) * 8;
            size_t go = kvoff + (size_t)(k0t + row)*(NG*DHEAD) + c8;
            cp_async16(&sm->Kh[row][c8], g_kh + go);
            cp_async16(&sm->Kl[row][c8], g_kl + go);
        }
        cp_commit();
        #pragma unroll
        for (int i = 0; i < 4; ++i) {
            int fid = tid + i*256;
            int row = fid >> 4, c8 = (fid & 15) * 8;
            size_t go = kvoff + (size_t)(k0t + row)*(NG*DHEAD) + c8;
            cp_async16(&sm->Vh[row][c8], g_vh + go);
            cp_async16(&sm->Vl[row][c8], g_vl + go);
        }
        cp_commit();
        asm volatile("cp.async.wait_group 1;" ::: "memory");
        __syncthreads();

        float cs[8][4];
        #pragma unroll
        for (int nt = 0; nt < 8; ++nt)
            #pragma unroll
            for (int r = 0; r < 4; ++r) cs[nt][r] = 0.f;

        #pragma unroll
        for (int ks = 0; ks < 8; ++ks) {
            int kk = ks * 16;
            uint32_t ah[4], al[4];
            int ar = m_base + (lane & 15);
            int ac = kk + (lane >> 4) * 8;
            ldsm_x4(ah, smem_u32(&sm->Qh[ar][ac]));
            ldsm_x4(al, smem_u32(&sm->Ql[ar][ac]));
            uint32_t kh[4][4], kl[4][4];
            #pragma unroll
            for (int gp = 0; gp < 4; ++gp) {
                int br = gp*16 + (lane & 7) + (lane >> 4) * 8;
                int bc = kk + ((lane >> 3) & 1) * 8;
                ldsm_x4(kh[gp], smem_u32(&sm->Kh[br][bc]));
                ldsm_x4(kl[gp], smem_u32(&sm->Kl[br][bc]));
            }
            #pragma unroll
            for (int nt = 0; nt < 8; ++nt) {
                int gp = nt >> 1, j = nt & 1;
                uint32_t b0h = kh[gp][j*2], b1h = kh[gp][j*2+1];
                uint32_t b0l = kl[gp][j*2], b1l = kl[gp][j*2+1];
                mma16816(cs[nt], ah, b0h, b1h);
                mma16816(cs[nt], ah, b0l, b1l);
                mma16816(cs[nt], al, b0h, b1h);
            }
        }

        {
            int row0 = q0 + m_base + rq;
            int row1 = row0 + 8;
            #pragma unroll
            for (int nt = 0; nt < 8; ++nt) {
                int col = k0t + nt*8 + (lane & 3)*2;
                cs[nt][0] = (col     > row0) ? -1e30f : cs[nt][0]*scale;
                cs[nt][1] = (col + 1 > row0) ? -1e30f : cs[nt][1]*scale;
                cs[nt][2] = (col     > row1) ? -1e30f : cs[nt][2]*scale;
                cs[nt][3] = (col + 1 > row1) ? -1e30f : cs[nt][3]*scale;
            }
        }

        {
            float mx0 = -1e30f, mx1 = -1e30f;
            #pragma unroll
            for (int nt = 0; nt < 8; ++nt) {
                mx0 = fmaxf(mx0, fmaxf(cs[nt][0], cs[nt][1]));
                mx1 = fmaxf(mx1, fmaxf(cs[nt][2], cs[nt][3]));
            }
            mx0 = fmaxf(mx0, __shfl_xor_sync(0xffffffffu, mx0, 1));
            mx0 = fmaxf(mx0, __shfl_xor_sync(0xffffffffu, mx0, 2));
            mx1 = fmaxf(mx1, __shfl_xor_sync(0xffffffffu, mx1, 1));
            mx1 = fmaxf(mx1, __shfl_xor_sync(0xffffffffu, mx1, 2));
            float m0n = fmaxf(m0, mx0), m1n = fmaxf(m1, mx1);
            float cr0 = __expf(m0 - m0n), cr1 = __expf(m1 - m1n);
            float s0 = 0.f, s1 = 0.f;
            #pragma unroll
            for (int nt = 0; nt < 8; ++nt) {
                cs[nt][0] = __expf(cs[nt][0] - m0n);
                cs[nt][1] = __expf(cs[nt][1] - m0n);
                cs[nt][2] = __expf(cs[nt][2] - m1n);
                cs[nt][3] = __expf(cs[nt][3] - m1n);
                s0 += cs[nt][0] + cs[nt][1];
                s1 += cs[nt][2] + cs[nt][3];
            }
            s0 += __shfl_xor_sync(0xffffffffu, s0, 1);
            s0 += __shfl_xor_sync(0xffffffffu, s0, 2);
            s1 += __shfl_xor_sync(0xffffffffu, s1, 1);
            s1 += __shfl_xor_sync(0xffffffffu, s1, 2);
            l0 = l0*cr0 + s0;  m0 = m0n;
            l1 = l1*cr1 + s1;  m1 = m1n;
            #pragma unroll
            for (int nt = 0; nt < 16; ++nt) {
                co[nt][0] *= cr0; co[nt][1] *= cr0;
                co[nt][2] *= cr1; co[nt][3] *= cr1;
            }
        }

        uint32_t ph[4][4], pl[4][4];
        #pragma unroll
        for (int t = 0; t < 4; ++t) {
            bf162 hi, lo;
            split_pair(cs[2*t][0],   cs[2*t][1],   &hi, &lo);
            ph[t][0] = *(uint32_t*)&hi; pl[t][0] = *(uint32_t*)&lo;
            split_pair(cs[2*t][2],   cs[2*t][3],   &hi, &lo);
            ph[t][1] = *(uint32_t*)&hi; pl[t][1] = *(uint32_t*)&lo;
            split_pair(cs[2*t+1][0], cs[2*t+1][1], &hi, &lo);
            ph[t][2] = *(uint32_t*)&hi; pl[t][2] = *(uint32_t*)&lo;
            split_pair(cs[2*t+1][2], cs[2*t+1][3], &hi, &lo);
            ph[t][3] = *(uint32_t*)&hi; pl[t][3] = *(uint32_t*)&lo;
        }

        asm volatile("cp.async.wait_group 0;" ::: "memory");
        __syncthreads();

        #pragma unroll
        for (int t = 0; t < 4; ++t) {
            int kk = t * 16;
            uint32_t vh[8][4], vl[8][4];
            #pragma unroll
            for (int gp = 0; gp < 8; ++gp) {
                int kr = kk + (lane & 7) + ((lane >> 3) & 1) * 8;
                int nn = gp*16 + (lane >> 4) * 8;
                ldsm_x4_t(vh[gp], smem_u32(&sm->Vh[kr][nn]));
                ldsm_x4_t(vl[gp], smem_u32(&sm->Vl[kr][nn]));
            }
            #pragma unroll
            for (int nt = 0; nt < 16; ++nt) {
                int gp = nt >> 1, j = nt & 1;
                uint32_t b0h = vh[gp][j*2], b1h = vh[gp][j*2+1];
                uint32_t b0l = vl[gp][j*2], b1l = vl[gp][j*2+1];
                mma16816(co[nt], ph[t], b0h, b1h);
                mma16816(co[nt], ph[t], b0l, b1l);
                mma16816(co[nt], pl[t], b0h, b1h);
            }
        }
    }

    {
        int r0 = m_base + rq;
        float il0 = 1.0f / l0;
        float il1 = 1.0f / l1;
        #pragma unroll
        for (int nt = 0; nt < 16; ++nt) {
            int col = nt*8 + (lane & 3)*2;
            size_t off0 = ((size_t)(b*S_LEN + q0 + r0))*(NH*DHEAD) + (size_t)h*DHEAD + col;
            size_t off1 = ((size_t)(b*S_LEN + q0 + r0 + 8))*(NH*DHEAD) + (size_t)h*DHEAD + col;
            bf162 hi, lo;
            split_pair(co[nt][0]*il0, co[nt][1]*il0, &hi, &lo);
            *(bf162*)(g_ch + off0) = hi;
            *(bf162*)(g_cl + off0) = lo;
            split_pair(co[nt][2]*il1, co[nt][3]*il1, &hi, &lo);
            *(bf162*)(g_ch + off1) = hi;
            *(bf162*)(g_cl + off1) = lo;
        }
    }
}

extern "C" void kernel_launch(void* const* d_in, const int* in_sizes, int n_in,
                              void* d_out, int out_size) {
    int idx_x = -1, sm_[2], nsm = 0, bg[3], nbg = 0;
    for (int i = 0; i < n_in; ++i) {
        if (in_sizes[i] == 8388608 && idx_x < 0) idx_x = i;
        else if (in_sizes[i] == 1048576 && nsm < 2) sm_[nsm++] = i;
        else if (in_sizes[i] == 4194304 && nbg < 3) bg[nbg++] = i;
    }
    const float *x, *Wk, *Wv;
    const unsigned char *c0, *c1, *c2;
    if (idx_x >= 0 && nsm == 2 && nbg == 3) {
        x  = (const float*)d_in[idx_x];
        Wk = (const float*)d_in[sm_[0]];
        Wv = (const float*)d_in[sm_[1]];
        c0 = (const unsigned char*)d_in[bg[0]];
        c1 = (const unsigned char*)d_in[bg[1]];
        c2 = (const unsigned char*)d_in[bg[2]];
    } else {
        x  = (const float*)d_in[0];
        Wk = (const float*)d_in[2];
        Wv = (const float*)d_in[3];
        c0 = (const unsigned char*)d_in[1];
        c1 = (const unsigned char*)d_in[4];
        c2 = (const unsigned char*)d_in[5];
    }
    float* out = (float*)d_out;

    bf16 *xh, *xl, *wqh, *wql, *wkh, *wkl, *wvh, *wvl, *woh, *wol;
    cudaGetSymbolAddress((void**)&xh,  g_xh);  cudaGetSymbolAddress((void**)&xl,  g_xl);
    cudaGetSymbolAddress((void**)&wqh, g_wqh); cudaGetSymbolAddress((void**)&wql, g_wql);
    cudaGetSymbolAddress((void**)&wkh, g_wkh); cudaGetSymbolAddress((void**)&wkl, g_wkl);
    cudaGetSymbolAddress((void**)&wvh, g_wvh); cudaGetSymbolAddress((void**)&wvl, g_wvl);
    cudaGetSymbolAddress((void**)&woh, g_woh); cudaGetSymbolAddress((void**)&wol, g_wol);

    probe_kernel<<<1, 32>>>(c0, c1, c2);
    build_rope_kernel<<<S_LEN, 64>>>();

    split_kernel<<<(MROWS*D_MODEL/2 + 255)/256, 256>>>(x, xh, xl, MROWS*D_MODEL/2, 0);
    split_kernel<<<(D_MODEL*NH*DHEAD/2 + 255)/256, 256>>>(0, wqh, wql, D_MODEL*NH*DHEAD/2, 1);
    split_kernel<<<(D_MODEL*NG*DHEAD/2 + 255)/256, 256>>>(Wk, wkh, wkl, D_MODEL*NG*DHEAD/2, 0);
    split_kernel<<<(D_MODEL*NG*DHEAD/2 + 255)/256, 256>>>(Wv, wvh, wvl, D_MODEL*NG*DHEAD/2, 0);
    split_kernel<<<(D_MODEL*D_MODEL/2 + 255)/256, 256>>>(0, woh, wol, D_MODEL*D_MODEL/2, 2);

    const size_t OUT_MAIN = (size_t)NB * S_LEN * D_MODEL;
    const size_t CACHE    = (size_t)NB * NG * S_LEN * DHEAD;
    float* cache_k = 0;
    float* cache_v = 0;
    if ((size_t)out_size >= OUT_MAIN + 2*CACHE) {
        cache_k = out + OUT_MAIN;
        cache_v = out + OUT_MAIN + CACHE;
    }

    int gemm_smem = (int)sizeof(SmemGemmP);
    cudaFuncSetAttribute(qkv_gemm_fused, cudaFuncAttributeMaxDynamicSharedMemorySize, gemm_smem);
    cudaFuncSetAttribute(out_gemm_bf16, cudaFuncAttributeMaxDynamicSharedMemorySize, gemm_smem);

    qkv_gemm_fused<<<dim3(24, MROWS/128), 256, gemm_smem>>>(cache_k, cache_v);

    int fl2_smem = (int)sizeof(SmemFlash);
    cudaFuncSetAttribute(flash2_kernel, cudaFuncAttributeMaxDynamicSharedMemorySize, fl2_smem);
    flash2_kernel<<<dim3(S_LEN/128, NH, NB), 256, fl2_smem>>>();

    out_gemm_bf16<<<dim3(D_MODEL/128, MROWS/128), 256, gemm_smem>>>(out);
}

// round 16
// speedup vs baseline: 4.8963x; 1.0154x over previous
#include <cuda_runtime.h>
#include <cuda_bf16.h>
#include <math.h>
#include <stdint.h>

#define S_LEN   2048
#define D_MODEL 2048
#define NH      16
#define NG      4
#define DHEAD   128
#define NB      2
#define MROWS   (NB*S_LEN)
typedef __nv_bfloat16 bf16;
typedef __nv_bfloat162 bf162;

__device__ float g_rope[S_LEN * DHEAD];
__device__ const float* g_wq_slot;
__device__ const float* g_wo_slot;

/* persistent bf16 hi/lo operands */
__device__ bf16 g_xh [(size_t)MROWS * D_MODEL],      g_xl [(size_t)MROWS * D_MODEL];
__device__ bf16 g_wqh[(size_t)D_MODEL * NH*DHEAD],   g_wql[(size_t)D_MODEL * NH*DHEAD];
__device__ bf16 g_wkh[(size_t)D_MODEL * NG*DHEAD],   g_wkl[(size_t)D_MODEL * NG*DHEAD];
__device__ bf16 g_wvh[(size_t)D_MODEL * NG*DHEAD],   g_wvl[(size_t)D_MODEL * NG*DHEAD];
__device__ bf16 g_woh[(size_t)D_MODEL * D_MODEL],    g_wol[(size_t)D_MODEL * D_MODEL];
__device__ bf16 g_qh [(size_t)MROWS * NH*DHEAD],     g_ql [(size_t)MROWS * NH*DHEAD];
__device__ bf16 g_kh [(size_t)MROWS * NG*DHEAD],     g_kl [(size_t)MROWS * NG*DHEAD];
__device__ bf16 g_vh [(size_t)MROWS * NG*DHEAD],     g_vl [(size_t)MROWS * NG*DHEAD];
__device__ bf16 g_ch [(size_t)MROWS * NH*DHEAD],     g_cl [(size_t)MROWS * NH*DHEAD];

__global__ void probe_kernel(const unsigned char* c0, const unsigned char* c1,
                             const unsigned char* c2) {
    if (threadIdx.x != 0 || blockIdx.x != 0) return;
    const unsigned char* cs[3] = {c0, c1, c2};
    int nb[3];
    for (int i = 0; i < 3; ++i) {
        int boolish = 1;
        for (int k = 0; k < 64; ++k)
            if (cs[i][k * 97] > 1) { boolish = 0; break; }
        nb[i] = boolish;
    }
    int a = -1, b = -1;
    for (int i = 0; i < 3; ++i)
        if (!nb[i]) { if (a < 0) a = i; else if (b < 0) b = i; }
    if (a < 0 || b < 0) { a = 0; b = 1; }
    g_wq_slot = (const float*)cs[a];
    g_wo_slot = (const float*)cs[b];
}

__global__ void build_rope_kernel() {
    int s = blockIdx.x, d = threadIdx.x;
    float e    = (float)d / 64.0f;
    float invf = 1.0f / powf(10000.0f, e);
    float ang  = (float)s * invf;
    g_rope[s*DHEAD + d]      = (float)cos((double)ang);
    g_rope[s*DHEAD + 64 + d] = (float)sin((double)ang);
}

__device__ __forceinline__ void split_pair(float x, float y, bf162* hi, bf162* lo) {
    bf16 hx = __float2bfloat16_rn(x);
    bf16 hy = __float2bfloat16_rn(y);
    *hi = __halves2bfloat162(hx, hy);
    *lo = __halves2bfloat162(__float2bfloat16_rn(x - __bfloat162float(hx)),
                             __float2bfloat16_rn(y - __bfloat162float(hy)));
}

/* single fused operand-split kernel over float2 units.
 * segments (blocks of 256 float2): x 16384 | wq 8192 | wk 2048 | wv 2048 | wo 8192
 * total = 36864 blocks (verified: sums of elem/512 per operand)               */
__global__ void __launch_bounds__(256) split_all(const float* x,
                                                 const float* Wk,
                                                 const float* Wv) {
    int blk = blockIdx.x;
    const float* in;
    bf16 *oh, *ol;
    int base;
    if (blk < 16384)      { in = x;         oh = g_xh;  ol = g_xl;  base = blk; }
    else if (blk < 24576) { in = g_wq_slot; oh = g_wqh; ol = g_wql; base = blk - 16384; }
    else if (blk < 26624) { in = Wk;        oh = g_wkh; ol = g_wkl; base = blk - 24576; }
    else if (blk < 28672) { in = Wv;        oh = g_wvh; ol = g_wvl; base = blk - 26624; }
    else                  { in = g_wo_slot; oh = g_woh; ol = g_wol; base = blk - 28672; }
    size_t i = (size_t)base * 256 + threadIdx.x;
    float2 v = *(const float2*)(in + i*2);
    bf162 hi, lo;
    split_pair(v.x, v.y, &hi, &lo);
    *(bf162*)(oh + i*2) = hi;
    *(bf162*)(ol + i*2) = lo;
}

/* ================= mma / async helpers ==================================== */
__device__ __forceinline__ uint32_t smem_u32(const void* p) {
    return (uint32_t)__cvta_generic_to_shared(p);
}
__device__ __forceinline__ void cp_async16(void* smem, const void* gmem) {
    asm volatile("cp.async.cg.shared.global [%0], [%1], 16;"
        :: "r"(smem_u32(smem)), "l"(gmem));
}
__device__ __forceinline__ void cp_commit() {
    asm volatile("cp.async.commit_group;");
}
__device__ __forceinline__ void ldsm_x4(uint32_t* r, uint32_t addr) {
    asm volatile("ldmatrix.sync.aligned.m8n8.x4.shared.b16 {%0,%1,%2,%3}, [%4];"
        : "=r"(r[0]), "=r"(r[1]), "=r"(r[2]), "=r"(r[3]) : "r"(addr));
}
__device__ __forceinline__ void ldsm_x4_t(uint32_t* r, uint32_t addr) {
    asm volatile("ldmatrix.sync.aligned.m8n8.x4.trans.shared.b16 {%0,%1,%2,%3}, [%4];"
        : "=r"(r[0]), "=r"(r[1]), "=r"(r[2]), "=r"(r[3]) : "r"(addr));
}
__device__ __forceinline__ void mma16816(float* c, const uint32_t* a,
                                         uint32_t b0, uint32_t b1) {
    asm volatile("mma.sync.aligned.m16n8k16.row.col.f32.bf16.bf16.f32 "
        "{%0,%1,%2,%3}, {%4,%5,%6,%7}, {%8,%9}, {%0,%1,%2,%3};"
        : "+f"(c[0]), "+f"(c[1]), "+f"(c[2]), "+f"(c[3])
        : "r"(a[0]), "r"(a[1]), "r"(a[2]), "r"(a[3]), "r"(b0), "r"(b1));
}

/* ================= pipelined pre-split bf16 GEMM ========================== */
struct SmemGemmP {
    bf16 Ah[2][128][40], Al[2][128][40];
    bf16 Bh[2][32][136], Bl[2][32][136];
};

__device__ __forceinline__ void gemm_load_stage(SmemGemmP* sm, int st,
                                                const bf16* Ah, const bf16* Al,
                                                const bf16* Bh, const bf16* Bl,
                                                int N, int K, int bm, int bn, int k0) {
    int tid = threadIdx.x;
    #pragma unroll
    for (int i = 0; i < 2; ++i) {
        int fid = tid + i*256;
        int row = fid >> 2, c8 = (fid & 3) * 8;
        size_t go = (size_t)(bm + row)*K + k0 + c8;
        cp_async16(&sm->Ah[st][row][c8], Ah + go);
        cp_async16(&sm->Al[st][row][c8], Al + go);
    }
    #pragma unroll
    for (int i = 0; i < 2; ++i) {
        int fid = tid + i*256;
        int row = fid >> 4, c8 = (fid & 15) * 8;
        size_t go = (size_t)(k0 + row)*N + bn + c8;
        cp_async16(&sm->Bh[st][row][c8], Bh + go);
        cp_async16(&sm->Bl[st][row][c8], Bl + go);
    }
}

__device__ __forceinline__ void gemm_mainloop(SmemGemmP* sm,
                                              const bf16* Ah, const bf16* Al,
                                              const bf16* Bh, const bf16* Bl,
                                              int N, int K, int bm, int bn,
                                              float c[2][8][4]) {
    int tid = threadIdx.x;
    int warp = tid >> 5, lane = tid & 31;
    int m_base = (warp >> 1) * 32;
    int n_base = (warp & 1) * 64;

    #pragma unroll
    for (int mt = 0; mt < 2; ++mt)
        #pragma unroll
        for (int nt = 0; nt < 8; ++nt)
            #pragma unroll
            for (int r = 0; r < 4; ++r) c[mt][nt][r] = 0.f;

    const int NIT = K / 32;
    gemm_load_stage(sm, 0, Ah, Al, Bh, Bl, N, K, bm, bn, 0);
    cp_commit();

    for (int it = 0; it < NIT; ++it) {
        int cur = it & 1;
        if (it + 1 < NIT) {
            gemm_load_stage(sm, cur ^ 1, Ah, Al, Bh, Bl, N, K, bm, bn, (it+1)*32);
            cp_commit();
            asm volatile("cp.async.wait_group 1;" ::: "memory");
        } else {
            asm volatile("cp.async.wait_group 0;" ::: "memory");
        }
        __syncthreads();

        #pragma unroll
        for (int ks = 0; ks < 32; ks += 16) {
            uint32_t ah[2][4], al[2][4];
            #pragma unroll
            for (int mt = 0; mt < 2; ++mt) {
                int rr = m_base + mt*16 + (lane & 15);
                int kk = ks + (lane >> 4) * 8;
                ldsm_x4(ah[mt], smem_u32(&sm->Ah[cur][rr][kk]));
                ldsm_x4(al[mt], smem_u32(&sm->Al[cur][rr][kk]));
            }
            uint32_t bh[4][4], bl[4][4];
            #pragma unroll
            for (int nc = 0; nc < 4; ++nc) {
                int kr = ks + (lane & 7) + ((lane >> 3) & 1) * 8;
                int nn = n_base + nc*16 + (lane >> 4) * 8;
                ldsm_x4_t(bh[nc], smem_u32(&sm->Bh[cur][kr][nn]));
                ldsm_x4_t(bl[nc], smem_u32(&sm->Bl[cur][kr][nn]));
            }
            #pragma unroll
            for (int mt = 0; mt < 2; ++mt)
                #pragma unroll
                for (int nc = 0; nc < 4; ++nc)
                    #pragma unroll
                    for (int hf = 0; hf < 2; ++hf) {
                        float* cc = c[mt][nc*2 + hf];
                        uint32_t b0h = bh[nc][hf*2], b1h = bh[nc][hf*2+1];
                        uint32_t b0l = bl[nc][hf*2], b1l = bl[nc][hf*2+1];
                        mma16816(cc, ah[mt], b0h, b1h);
                        mma16816(cc, ah[mt], b0l, b1l);
                        mma16816(cc, al[mt], b0h, b1h);
                    }
        }
        __syncthreads();
    }
}

/* fused QKV GEMM: epilogue applies RoPE (q,k), splits to bf16 hi/lo, and
 * writes the fp32 KV cache directly. Each 128-col block = one head.        */
__global__ void __launch_bounds__(256, 2) qkv_gemm_fused(float* cache_k, float* cache_v) {
    extern __shared__ char smraw[];
    SmemGemmP* sm = (SmemGemmP*)smraw;
    int bx = blockIdx.x, bm = blockIdx.y * 128;
    int tid = threadIdx.x;
    int warp = tid >> 5, lane = tid & 31;
    int m_base = (warp >> 1) * 32;
    int n_base = (warp & 1) * 64;

    int mode;      /* 0=q, 1=k, 2=v */
    int bn, N;
    bf16 *oh, *ol;
    if (bx < 16)      { mode = 0; bn = bx*128;      N = NH*DHEAD; oh = g_qh; ol = g_ql; }
    else if (bx < 20) { mode = 1; bn = (bx-16)*128; N = NG*DHEAD; oh = g_kh; ol = g_kl; }
    else              { mode = 2; bn = (bx-20)*128; N = NG*DHEAD; oh = g_vh; ol = g_vl; }

    float c[2][8][4];
    if (mode == 0)
        gemm_mainloop(sm, g_xh, g_xl, g_wqh, g_wql, N, D_MODEL, bm, bn, c);
    else if (mode == 1)
        gemm_mainloop(sm, g_xh, g_xl, g_wkh, g_wkl, N, D_MODEL, bm, bn, c);
    else
        gemm_mainloop(sm, g_xh, g_xl, g_wvh, g_wvl, N, D_MODEL, bm, bn, c);

    /* stage fp32 tile through smem (aliases pipeline buffers; post-sync) */
    float* Cs = (float*)smraw;          /* [128][132] = 67,584 B */
    #pragma unroll
    for (int mt = 0; mt < 2; ++mt)
        #pragma unroll
        for (int nt = 0; nt < 8; ++nt) {
            int r   = m_base + mt*16 + (lane >> 2);
            int col = n_base + nt*8 + (lane & 3)*2;
            *(float2*)&Cs[r*132 + col]     = make_float2(c[mt][nt][0], c[mt][nt][1]);
            *(float2*)&Cs[(r+8)*132 + col] = make_float2(c[mt][nt][2], c[mt][nt][3]);
        }
    __syncthreads();

    int ghead = bn >> 7;
    #pragma unroll
    for (int i = 0; i < 32; ++i) {
        int p   = tid + i*256;
        int row = p >> 6, d = p & 63;
        int grow = bm + row;
        int s = grow & (S_LEN - 1);
        int b = grow >> 11;
        float x1 = Cs[row*132 + d];
        float x2 = Cs[row*132 + d + 64];
        float r1, r2;
        if (mode < 2) {
            float ct = g_rope[s*DHEAD + d];
            float st = g_rope[s*DHEAD + 64 + d];
            r1 = x1*ct - x2*st;
            r2 = x2*ct + x1*st;
        } else { r1 = x1; r2 = x2; }
        size_t o = (size_t)grow*N + bn + d;
        bf16 h1 = __float2bfloat16_rn(r1), h2 = __float2bfloat16_rn(r2);
        oh[o]      = h1;
        oh[o + 64] = h2;
        ol[o]      = __float2bfloat16_rn(r1 - __bfloat162float(h1));
        ol[o + 64] = __float2bfloat16_rn(r2 - __bfloat162float(h2));
        if (mode == 1 && cache_k) {
            size_t co_ = ((size_t)(b*NG + ghead)*S_LEN + s)*DHEAD + d;
            cache_k[co_]      = r1;
            cache_k[co_ + 64] = r2;
        } else if (mode == 2 && cache_v) {
            size_t co_ = ((size_t)(b*NG + ghead)*S_LEN + s)*DHEAD + d;
            cache_v[co_]      = r1;
            cache_v[co_ + 64] = r2;
        }
    }
}

/* output GEMM: plain fp32 epilogue to d_out */
__global__ void __launch_bounds__(256, 2) out_gemm_bf16(float* __restrict__ C) {
    extern __shared__ char smraw[];
    SmemGemmP* sm = (SmemGemmP*)smraw;
    int tid = threadIdx.x;
    int warp = tid >> 5, lane = tid & 31;
    int m_base = (warp >> 1) * 32;
    int n_base = (warp & 1) * 64;
    int bm = blockIdx.y*128, bn = blockIdx.x*128;

    float c[2][8][4];
    gemm_mainloop(sm, g_ch, g_cl, g_woh, g_wol, D_MODEL, D_MODEL, bm, bn, c);

    #pragma unroll
    for (int mt = 0; mt < 2; ++mt)
        #pragma unroll
        for (int nt = 0; nt < 8; ++nt) {
            int r   = bm + m_base + mt*16 + (lane >> 2);
            int col = bn + n_base + nt*8 + (lane & 3)*2;
            *(float2*)(C + (size_t)r*D_MODEL + col)     = make_float2(c[mt][nt][0], c[mt][nt][1]);
            *(float2*)(C + (size_t)(r+8)*D_MODEL + col) = make_float2(c[mt][nt][2], c[mt][nt][3]);
        }
}

/* ================= flash attention, BQ=128, register softmax ============== */
struct SmemFlash {
    bf16 Qh[128][136], Ql[128][136];
    bf16 Kh[64][136], Kl[64][136];
    bf16 Vh[64][136], Vl[64][136];
};

__global__ void __launch_bounds__(256) flash2_kernel() {
    extern __shared__ char smraw[];
    SmemFlash* sm = (SmemFlash*)smraw;

    int qt = (int)(gridDim.x - 1 - blockIdx.x);
    int h = blockIdx.y, b = blockIdx.z;
    int g  = h >> 2;
    int q0 = qt * 128;
    int tid = threadIdx.x, warp = tid >> 5, lane = tid & 31;
    int m_base = warp * 16;
    int rq = lane >> 2;

    size_t qoff = ((size_t)(b*S_LEN + q0))*(NH*DHEAD) + (size_t)h*DHEAD;
    #pragma unroll
    for (int i = 0; i < 8; ++i) {
        int fid = tid + i*256;
        int row = fid >> 4, c8 = (fid & 15) * 8;
        size_t go = qoff + (size_t)row*(NH*DHEAD) + c8;
        *(uint4*)&sm->Qh[row][c8] = *(const uint4*)(g_qh + go);
        *(uint4*)&sm->Ql[row][c8] = *(const uint4*)(g_ql + go);
    }

    float co[16][4];
    #pragma unroll
    for (int nt = 0; nt < 16; ++nt)
        #pragma unroll
        for (int r = 0; r < 4; ++r) co[nt][r] = 0.f;
    float m0 = -1e30f, m1 = -1e30f, l0 = 0.f, l1 = 0.f;

    size_t kvoff = (size_t)(b*S_LEN)*(NG*DHEAD) + (size_t)g*DHEAD;
    const float scale = 0.08838834764831845f;
    const int nkt = 2*qt + 2;

    for (int kt = 0; kt < nkt; ++kt) {
        int k0t = kt * 64;
        __syncthreads();
        #pragma unroll
        for (int i = 0; i < 4; ++i) {
            int fid = tid + i*256;
            int row = fid >> 4, c8 = (fid & 15) * 8;
            size_t go = kvoff + (size_t)(k0t + row)*(NG*DHEAD) + c8;
            cp_async16(&sm->Kh[row][c8], g_kh + go);
            cp_async16(&sm->Kl[row][c8], g_kl + go);
        }
        cp_commit();
        #pragma unroll
        for (int i = 0; i < 4; ++i) {
            int fid = tid + i*256;
            int row = fid >> 4, c8 = (fid & 15) * 8;
            size_t go = kvoff + (size_t)(k0t + row)*(NG*DHEAD) + c8;
            cp_async16(&sm->Vh[row][c8], g_vh + go);
            cp_async16(&sm->Vl[row][c8], g_vl + go);
        }
        cp_commit();
        asm volatile("cp.async.wait_group 1;" ::: "memory");
        __syncthreads();

        float cs[8][4];
        #pragma unroll
        for (int nt = 0; nt < 8; ++nt)
            #pragma unroll
            for (int r = 0; r < 4; ++r) cs[nt][r] = 0.f;

        #pragma unroll
        for (int ks = 0; ks < 8; ++ks) {
            int kk = ks * 16;
            uint32_t ah[4], al[4];
            int ar = m_base + (lane & 15);
            int ac = kk + (lane >> 4) * 8;
            ldsm_x4(ah, smem_u32(&sm->Qh[ar][ac]));
            ldsm_x4(al, smem_u32(&sm->Ql[ar][ac]));
            uint32_t kh[4][4], kl[4][4];
            #pragma unroll
            for (int gp = 0; gp < 4; ++gp) {
                int br = gp*16 + (lane & 7) + (lane >> 4) * 8;
                int bc = kk + ((lane >> 3) & 1) * 8;
                ldsm_x4(kh[gp], smem_u32(&sm->Kh[br][bc]));
                ldsm_x4(kl[gp], smem_u32(&sm->Kl[br][bc]));
            }
            #pragma unroll
            for (int nt = 0; nt < 8; ++nt) {
                int gp = nt >> 1, j = nt & 1;
                uint32_t b0h = kh[gp][j*2], b1h = kh[gp][j*2+1];
                uint32_t b0l = kl[gp][j*2], b1l = kl[gp][j*2+1];
                mma16816(cs[nt], ah, b0h, b1h);
                mma16816(cs[nt], ah, b0l, b1l);
                mma16816(cs[nt], al, b0h, b1h);
            }
        }

        {
            int row0 = q0 + m_base + rq;
            int row1 = row0 + 8;
            #pragma unroll
            for (int nt = 0; nt < 8; ++nt) {
                int col = k0t + nt*8 + (lane & 3)*2;
                cs[nt][0] = (col     > row0) ? -1e30f : cs[nt][0]*scale;
                cs[nt][1] = (col + 1 > row0) ? -1e30f : cs[nt][1]*scale;
                cs[nt][2] = (col     > row1) ? -1e30f : cs[nt][2]*scale;
                cs[nt][3] = (col + 1 > row1) ? -1e30f : cs[nt][3]*scale;
            }
        }

        {
            float mx0 = -1e30f, mx1 = -1e30f;
            #pragma unroll
            for (int nt = 0; nt < 8; ++nt) {
                mx0 = fmaxf(mx0, fmaxf(cs[nt][0], cs[nt][1]));
                mx1 = fmaxf(mx1, fmaxf(cs[nt][2], cs[nt][3]));
            }
            mx0 = fmaxf(mx0, __shfl_xor_sync(0xffffffffu, mx0, 1));
            mx0 = fmaxf(mx0, __shfl_xor_sync(0xffffffffu, mx0, 2));
            mx1 = fmaxf(mx1, __shfl_xor_sync(0xffffffffu, mx1, 1));
            mx1 = fmaxf(mx1, __shfl_xor_sync(0xffffffffu, mx1, 2));
            float m0n = fmaxf(m0, mx0), m1n = fmaxf(m1, mx1);
            float cr0 = __expf(m0 - m0n), cr1 = __expf(m1 - m1n);
            float s0 = 0.f, s1 = 0.f;
            #pragma unroll
            for (int nt = 0; nt < 8; ++nt) {
                cs[nt][0] = __expf(cs[nt][0] - m0n);
                cs[nt][1] = __expf(cs[nt][1] - m0n);
                cs[nt][2] = __expf(cs[nt][2] - m1n);
                cs[nt][3] = __expf(cs[nt][3] - m1n);
                s0 += cs[nt][0] + cs[nt][1];
                s1 += cs[nt][2] + cs[nt][3];
            }
            s0 += __shfl_xor_sync(0xffffffffu, s0, 1);
            s0 += __shfl_xor_sync(0xffffffffu, s0, 2);
            s1 += __shfl_xor_sync(0xffffffffu, s1, 1);
            s1 += __shfl_xor_sync(0xffffffffu, s1, 2);
            l0 = l0*cr0 + s0;  m0 = m0n;
            l1 = l1*cr1 + s1;  m1 = m1n;
            #pragma unroll
            for (int nt = 0; nt < 16; ++nt) {
                co[nt][0] *= cr0; co[nt][1] *= cr0;
                co[nt][2] *= cr1; co[nt][3] *= cr1;
            }
        }

        uint32_t ph[4][4], pl[4][4];
        #pragma unroll
        for (int t = 0; t < 4; ++t) {
            bf162 hi, lo;
            split_pair(cs[2*t][0],   cs[2*t][1],   &hi, &lo);
            ph[t][0] = *(uint32_t*)&hi; pl[t][0] = *(uint32_t*)&lo;
            split_pair(cs[2*t][2],   cs[2*t][3],   &hi, &lo);
            ph[t][1] = *(uint32_t*)&hi; pl[t][1] = *(uint32_t*)&lo;
            split_pair(cs[2*t+1][0], cs[2*t+1][1], &hi, &lo);
            ph[t][2] = *(uint32_t*)&hi; pl[t][2] = *(uint32_t*)&lo;
            split_pair(cs[2*t+1][2], cs[2*t+1][3], &hi, &lo);
            ph[t][3] = *(uint32_t*)&hi; pl[t][3] = *(uint32_t*)&lo;
        }

        asm volatile("cp.async.wait_group 0;" ::: "memory");
        __syncthreads();

        #pragma unroll
        for (int t = 0; t < 4; ++t) {
            int kk = t * 16;
            uint32_t vh[8][4], vl[8][4];
            #pragma unroll
            for (int gp = 0; gp < 8; ++gp) {
                int kr = kk + (lane & 7) + ((lane >> 3) & 1) * 8;
                int nn = gp*16 + (lane >> 4) * 8;
                ldsm_x4_t(vh[gp], smem_u32(&sm->Vh[kr][nn]));
                ldsm_x4_t(vl[gp], smem_u32(&sm->Vl[kr][nn]));
            }
            #pragma unroll
            for (int nt = 0; nt < 16; ++nt) {
                int gp = nt >> 1, j = nt & 1;
                uint32_t b0h = vh[gp][j*2], b1h = vh[gp][j*2+1];
                uint32_t b0l = vl[gp][j*2], b1l = vl[gp][j*2+1];
                mma16816(co[nt], ph[t], b0h, b1h);
                mma16816(co[nt], ph[t], b0l, b1l);
                mma16816(co[nt], pl[t], b0h, b1h);
            }
        }
    }

    {
        int r0 = m_base + rq;
        float il0 = 1.0f / l0;
        float il1 = 1.0f / l1;
        #pragma unroll
        for (int nt = 0; nt < 16; ++nt) {
            int col = nt*8 + (lane & 3)*2;
            size_t off0 = ((size_t)(b*S_LEN + q0 + r0))*(NH*DHEAD) + (size_t)h*DHEAD + col;
            size_t off1 = ((size_t)(b*S_LEN + q0 + r0 + 8))*(NH*DHEAD) + (size_t)h*DHEAD + col;
            bf162 hi, lo;
            split_pair(co[nt][0]*il0, co[nt][1]*il0, &hi, &lo);
            *(bf162*)(g_ch + off0) = hi;
            *(bf162*)(g_cl + off0) = lo;
            split_pair(co[nt][2]*il1, co[nt][3]*il1, &hi, &lo);
            *(bf162*)(g_ch + off1) = hi;
            *(bf162*)(g_cl + off1) = lo;
        }
    }
}

extern "C" void kernel_launch(void* const* d_in, const int* in_sizes, int n_in,
                              void* d_out, int out_size) {
    int idx_x = -1, sm_[2], nsm = 0, bg[3], nbg = 0;
    for (int i = 0; i < n_in; ++i) {
        if (in_sizes[i] == 8388608 && idx_x < 0) idx_x = i;
        else if (in_sizes[i] == 1048576 && nsm < 2) sm_[nsm++] = i;
        else if (in_sizes[i] == 4194304 && nbg < 3) bg[nbg++] = i;
    }
    const float *x, *Wk, *Wv;
    const unsigned char *c0, *c1, *c2;
    if (idx_x >= 0 && nsm == 2 && nbg == 3) {
        x  = (const float*)d_in[idx_x];
        Wk = (const float*)d_in[sm_[0]];
        Wv = (const float*)d_in[sm_[1]];
        c0 = (const unsigned char*)d_in[bg[0]];
        c1 = (const unsigned char*)d_in[bg[1]];
        c2 = (const unsigned char*)d_in[bg[2]];
    } else {
        x  = (const float*)d_in[0];
        Wk = (const float*)d_in[2];
        Wv = (const float*)d_in[3];
        c0 = (const unsigned char*)d_in[1];
        c1 = (const unsigned char*)d_in[4];
        c2 = (const unsigned char*)d_in[5];
    }
    float* out = (float*)d_out;

    probe_kernel<<<1, 32>>>(c0, c1, c2);
    build_rope_kernel<<<S_LEN, 64>>>();

    split_all<<<36864, 256>>>(x, Wk, Wv);

    const size_t OUT_MAIN = (size_t)NB * S_LEN * D_MODEL;
    const size_t CACHE    = (size_t)NB * NG * S_LEN * DHEAD;
    float* cache_k = 0;
    float* cache_v = 0;
    if ((size_t)out_size >= OUT_MAIN + 2*CACHE) {
        cache_k = out + OUT_MAIN;
        cache_v = out + OUT_MAIN + CACHE;
    }

    int gemm_smem = (int)sizeof(SmemGemmP);
    cudaFuncSetAttribute(qkv_gemm_fused, cudaFuncAttributeMaxDynamicSharedMemorySize, gemm_smem);
    cudaFuncSetAttribute(out_gemm_bf16, cudaFuncAttributeMaxDynamicSharedMemorySize, gemm_smem);

    qkv_gemm_fused<<<dim3(24, MROWS/128), 256, gemm_smem>>>(cache_k, cache_v);

    int fl2_smem = (int)sizeof(SmemFlash);
    cudaFuncSetAttribute(flash2_kernel, cudaFuncAttributeMaxDynamicSharedMemorySize, fl2_smem);
    flash2_kernel<<<dim3(S_LEN/128, NH, NB), 256, fl2_smem>>>();

    out_gemm_bf16<<<dim3(D_MODEL/128, MROWS/128), 256, gemm_smem>>>(out);
}

// round 17
// speedup vs baseline: 4.9224x; 1.0053x over previous
#include <cuda_runtime.h>
#include <cuda_bf16.h>
#include <math.h>
#include <stdint.h>

#define S_LEN   2048
#define D_MODEL 2048
#define NH      16
#define NG      4
#define DHEAD   128
#define NB      2
#define MROWS   (NB*S_LEN)
typedef __nv_bfloat16 bf16;
typedef __nv_bfloat162 bf162;

__device__ float g_rope[S_LEN * DHEAD];
__device__ const float* g_wq_slot;
__device__ const float* g_wo_slot;

__device__ bf16 g_xh [(size_t)MROWS * D_MODEL],      g_xl [(size_t)MROWS * D_MODEL];
__device__ bf16 g_wqh[(size_t)D_MODEL * NH*DHEAD],   g_wql[(size_t)D_MODEL * NH*DHEAD];
__device__ bf16 g_wkh[(size_t)D_MODEL * NG*DHEAD],   g_wkl[(size_t)D_MODEL * NG*DHEAD];
__device__ bf16 g_wvh[(size_t)D_MODEL * NG*DHEAD],   g_wvl[(size_t)D_MODEL * NG*DHEAD];
__device__ bf16 g_woh[(size_t)D_MODEL * D_MODEL],    g_wol[(size_t)D_MODEL * D_MODEL];
__device__ bf16 g_qh [(size_t)MROWS * NH*DHEAD],     g_ql [(size_t)MROWS * NH*DHEAD];
__device__ bf16 g_kh [(size_t)MROWS * NG*DHEAD],     g_kl [(size_t)MROWS * NG*DHEAD];
__device__ bf16 g_vh [(size_t)MROWS * NG*DHEAD],     g_vl [(size_t)MROWS * NG*DHEAD];
__device__ bf16 g_ch [(size_t)MROWS * NH*DHEAD],     g_cl [(size_t)MROWS * NH*DHEAD];

__global__ void probe_kernel(const unsigned char* c0, const unsigned char* c1,
                             const unsigned char* c2) {
    if (threadIdx.x != 0 || blockIdx.x != 0) return;
    const unsigned char* cs[3] = {c0, c1, c2};
    int nb[3];
    for (int i = 0; i < 3; ++i) {
        int boolish = 1;
        for (int k = 0; k < 64; ++k)
            if (cs[i][k * 97] > 1) { boolish = 0; break; }
        nb[i] = boolish;
    }
    int a = -1, b = -1;
    for (int i = 0; i < 3; ++i)
        if (!nb[i]) { if (a < 0) a = i; else if (b < 0) b = i; }
    if (a < 0 || b < 0) { a = 0; b = 1; }
    g_wq_slot = (const float*)cs[a];
    g_wo_slot = (const float*)cs[b];
}

__global__ void build_rope_kernel() {
    int s = blockIdx.x, d = threadIdx.x;
    float e    = (float)d / 64.0f;
    float invf = 1.0f / powf(10000.0f, e);
    float ang  = (float)s * invf;
    g_rope[s*DHEAD + d]      = (float)cos((double)ang);
    g_rope[s*DHEAD + 64 + d] = (float)sin((double)ang);
}

__device__ __forceinline__ void split_pair(float x, float y, bf162* hi, bf162* lo) {
    bf16 hx = __float2bfloat16_rn(x);
    bf16 hy = __float2bfloat16_rn(y);
    *hi = __halves2bfloat162(hx, hy);
    *lo = __halves2bfloat162(__float2bfloat16_rn(x - __bfloat162float(hx)),
                             __float2bfloat16_rn(y - __bfloat162float(hy)));
}

/* segments (blocks of 256 float2): x 16384 | wq 8192 | wk 2048 | wv 2048 | wo 8192
 * total = 36864 */
__global__ void __launch_bounds__(256) split_all(const float* x,
                                                 const float* Wk,
                                                 const float* Wv) {
    int blk = blockIdx.x;
    const float* in;
    bf16 *oh, *ol;
    int base;
    if (blk < 16384)      { in = x;         oh = g_xh;  ol = g_xl;  base = blk; }
    else if (blk < 24576) { in = g_wq_slot; oh = g_wqh; ol = g_wql; base = blk - 16384; }
    else if (blk < 26624) { in = Wk;        oh = g_wkh; ol = g_wkl; base = blk - 24576; }
    else if (blk < 28672) { in = Wv;        oh = g_wvh; ol = g_wvl; base = blk - 26624; }
    else                  { in = g_wo_slot; oh = g_woh; ol = g_wol; base = blk - 28672; }
    size_t i = (size_t)base * 256 + threadIdx.x;
    float2 v = *(const float2*)(in + i*2);
    bf162 hi, lo;
    split_pair(v.x, v.y, &hi, &lo);
    *(bf162*)(oh + i*2) = hi;
    *(bf162*)(ol + i*2) = lo;
}

/* ================= mma / async helpers ==================================== */
__device__ __forceinline__ uint32_t smem_u32(const void* p) {
    return (uint32_t)__cvta_generic_to_shared(p);
}
__device__ __forceinline__ void cp_async16(void* smem, const void* gmem) {
    asm volatile("cp.async.cg.shared.global [%0], [%1], 16;"
        :: "r"(smem_u32(smem)), "l"(gmem));
}
__device__ __forceinline__ void cp_commit() {
    asm volatile("cp.async.commit_group;");
}
__device__ __forceinline__ void ldsm_x4(uint32_t* r, uint32_t addr) {
    asm volatile("ldmatrix.sync.aligned.m8n8.x4.shared.b16 {%0,%1,%2,%3}, [%4];"
        : "=r"(r[0]), "=r"(r[1]), "=r"(r[2]), "=r"(r[3]) : "r"(addr));
}
__device__ __forceinline__ void ldsm_x4_t(uint32_t* r, uint32_t addr) {
    asm volatile("ldmatrix.sync.aligned.m8n8.x4.trans.shared.b16 {%0,%1,%2,%3}, [%4];"
        : "=r"(r[0]), "=r"(r[1]), "=r"(r[2]), "=r"(r[3]) : "r"(addr));
}
__device__ __forceinline__ void mma16816(float* c, const uint32_t* a,
                                         uint32_t b0, uint32_t b1) {
    asm volatile("mma.sync.aligned.m16n8k16.row.col.f32.bf16.bf16.f32 "
        "{%0,%1,%2,%3}, {%4,%5,%6,%7}, {%8,%9}, {%0,%1,%2,%3};"
        : "+f"(c[0]), "+f"(c[1]), "+f"(c[2]), "+f"(c[3])
        : "r"(a[0]), "r"(a[1]), "r"(a[2]), "r"(a[3]), "r"(b0), "r"(b1));
}

/* ================= pipelined pre-split bf16 GEMM ========================== */
struct SmemGemmP {
    bf16 Ah[2][128][40], Al[2][128][40];
    bf16 Bh[2][32][136], Bl[2][32][136];
};

__device__ __forceinline__ void gemm_load_stage(SmemGemmP* sm, int st,
                                                const bf16* Ah, const bf16* Al,
                                                const bf16* Bh, const bf16* Bl,
                                                int N, int K, int bm, int bn, int k0) {
    int tid = threadIdx.x;
    #pragma unroll
    for (int i = 0; i < 2; ++i) {
        int fid = tid + i*256;
        int row = fid >> 2, c8 = (fid & 3) * 8;
        size_t go = (size_t)(bm + row)*K + k0 + c8;
        cp_async16(&sm->Ah[st][row][c8], Ah + go);
        cp_async16(&sm->Al[st][row][c8], Al + go);
    }
    #pragma unroll
    for (int i = 0; i < 2; ++i) {
        int fid = tid + i*256;
        int row = fid >> 4, c8 = (fid & 15) * 8;
        size_t go = (size_t)(k0 + row)*N + bn + c8;
        cp_async16(&sm->Bh[st][row][c8], Bh + go);
        cp_async16(&sm->Bl[st][row][c8], Bl + go);
    }
}

__device__ __forceinline__ void gemm_mainloop(SmemGemmP* sm,
                                              const bf16* Ah, const bf16* Al,
                                              const bf16* Bh, const bf16* Bl,
                                              int N, int K, int bm, int bn,
                                              float c[2][8][4]) {
    int tid = threadIdx.x;
    int warp = tid >> 5, lane = tid & 31;
    int m_base = (warp >> 1) * 32;
    int n_base = (warp & 1) * 64;

    #pragma unroll
    for (int mt = 0; mt < 2; ++mt)
        #pragma unroll
        for (int nt = 0; nt < 8; ++nt)
            #pragma unroll
            for (int r = 0; r < 4; ++r) c[mt][nt][r] = 0.f;

    const int NIT = K / 32;
    gemm_load_stage(sm, 0, Ah, Al, Bh, Bl, N, K, bm, bn, 0);
    cp_commit();

    for (int it = 0; it < NIT; ++it) {
        int cur = it & 1;
        if (it + 1 < NIT) {
            gemm_load_stage(sm, cur ^ 1, Ah, Al, Bh, Bl, N, K, bm, bn, (it+1)*32);
            cp_commit();
            asm volatile("cp.async.wait_group 1;" ::: "memory");
        } else {
            asm volatile("cp.async.wait_group 0;" ::: "memory");
        }
        __syncthreads();

        #pragma unroll
        for (int ks = 0; ks < 32; ks += 16) {
            uint32_t ah[2][4], al[2][4];
            #pragma unroll
            for (int mt = 0; mt < 2; ++mt) {
                int rr = m_base + mt*16 + (lane & 15);
                int kk = ks + (lane >> 4) * 8;
                ldsm_x4(ah[mt], smem_u32(&sm->Ah[cur][rr][kk]));
                ldsm_x4(al[mt], smem_u32(&sm->Al[cur][rr][kk]));
            }
            uint32_t bh[4][4], bl[4][4];
            #pragma unroll
            for (int nc = 0; nc < 4; ++nc) {
                int kr = ks + (lane & 7) + ((lane >> 3) & 1) * 8;
                int nn = n_base + nc*16 + (lane >> 4) * 8;
                ldsm_x4_t(bh[nc], smem_u32(&sm->Bh[cur][kr][nn]));
                ldsm_x4_t(bl[nc], smem_u32(&sm->Bl[cur][kr][nn]));
            }
            /* pass loop OUTERMOST: consecutive MMAs hit distinct accumulators;
             * per-accumulator order (hi*hi, hi*lo, lo*hi) unchanged          */
            #pragma unroll
            for (int pass = 0; pass < 3; ++pass)
                #pragma unroll
                for (int mt = 0; mt < 2; ++mt)
                    #pragma unroll
                    for (int nc = 0; nc < 4; ++nc)
                        #pragma unroll
                        for (int hf = 0; hf < 2; ++hf) {
                            float* cc = c[mt][nc*2 + hf];
                            const uint32_t* aa = (pass == 2) ? al[mt] : ah[mt];
                            uint32_t b0 = (pass == 1) ? bl[nc][hf*2]   : bh[nc][hf*2];
                            uint32_t b1 = (pass == 1) ? bl[nc][hf*2+1] : bh[nc][hf*2+1];
                            mma16816(cc, aa, b0, b1);
                        }
        }
        __syncthreads();
    }
}

/* fused QKV GEMM: epilogue applies RoPE (q,k), splits, writes fp32 KV cache */
__global__ void __launch_bounds__(256, 2) qkv_gemm_fused(float* cache_k, float* cache_v) {
    extern __shared__ char smraw[];
    SmemGemmP* sm = (SmemGemmP*)smraw;
    int bx = blockIdx.x, bm = blockIdx.y * 128;
    int tid = threadIdx.x;
    int warp = tid >> 5, lane = tid & 31;
    int m_base = (warp >> 1) * 32;
    int n_base = (warp & 1) * 64;

    int mode;
    int bn, N;
    bf16 *oh, *ol;
    if (bx < 16)      { mode = 0; bn = bx*128;      N = NH*DHEAD; oh = g_qh; ol = g_ql; }
    else if (bx < 20) { mode = 1; bn = (bx-16)*128; N = NG*DHEAD; oh = g_kh; ol = g_kl; }
    else              { mode = 2; bn = (bx-20)*128; N = NG*DHEAD; oh = g_vh; ol = g_vl; }

    float c[2][8][4];
    if (mode == 0)
        gemm_mainloop(sm, g_xh, g_xl, g_wqh, g_wql, N, D_MODEL, bm, bn, c);
    else if (mode == 1)
        gemm_mainloop(sm, g_xh, g_xl, g_wkh, g_wkl, N, D_MODEL, bm, bn, c);
    else
        gemm_mainloop(sm, g_xh, g_xl, g_wvh, g_wvl, N, D_MODEL, bm, bn, c);

    float* Cs = (float*)smraw;          /* [128][132] = 67,584 B */
    #pragma unroll
    for (int mt = 0; mt < 2; ++mt)
        #pragma unroll
        for (int nt = 0; nt < 8; ++nt) {
            int r   = m_base + mt*16 + (lane >> 2);
            int col = n_base + nt*8 + (lane & 3)*2;
            *(float2*)&Cs[r*132 + col]     = make_float2(c[mt][nt][0], c[mt][nt][1]);
            *(float2*)&Cs[(r+8)*132 + col] = make_float2(c[mt][nt][2], c[mt][nt][3]);
        }
    __syncthreads();

    int ghead = bn >> 7;
    #pragma unroll
    for (int i = 0; i < 32; ++i) {
        int p   = tid + i*256;
        int row = p >> 6, d = p & 63;
        int grow = bm + row;
        int s = grow & (S_LEN - 1);
        int b = grow >> 11;
        float x1 = Cs[row*132 + d];
        float x2 = Cs[row*132 + d + 64];
        float r1, r2;
        if (mode < 2) {
            float ct = g_rope[s*DHEAD + d];
            float st = g_rope[s*DHEAD + 64 + d];
            r1 = x1*ct - x2*st;
            r2 = x2*ct + x1*st;
        } else { r1 = x1; r2 = x2; }
        size_t o = (size_t)grow*N + bn + d;
        bf16 h1 = __float2bfloat16_rn(r1), h2 = __float2bfloat16_rn(r2);
        oh[o]      = h1;
        oh[o + 64] = h2;
        ol[o]      = __float2bfloat16_rn(r1 - __bfloat162float(h1));
        ol[o + 64] = __float2bfloat16_rn(r2 - __bfloat162float(h2));
        if (mode == 1 && cache_k) {
            size_t co_ = ((size_t)(b*NG + ghead)*S_LEN + s)*DHEAD + d;
            cache_k[co_]      = r1;
            cache_k[co_ + 64] = r2;
        } else if (mode == 2 && cache_v) {
            size_t co_ = ((size_t)(b*NG + ghead)*S_LEN + s)*DHEAD + d;
            cache_v[co_]      = r1;
            cache_v[co_ + 64] = r2;
        }
    }
}

__global__ void __launch_bounds__(256, 2) out_gemm_bf16(float* __restrict__ C) {
    extern __shared__ char smraw[];
    SmemGemmP* sm = (SmemGemmP*)smraw;
    int tid = threadIdx.x;
    int warp = tid >> 5, lane = tid & 31;
    int m_base = (warp >> 1) * 32;
    int n_base = (warp & 1) * 64;
    int bm = blockIdx.y*128, bn = blockIdx.x*128;

    float c[2][8][4];
    gemm_mainloop(sm, g_ch, g_cl, g_woh, g_wol, D_MODEL, D_MODEL, bm, bn, c);

    #pragma unroll
    for (int mt = 0; mt < 2; ++mt)
        #pragma unroll
        for (int nt = 0; nt < 8; ++nt) {
            int r   = bm + m_base + mt*16 + (lane >> 2);
            int col = bn + n_base + nt*8 + (lane & 3)*2;
            *(float2*)(C + (size_t)r*D_MODEL + col)     = make_float2(c[mt][nt][0], c[mt][nt][1]);
            *(float2*)(C + (size_t)(r+8)*D_MODEL + col) = make_float2(c[mt][nt][2], c[mt][nt][3]);
        }
}

/* ================= flash attention, BQ=128, register softmax ============== */
struct SmemFlash {
    bf16 Qh[128][136], Ql[128][136];
    bf16 Kh[64][136], Kl[64][136];
    bf16 Vh[64][136], Vl[64][136];
};

__global__ void __launch_bounds__(256) flash2_kernel() {
    extern __shared__ char smraw[];
    SmemFlash* sm = (SmemFlash*)smraw;

    int qt = (int)(gridDim.x - 1 - blockIdx.x);
    int h = blockIdx.y, b = blockIdx.z;
    int g  = h >> 2;
    int q0 = qt * 128;
    int tid = threadIdx.x, warp = tid >> 5, lane = tid & 31;
    int m_base = warp * 16;
    int rq = lane >> 2;

    size_t qoff = ((size_t)(b*S_LEN + q0))*(NH*DHEAD) + (size_t)h*DHEAD;
    #pragma unroll
    for (int i = 0; i < 8; ++i) {
        int fid = tid + i*256;
        int row = fid >> 4, c8 = (fid & 15) * 8;
        size_t go = qoff + (size_t)row*(NH*DHEAD) + c8;
        *(uint4*)&sm->Qh[row][c8] = *(const uint4*)(g_qh + go);
        *(uint4*)&sm->Ql[row][c8] = *(const uint4*)(g_ql + go);
    }

    float co[16][4];
    #pragma unroll
    for (int nt = 0; nt < 16; ++nt)
        #pragma unroll
        for (int r = 0; r < 4; ++r) co[nt][r] = 0.f;
    float m0 = -1e30f, m1 = -1e30f, l0 = 0.f, l1 = 0.f;

    size_t kvoff = (size_t)(b*S_LEN)*(NG*DHEAD) + (size_t)g*DHEAD;
    const float scale = 0.08838834764831845f;
    const int nkt = 2*qt + 2;

    for (int kt = 0; kt < nkt; ++kt) {
        int k0t = kt * 64;
        __syncthreads();
        #pragma unroll
        for (int i = 0; i < 4; ++i) {
            int fid = tid + i*256;
            int row = fid >> 4, c8 = (fid & 15) * 8;
            size_t go = kvoff + (size_t)(k0t + row)*(NG*DHEAD) + c8;
            cp_async16(&sm->Kh[row][c8], g_kh + go);
            cp_async16(&sm->Kl[row][c8], g_kl + go);
        }
        cp_commit();
        #pragma unroll
        for (int i = 0; i < 4; ++i) {
            int fid = tid + i*256;
            int row = fid >> 4, c8 = (fid & 15) * 8;
            size_t go = kvoff + (size_t)(k0t + row)*(NG*DHEAD) + c8;
            cp_async16(&sm->Vh[row][c8], g_vh + go);
            cp_async16(&sm->Vl[row][c8], g_vl + go);
        }
        cp_commit();
        asm volatile("cp.async.wait_group 1;" ::: "memory");
        __syncthreads();

        float cs[8][4];
        #pragma unroll
        for (int nt = 0; nt < 8; ++nt)
            #pragma unroll
            for (int r = 0; r < 4; ++r) cs[nt][r] = 0.f;

        #pragma unroll
        for (int ks = 0; ks < 8; ++ks) {
            int kk = ks * 16;
            uint32_t ah[4], al[4];
            int ar = m_base + (lane & 15);
            int ac = kk + (lane >> 4) * 8;
            ldsm_x4(ah, smem_u32(&sm->Qh[ar][ac]));
            ldsm_x4(al, smem_u32(&sm->Ql[ar][ac]));
            uint32_t kh[4][4], kl[4][4];
            #pragma unroll
            for (int gp = 0; gp < 4; ++gp) {
                int br = gp*16 + (lane & 7) + (lane >> 4) * 8;
                int bc = kk + ((lane >> 3) & 1) * 8;
                ldsm_x4(kh[gp], smem_u32(&sm->Kh[br][bc]));
                ldsm_x4(kl[gp], smem_u32(&sm->Kl[br][bc]));
            }
            #pragma unroll
            for (int pass = 0; pass < 3; ++pass)
                #pragma unroll
                for (int nt = 0; nt < 8; ++nt) {
                    int gp = nt >> 1, j = nt & 1;
                    const uint32_t* aa = (pass == 2) ? al : ah;
                    uint32_t b0 = (pass == 1) ? kl[gp][j*2]   : kh[gp][j*2];
                    uint32_t b1 = (pass == 1) ? kl[gp][j*2+1] : kh[gp][j*2+1];
                    mma16816(cs[nt], aa, b0, b1);
                }
        }

        {
            int row0 = q0 + m_base + rq;
            int row1 = row0 + 8;
            #pragma unroll
            for (int nt = 0; nt < 8; ++nt) {
                int col = k0t + nt*8 + (lane & 3)*2;
                cs[nt][0] = (col     > row0) ? -1e30f : cs[nt][0]*scale;
                cs[nt][1] = (col + 1 > row0) ? -1e30f : cs[nt][1]*scale;
                cs[nt][2] = (col     > row1) ? -1e30f : cs[nt][2]*scale;
                cs[nt][3] = (col + 1 > row1) ? -1e30f : cs[nt][3]*scale;
            }
        }

        {
            float mx0 = -1e30f, mx1 = -1e30f;
            #pragma unroll
            for (int nt = 0; nt < 8; ++nt) {
                mx0 = fmaxf(mx0, fmaxf(cs[nt][0], cs[nt][1]));
                mx1 = fmaxf(mx1, fmaxf(cs[nt][2], cs[nt][3]));
            }
            mx0 = fmaxf(mx0, __shfl_xor_sync(0xffffffffu, mx0, 1));
            mx0 = fmaxf(mx0, __shfl_xor_sync(0xffffffffu, mx0, 2));
            mx1 = fmaxf(mx1, __shfl_xor_sync(0xffffffffu, mx1, 1));
            mx1 = fmaxf(mx1, __shfl_xor_sync(0xffffffffu, mx1, 2));
            float m0n = fmaxf(m0, mx0), m1n = fmaxf(m1, mx1);
            float cr0 = __expf(m0 - m0n), cr1 = __expf(m1 - m1n);
            float s0 = 0.f, s1 = 0.f;
            #pragma unroll
            for (int nt = 0; nt < 8; ++nt) {
                cs[nt][0] = __expf(cs[nt][0] - m0n);
                cs[nt][1] = __expf(cs[nt][1] - m0n);
                cs[nt][2] = __expf(cs[nt][2] - m1n);
                cs[nt][3] = __expf(cs[nt][3] - m1n);
                s0 += cs[nt][0] + cs[nt][1];
                s1 += cs[nt][2] + cs[nt][3];
            }
            s0 += __shfl_xor_sync(0xffffffffu, s0, 1);
            s0 += __shfl_xor_sync(0xffffffffu, s0, 2);
            s1 += __shfl_xor_sync(0xffffffffu, s1, 1);
            s1 += __shfl_xor_sync(0xffffffffu, s1, 2);
            l0 = l0*cr0 + s0;  m0 = m0n;
            l1 = l1*cr1 + s1;  m1 = m1n;
            #pragma unroll
            for (int nt = 0; nt < 16; ++nt) {
                co[nt][0] *= cr0; co[nt][1] *= cr0;
                co[nt][2] *= cr1; co[nt][3] *= cr1;
            }
        }

        uint32_t ph[4][4], pl[4][4];
        #pragma unroll
        for (int t = 0; t < 4; ++t) {
            bf162 hi, lo;
            split_pair(cs[2*t][0],   cs[2*t][1],   &hi, &lo);
            ph[t][0] = *(uint32_t*)&hi; pl[t][0] = *(uint32_t*)&lo;
            split_pair(cs[2*t][2],   cs[2*t][3],   &hi, &lo);
            ph[t][1] = *(uint32_t*)&hi; pl[t][1] = *(uint32_t*)&lo;
            split_pair(cs[2*t+1][0], cs[2*t+1][1], &hi, &lo);
            ph[t][2] = *(uint32_t*)&hi; pl[t][2] = *(uint32_t*)&lo;
            split_pair(cs[2*t+1][2], cs[2*t+1][3], &hi, &lo);
            ph[t][3] = *(uint32_t*)&hi; pl[t][3] = *(uint32_t*)&lo;
        }

        asm volatile("cp.async.wait_group 0;" ::: "memory");
        __syncthreads();

        #pragma unroll
        for (int t = 0; t < 4; ++t) {
            int kk = t * 16;
            uint32_t vh[8][4], vl[8][4];
            #pragma unroll
            for (int gp = 0; gp < 8; ++gp) {
                int kr = kk + (lane & 7) + ((lane >> 3) & 1) * 8;
                int nn = gp*16 + (lane >> 4) * 8;
                ldsm_x4_t(vh[gp], smem_u32(&sm->Vh[kr][nn]));
                ldsm_x4_t(vl[gp], smem_u32(&sm->Vl[kr][nn]));
            }
            #pragma unroll
            for (int pass = 0; pass < 3; ++pass)
                #pragma unroll
                for (int nt = 0; nt < 16; ++nt) {
                    int gp = nt >> 1, j = nt & 1;
                    const uint32_t* aa = (pass == 2) ? pl[t] : ph[t];
                    uint32_t b0 = (pass == 1) ? vl[gp][j*2]   : vh[gp][j*2];
                    uint32_t b1 = (pass == 1) ? vl[gp][j*2+1] : vh[gp][j*2+1];
                    mma16816(co[nt], aa, b0, b1);
                }
        }
    }

    {
        int r0 = m_base + rq;
        float il0 = 1.0f / l0;
        float il1 = 1.0f / l1;
        #pragma unroll
        for (int nt = 0; nt < 16; ++nt) {
            int col = nt*8 + (lane & 3)*2;
            size_t off0 = ((size_t)(b*S_LEN + q0 + r0))*(NH*DHEAD) + (size_t)h*DHEAD + col;
            size_t off1 = ((size_t)(b*S_LEN + q0 + r0 + 8))*(NH*DHEAD) + (size_t)h*DHEAD + col;
            bf162 hi, lo;
            split_pair(co[nt][0]*il0, co[nt][1]*il0, &hi, &lo);
            *(bf162*)(g_ch + off0) = hi;
            *(bf162*)(g_cl + off0) = lo;
            split_pair(co[nt][2]*il1, co[nt][3]*il1, &hi, &lo);
            *(bf162*)(g_ch + off1) = hi;
            *(bf162*)(g_cl + off1) = lo;
        }
    }
}

extern "C" void kernel_launch(void* const* d_in, const int* in_sizes, int n_in,
                              void* d_out, int out_size) {
    int idx_x = -1, sm_[2], nsm = 0, bg[3], nbg = 0;
    for (int i = 0; i < n_in; ++i) {
        if (in_sizes[i] == 8388608 && idx_x < 0) idx_x = i;
        else if (in_sizes[i] == 1048576 && nsm < 2) sm_[nsm++] = i;
        else if (in_sizes[i] == 4194304 && nbg < 3) bg[nbg++] = i;
    }
    const float *x, *Wk, *Wv;
    const unsigned char *c0, *c1, *c2;
    if (idx_x >= 0 && nsm == 2 && nbg == 3) {
        x  = (const float*)d_in[idx_x];
        Wk = (const float*)d_in[sm_[0]];
        Wv = (const float*)d_in[sm_[1]];
        c0 = (const unsigned char*)d_in[bg[0]];
        c1 = (const unsigned char*)d_in[bg[1]];
        c2 = (const unsigned char*)d_in[bg[2]];
    } else {
        x  = (const float*)d_in[0];
        Wk = (const float*)d_in[2];
        Wv = (const float*)d_in[3];
        c0 = (const unsigned char*)d_in[1];
        c1 = (const unsigned char*)d_in[4];
        c2 = (const unsigned char*)d_in[5];
    }
    float* out = (float*)d_out;

    probe_kernel<<<1, 32>>>(c0, c1, c2);
    build_rope_kernel<<<S_LEN, 64>>>();

    split_all<<<36864, 256>>>(x, Wk, Wv);

    const size_t OUT_MAIN = (size_t)NB * S_LEN * D_MODEL;
    const size_t CACHE    = (size_t)NB * NG * S_LEN * DHEAD;
    float* cache_k = 0;
    float* cache_v = 0;
    if ((size_t)out_size >= OUT_MAIN + 2*CACHE) {
        cache_k = out + OUT_MAIN;
        cache_v = out + OUT_MAIN + CACHE;
    }

    int gemm_smem = (int)sizeof(SmemGemmP);
    cudaFuncSetAttribute(qkv_gemm_fused, cudaFuncAttributeMaxDynamicSharedMemorySize, gemm_smem);
    cudaFuncSetAttribute(out_gemm_bf16, cudaFuncAttributeMaxDynamicSharedMemorySize, gemm_smem);

    qkv_gemm_fused<<<dim3(24, MROWS/128), 256, gemm_smem>>>(cache_k, cache_v);

    int fl2_smem = (int)sizeof(SmemFlash);
    cudaFuncSetAttribute(flash2_kernel, cudaFuncAttributeMaxDynamicSharedMemorySize, fl2_smem);
    flash2_kernel<<<dim3(S_LEN/128, NH, NB), 256, fl2_smem>>>();

    out_gemm_bf16<<<dim3(D_MODEL/128, MROWS/128), 256, gemm_smem>>>(out);
}